// round 11
// baseline (speedup 1.0000x reference)
#include <cuda_runtime.h>
#include <cuda_bf16.h>
#include <cuda_fp16.h>
#include <math.h>
#include <stdint.h>

// ---------------- problem constants ----------------
#define BT_    4096          // B*T
#define C_     2048
#define T_     1024
#define H_     16
#define HD_    128
#define HID_   5464
#define HBLK_  688           // padded hidden block
#define HIDP_  5504          // 8*688
#define NQKV_  6144
#define NGU_   11008         // interleaved gate/up

// ---------------- helpers ----------------
__device__ __forceinline__ uint32_t smem_u32(const void* p) {
    uint32_t a;
    asm("{ .reg .u64 t; cvta.to.shared.u64 t, %1; cvt.u32.u64 %0, t; }" : "=r"(a) : "l"(p));
    return a;
}
#define SW128(o) ((o) ^ (((o) >> 3) & 0x70))          // 128B-row swizzle
#define SWK(o)   ((o) ^ ((((o) >> 8) & 7) << 4))      // 256B-row swizzle

__device__ __forceinline__ void cp16(uint32_t s, const void* g) {
    asm volatile("cp.async.cg.shared.global [%0], [%1], 16;"
                 :: "r"(s), "l"(__cvta_generic_to_global(g)));
}
__device__ __forceinline__ void ldm_x4(uint32_t addr, uint32_t& r0, uint32_t& r1,
                                       uint32_t& r2, uint32_t& r3) {
    asm volatile("ldmatrix.sync.aligned.m8n8.x4.shared.b16 {%0,%1,%2,%3}, [%4];"
                 : "=r"(r0), "=r"(r1), "=r"(r2), "=r"(r3) : "r"(addr));
}
__device__ __forceinline__ void ldm_x4t(uint32_t addr, uint32_t& r0, uint32_t& r1,
                                        uint32_t& r2, uint32_t& r3) {
    asm volatile("ldmatrix.sync.aligned.m8n8.x4.trans.shared.b16 {%0,%1,%2,%3}, [%4];"
                 : "=r"(r0), "=r"(r1), "=r"(r2), "=r"(r3) : "r"(addr));
}
__device__ __forceinline__ void mma16816h(float* c, const uint32_t* a, uint32_t b0, uint32_t b1) {
    asm volatile(
        "mma.sync.aligned.m16n8k16.row.col.f32.f16.f16.f32 "
        "{%0,%1,%2,%3}, {%4,%5,%6,%7}, {%8,%9}, {%0,%1,%2,%3};"
        : "+f"(c[0]), "+f"(c[1]), "+f"(c[2]), "+f"(c[3])
        : "r"(a[0]), "r"(a[1]), "r"(a[2]), "r"(a[3]), "r"(b0), "r"(b1));
}
__device__ __forceinline__ uint32_t packh2(float x, float y) {
    __half2 h = __floats2half2_rn(x, y);
    return *(uint32_t*)&h;
}

// ---------------- scratch (device globals, no allocs) ----------------
__device__ __half g_Wqkv[(size_t)NQKV_*C_];
__device__ __half g_Wo  [(size_t)C_*C_];
__device__ __half g_Wgu [(size_t)NGU_*C_];   // interleaved: 16-col groups (8 gate + 8 up)
__device__ __half g_Wd  [(size_t)C_*HIDP_];
__device__ __half g_XN  [(size_t)BT_*C_];
__device__ __half g_Y   [(size_t)BT_*C_];
__device__ __half g_HN  [(size_t)BT_*C_];
__device__ __half g_PR  [(size_t)BT_*HIDP_];
__device__ __half g_QKV [(size_t)BT_*NQKV_];
__device__ float  g_Hb  [(size_t)BT_*C_];
__device__ int    g_Ji[64];
__device__ float  g_Sg[64];
__device__ float  g_scale[56];
__device__ double g_part[7*8*8];

struct ScaleSrc { const float* p[7]; int op[7]; };

// ---------------- octonion table ----------------
__global__ void build_tables_k() {
    int idx[8][8]; float sg[8][8];
    for (int j = 0; j < 8; j++) { idx[0][j] = j; sg[0][j] = 1.f; }
    for (int i = 1; i < 8; i++) {
        idx[i][0] = i; sg[i][0] = 1.f;
        idx[i][i] = 0; sg[i][i] = -1.f;
    }
    const int tr[7][3] = {{1,2,3},{1,4,5},{1,7,6},{2,4,6},{2,5,7},{3,4,7},{3,6,5}};
    for (int t = 0; t < 7; t++) {
        int a = tr[t][0], b = tr[t][1], c = tr[t][2];
        int per[3][3] = {{a,b,c},{b,c,a},{c,a,b}};
        for (int u = 0; u < 3; u++) {
            int p = per[u][0], q = per[u][1], r = per[u][2];
            idx[p][q] = r; sg[p][q] = 1.f;
            idx[q][p] = r; sg[q][p] = -1.f;
        }
    }
    for (int i = 0; i < 8; i++)
        for (int j = 0; j < 8; j++) {
            int k = idx[i][j];
            g_Ji[k*8 + j] = i;
            g_Sg[k*8 + j] = sg[i][j];
        }
}

// ---------------- scales ----------------
__global__ void scales_part_k(ScaleSrc ss) {
    int t = blockIdx.z, i = blockIdx.x, sl = blockIdx.y;
    int OP = ss.op[t];
    const float* Wi = ss.p[t] + (size_t)i * OP;
    int per = (OP + 7) / 8;
    int st = sl * per, en = min(OP, st + per);
    double s = 0.0;
    for (int u = st + threadIdx.x; u < en; u += 256) s += (double)fabsf(Wi[u]);
    __shared__ double red[256];
    red[threadIdx.x] = s; __syncthreads();
    for (int stp = 128; stp > 0; stp >>= 1) {
        if (threadIdx.x < stp) red[threadIdx.x] += red[threadIdx.x + stp];
        __syncthreads();
    }
    if (threadIdx.x == 0) g_part[(t*8 + i)*8 + sl] = red[0];
}
__global__ void scales_fin_k(ScaleSrc ss) {
    int id = threadIdx.x;
    int t = id >> 3, i = id & 7;
    double s = 0.0;
    for (int j = 0; j < 8; j++) s += g_part[(t*8 + i)*8 + j];
    g_scale[id] = (float)(s / (double)ss.op[t]);
}

__device__ __forceinline__ float tsign(float w, float s) {
    float q = rintf(w / (s + 1e-8f));
    return fmaxf(-1.f, fminf(1.f, q));
}

// ---------------- weight builds (half2 per thread) ----------------
__global__ void build_qkv_k(const float* __restrict__ wq, const float* __restrict__ wk,
                            const float* __restrict__ wv, __half* __restrict__ F) {
    int id = blockIdx.x * 256 + threadIdx.x;        // NQKV_*C_/2
    int r = id >> 10, c = (id & 1023) << 1;
    int t = r >> 11, rr = r & 2047;
    int kb = rr >> 8, o = rr & 255, jb = c >> 8, p = c & 255;
    int i = g_Ji[kb*8 + jb];
    const float* src = (t == 0) ? wq : ((t == 1) ? wk : wv);
    float s = g_scale[t*8 + i];
    float sg = g_Sg[kb*8 + jb];
    float2 w = *(const float2*)&src[((size_t)i << 16) + (o << 8) + p];
    *(__half2*)&F[(size_t)r * C_ + c] =
        __floats2half2_rn(sg * tsign(w.x, s) * s, sg * tsign(w.y, s) * s);
}
__global__ void build_wo_k(const float* __restrict__ wo, __half* __restrict__ F) {
    int id = blockIdx.x * 256 + threadIdx.x;        // C_*C_/2
    int r = id >> 10, c = (id & 1023) << 1;
    int kb = r >> 8, o = r & 255, jb = c >> 8, p = c & 255;
    int i = g_Ji[kb*8 + jb];
    float s = g_scale[24 + i];
    float sg = g_Sg[kb*8 + jb];
    float2 w = *(const float2*)&wo[((size_t)i << 16) + (o << 8) + p];
    *(__half2*)&F[(size_t)r * C_ + c] =
        __floats2half2_rn(sg * tsign(w.x, s) * s, sg * tsign(w.y, s) * s);
}
// interleaved GU: row n (0..11007): hid = (n>>4)*8 + (n&7), type = (n>>3)&1
__global__ void build_gu_k(const float* __restrict__ wg, const float* __restrict__ wu,
                           __half* __restrict__ F) {
    int id = blockIdx.x * 256 + threadIdx.x;        // NGU_*C_/2
    int r = id >> 10, c = (id & 1023) << 1;
    int type = (r >> 3) & 1;
    int hid = ((r >> 4) << 3) + (r & 7);
    int kb = hid / HBLK_, o = hid - kb * HBLK_;
    if (o >= 683) { *(__half2*)&F[(size_t)r * C_ + c] = __floats2half2_rn(0.f, 0.f); return; }
    int jb = c >> 8, p = c & 255;
    int i = g_Ji[kb*8 + jb];
    const float* src = type ? wu : wg;
    float s = g_scale[32 + type*8 + i];
    float sg = g_Sg[kb*8 + jb];
    float2 w = *(const float2*)&src[((size_t)i * 683 + o) * 256 + p];
    *(__half2*)&F[(size_t)r * C_ + c] =
        __floats2half2_rn(sg * tsign(w.x, s) * s, sg * tsign(w.y, s) * s);
}
__global__ void build_d_k(const float* __restrict__ wd, __half* __restrict__ F) {
    int id = blockIdx.x * 256 + threadIdx.x;        // C_*HIDP_/2
    int r = id / (HIDP_/2), c = (id - r * (HIDP_/2)) * 2;
    int jb = c / HBLK_, p = c - jb * HBLK_;
    int kb = r >> 8, o = r & 255;
    int i = g_Ji[kb*8 + jb];
    float s = g_scale[48 + i];
    float sg = g_Sg[kb*8 + jb];
    float v0 = 0.f, v1 = 0.f;
    if (p < 683) {
        const float* base = &wd[((size_t)i * 256 + o) * 683 + p];
        v0 = sg * tsign(base[0], s) * s;
        if (p + 1 < 683) v1 = sg * tsign(base[1], s) * s;
    }
    *(__half2*)&F[(size_t)r * HIDP_ + c] = __floats2half2_rn(v0, v1);
}

// ---------------- rmsnorm -> fp16 ----------------
__global__ void rmsnorm_k(const float* __restrict__ x, const float* __restrict__ w,
                          __half* __restrict__ oh) {
    int row = blockIdx.x;
    const float* xr = x + (size_t)row * C_;
    float s = 0.f;
    for (int c = threadIdx.x; c < C_; c += 256) { float v = xr[c]; s += v * v; }
    __shared__ float red[256];
    red[threadIdx.x] = s; __syncthreads();
    for (int st = 128; st > 0; st >>= 1) {
        if (threadIdx.x < st) red[threadIdx.x] += red[threadIdx.x + st];
        __syncthreads();
    }
    float inv = 1.0f / sqrtf(red[0] / (float)C_ + 1e-6f);
    for (int c = threadIdx.x; c < C_; c += 256)
        oh[(size_t)row * C_ + c] = __float2half(xr[c] * inv * w[c]);
}

// ---------------- 256x128x64 fp16 GEMM, 256 threads, warp tile 64x64, 4 stages ----------------
// mode 0: float out (+addsrc)
// mode 2: half out with fused RoPE (cols < 4096 get rotated)
// mode 3: interleaved silu(gate)*up -> half out [M, N/2]
#define G1_ABYTES 32768    // A: 256 rows x 128B
#define G1_BBYTES 16384    // B: 128 rows x 128B
#define G1_STAGE  49152
#define G1_SMEM   (4 * G1_STAGE)

__global__ __launch_bounds__(256, 1) void gemm1_k(
    const __half* __restrict__ A, const __half* __restrict__ B,
    const float* __restrict__ addsrc, void* __restrict__ outp,
    int M, int N, int K, int mode,
    const float* __restrict__ fc, const float* __restrict__ fs)
{
    extern __shared__ __align__(1024) char smem[];
    int tid = threadIdx.x, wid = tid >> 5, lane = tid & 31;
    int wr = wid >> 1, wc = wid & 1;
    int bm = blockIdx.y * 256, bn = blockIdx.x * 128;
    uint32_t sbase = smem_u32(smem);
    int total = K >> 6;

    float acc[4][8][4];
#pragma unroll
    for (int mt = 0; mt < 4; mt++)
#pragma unroll
        for (int nt = 0; nt < 8; nt++)
#pragma unroll
            for (int e = 0; e < 4; e++) acc[mt][nt][e] = 0.f;

    int a_row = ((lane >> 3) & 1) * 8 + (lane & 7);
    int a_kb  = (lane >> 4) * 16;
    int b_n   = ((lane >> 4) & 1) * 8 + (lane & 7);
    int b_kb  = ((lane >> 3) & 1) * 16;

#define ISSUE1(ch) do {                                                       \
        int k0_ = (ch) << 6;                                                  \
        uint32_t stg_ = sbase + ((ch) & 3) * G1_STAGE;                        \
        _Pragma("unroll")                                                     \
        for (int u = 0; u < 8; u++) {                                         \
            int i_ = tid + u * 256;                                           \
            int row_ = i_ >> 3, seg_ = i_ & 7;                                \
            cp16(stg_ + SW128(row_ * 128 + seg_ * 16),                        \
                 A + (size_t)(bm + row_) * K + k0_ + seg_ * 8);               \
        }                                                                     \
        _Pragma("unroll")                                                     \
        for (int u = 0; u < 4; u++) {                                         \
            int i_ = tid + u * 256;                                           \
            int row_ = i_ >> 3, seg_ = i_ & 7;                                \
            cp16(stg_ + G1_ABYTES + SW128(row_ * 128 + seg_ * 16),            \
                 B + (size_t)(bn + row_) * K + k0_ + seg_ * 8);               \
        }                                                                     \
        asm volatile("cp.async.commit_group;" ::: "memory");                  \
    } while (0)

    ISSUE1(0);
    if (total > 1) ISSUE1(1);
    if (total > 2) ISSUE1(2);
    for (int ch = 0; ch < total; ch++) {
        if (ch + 3 < total) {
            ISSUE1(ch + 3);
            asm volatile("cp.async.wait_group 3;" ::: "memory");
        } else if (ch + 2 < total) {
            asm volatile("cp.async.wait_group 2;" ::: "memory");
        } else if (ch + 1 < total) {
            asm volatile("cp.async.wait_group 1;" ::: "memory");
        } else {
            asm volatile("cp.async.wait_group 0;" ::: "memory");
        }
        __syncthreads();

        uint32_t stg = sbase + (ch & 3) * G1_STAGE;
#pragma unroll
        for (int kk = 0; kk < 4; kk++) {
            uint32_t a[4][4];
#pragma unroll
            for (int mt = 0; mt < 4; mt++) {
                uint32_t byte = (uint32_t)(wr * 64 + mt * 16 + a_row) * 128 + kk * 32 + a_kb;
                ldm_x4(stg + SW128(byte), a[mt][0], a[mt][1], a[mt][2], a[mt][3]);
            }
            uint32_t b[4][4];
#pragma unroll
            for (int np = 0; np < 4; np++) {
                uint32_t byte = (uint32_t)(wc * 64 + np * 16 + b_n) * 128 + kk * 32 + b_kb;
                ldm_x4(stg + G1_ABYTES + SW128(byte), b[np][0], b[np][1], b[np][2], b[np][3]);
            }
#pragma unroll
            for (int mt = 0; mt < 4; mt++)
#pragma unroll
                for (int nt = 0; nt < 8; nt++)
                    mma16816h(acc[mt][nt], a[mt], b[nt >> 1][(nt & 1) * 2],
                              b[nt >> 1][(nt & 1) * 2 + 1]);
        }
        __syncthreads();
    }

    // ---------------- epilogue ----------------
    if (mode == 0) {
        float* Cm = (float*)outp;
#pragma unroll
        for (int mt = 0; mt < 4; mt++)
#pragma unroll
            for (int nt = 0; nt < 8; nt++) {
                int r0 = bm + wr * 64 + mt * 16 + (lane >> 2);
                int c  = bn + wc * 64 + nt * 8 + 2 * (lane & 3);
                size_t i0 = (size_t)r0 * N + c;
                size_t i1 = i0 + (size_t)8 * N;
                float2 v0 = make_float2(acc[mt][nt][0], acc[mt][nt][1]);
                float2 v1 = make_float2(acc[mt][nt][2], acc[mt][nt][3]);
                if (addsrc) {
                    float2 s0 = *(const float2*)&addsrc[i0];
                    float2 s1 = *(const float2*)&addsrc[i1];
                    v0.x += s0.x; v0.y += s0.y;
                    v1.x += s1.x; v1.y += s1.y;
                }
                *(float2*)&Cm[i0] = v0;
                *(float2*)&Cm[i1] = v1;
            }
    } else if (mode == 2) {
        __half* Cm = (__half*)outp;
#pragma unroll
        for (int mt = 0; mt < 4; mt++)
#pragma unroll
            for (int nt = 0; nt < 8; nt++) {
                int r0 = bm + wr * 64 + mt * 16 + (lane >> 2);
                int c  = bn + wc * 64 + nt * 8 + 2 * (lane & 3);
                float x0 = acc[mt][nt][0], y0 = acc[mt][nt][1];
                float x1 = acc[mt][nt][2], y1 = acc[mt][nt][3];
                if (c < 4096) {
                    int dp = (c & 127) >> 1;
                    int t0 = r0 & (T_ - 1), t1 = (r0 + 8) & (T_ - 1);
                    float c0 = fc[t0 * 64 + dp], s0 = fs[t0 * 64 + dp];
                    float c1 = fc[t1 * 64 + dp], s1 = fs[t1 * 64 + dp];
                    float nx0 = x0 * c0 - y0 * s0, ny0 = x0 * s0 + y0 * c0;
                    float nx1 = x1 * c1 - y1 * s1, ny1 = x1 * s1 + y1 * c1;
                    x0 = nx0; y0 = ny0; x1 = nx1; y1 = ny1;
                }
                *(__half2*)&Cm[(size_t)r0 * N + c] = __floats2half2_rn(x0, y0);
                *(__half2*)&Cm[(size_t)(r0 + 8) * N + c] = __floats2half2_rn(x1, y1);
            }
    } else {   // mode 3: silu(gate)*up, interleaved 16-col groups, out width N/2
        __half* Cm = (__half*)outp;
        int NO = N >> 1;
#pragma unroll
        for (int mt = 0; mt < 4; mt++)
#pragma unroll
            for (int ntp = 0; ntp < 4; ntp++) {
                int r0 = bm + wr * 64 + mt * 16 + (lane >> 2);
                int n0 = bn + wc * 64 + ntp * 16 + 2 * (lane & 3);
                int hid = ((n0 >> 4) << 3) + (n0 & 7);
                float* gv = acc[mt][2 * ntp];
                float* uv = acc[mt][2 * ntp + 1];
                float p0 = gv[0] / (1.f + __expf(-gv[0])) * uv[0];
                float p1 = gv[1] / (1.f + __expf(-gv[1])) * uv[1];
                float p2 = gv[2] / (1.f + __expf(-gv[2])) * uv[2];
                float p3 = gv[3] / (1.f + __expf(-gv[3])) * uv[3];
                *(__half2*)&Cm[(size_t)r0 * NO + hid] = __floats2half2_rn(p0, p1);
                *(__half2*)&Cm[(size_t)(r0 + 8) * NO + hid] = __floats2half2_rn(p2, p3);
            }
    }
}

// ---------------- HMMA flash attention ----------------
#define ATT_SMEM 98304     // Q 32K | 2 x (K 16K + V 16K)
__global__ __launch_bounds__(256, 1) void attn_k(
    const __half* __restrict__ qkv, __half* __restrict__ y)
{
    extern __shared__ __align__(1024) char smem[];
    uint32_t sQ = smem_u32(smem);
    int tid = threadIdx.x, wid = tid >> 5, lane = tid & 31;
    int bh = blockIdx.x, qt = blockIdx.y;
    int bb = bh >> 4, h = bh & 15;
    const float sc = 0.08838834764831845f;

    int a_row = ((lane >> 3) & 1) * 8 + (lane & 7);
    int a_kb  = (lane >> 4) * 16;
    int b_n   = ((lane >> 4) & 1) * 8 + (lane & 7);
    int b_kb  = ((lane >> 3) & 1) * 16;
    int v_key = ((lane >> 3) & 1) * 8 + (lane & 7);
    int v_col = ((lane >> 4) & 1) * 8;

    int qrow0 = bb * T_ + qt * 128;

#pragma unroll
    for (int u = 0; u < 8; u++) {
        int i = tid + u * 256;
        int row = i >> 4, seg = i & 15;
        cp16(sQ + SWK(row * 256 + seg * 16),
             qkv + (size_t)(qrow0 + row) * NQKV_ + h * HD_ + seg * 8);
    }
    asm volatile("cp.async.commit_group;" ::: "memory");

    int nkt = 2 * qt + 2;
#define ISSUE_KV(kt_) do {                                                    \
        uint32_t stg_ = sQ + 32768 + ((kt_) & 1) * 32768;                     \
        int kb_ = (kt_) * 64;                                                 \
        _Pragma("unroll")                                                     \
        for (int u = 0; u < 4; u++) {                                         \
            int i_ = tid + u * 256;                                           \
            int row_ = i_ >> 4, seg_ = i_ & 15;                               \
            size_t gr_ = (size_t)(bb * T_ + kb_ + row_) * NQKV_ + h * HD_ + seg_ * 8; \
            uint32_t so_ = SWK(row_ * 256 + seg_ * 16);                       \
            cp16(stg_ + so_, qkv + 2048 + gr_);                               \
            cp16(stg_ + 16384 + so_, qkv + 4096 + gr_);                       \
        }                                                                     \
        asm volatile("cp.async.commit_group;" ::: "memory");                  \
    } while (0)

    ISSUE_KV(0);
    asm volatile("cp.async.wait_group 1;" ::: "memory");
    __syncthreads();

    uint32_t qa[8][4];
#pragma unroll
    for (int kk = 0; kk < 8; kk++) {
        uint32_t byte = (uint32_t)(wid * 16 + a_row) * 256 + kk * 32 + a_kb;
        ldm_x4(sQ + SWK(byte), qa[kk][0], qa[kk][1], qa[kk][2], qa[kk][3]);
    }

    float o[16][4];
#pragma unroll
    for (int nt = 0; nt < 16; nt++)
#pragma unroll
        for (int e = 0; e < 4; e++) o[nt][e] = 0.f;
    float mrun0 = -INFINITY, mrun1 = -INFINITY, lrun0 = 0.f, lrun1 = 0.f;

    int rg0 = qt * 128 + wid * 16 + (lane >> 2);
    int rg1 = rg0 + 8;

    for (int kt = 0; kt < nkt; kt++) {
        if (kt + 1 < nkt) {
            ISSUE_KV(kt + 1);
            asm volatile("cp.async.wait_group 1;" ::: "memory");
        } else {
            asm volatile("cp.async.wait_group 0;" ::: "memory");
        }
        __syncthreads();
        uint32_t sK = sQ + 32768 + (kt & 1) * 32768;
        uint32_t sV = sK + 16384;

        float s[8][4];
#pragma unroll
        for (int nt = 0; nt < 8; nt++)
#pragma unroll
            for (int e = 0; e < 4; e++) s[nt][e] = 0.f;
#pragma unroll
        for (int kk = 0; kk < 8; kk++) {
            uint32_t bq[4][4];
#pragma unroll
            for (int np = 0; np < 4; np++) {
                uint32_t byte = (uint32_t)(np * 16 + b_n) * 256 + kk * 32 + b_kb;
                ldm_x4(sK + SWK(byte), bq[np][0], bq[np][1], bq[np][2], bq[np][3]);
            }
#pragma unroll
            for (int nt = 0; nt < 8; nt++)
                mma16816h(s[nt], qa[kk], bq[nt >> 1][(nt & 1) * 2],
                          bq[nt >> 1][(nt & 1) * 2 + 1]);
        }

        int kb0 = kt * 64;
        bool domask = (kt >= 2 * qt);
        float m0 = -INFINITY, m1 = -INFINITY;
#pragma unroll
        for (int nt = 0; nt < 8; nt++) {
            int k0 = kb0 + nt * 8 + 2 * (lane & 3);
#pragma unroll
            for (int e = 0; e < 4; e++) {
                float sv = s[nt][e] * sc;
                if (domask) {
                    int kc = k0 + (e & 1);
                    int rg = (e < 2) ? rg0 : rg1;
                    if (kc > rg) sv = -1e30f;
                }
                s[nt][e] = sv;
            }
            m0 = fmaxf(m0, fmaxf(s[nt][0], s[nt][1]));
            m1 = fmaxf(m1, fmaxf(s[nt][2], s[nt][3]));
        }
        m0 = fmaxf(m0, __shfl_xor_sync(0xffffffffu, m0, 1));
        m0 = fmaxf(m0, __shfl_xor_sync(0xffffffffu, m0, 2));
        m1 = fmaxf(m1, __shfl_xor_sync(0xffffffffu, m1, 1));
        m1 = fmaxf(m1, __shfl_xor_sync(0xffffffffu, m1, 2));
        float mn0 = fmaxf(mrun0, m0), mn1 = fmaxf(mrun1, m1);
        float al0 = __expf(mrun0 - mn0), al1 = __expf(mrun1 - mn1);
        mrun0 = mn0; mrun1 = mn1;
        float ls0 = 0.f, ls1 = 0.f;
#pragma unroll
        for (int nt = 0; nt < 8; nt++) {
            s[nt][0] = __expf(s[nt][0] - mn0);
            s[nt][1] = __expf(s[nt][1] - mn0);
            s[nt][2] = __expf(s[nt][2] - mn1);
            s[nt][3] = __expf(s[nt][3] - mn1);
            ls0 += s[nt][0] + s[nt][1];
            ls1 += s[nt][2] + s[nt][3];
        }
        ls0 += __shfl_xor_sync(0xffffffffu, ls0, 1);
        ls0 += __shfl_xor_sync(0xffffffffu, ls0, 2);
        ls1 += __shfl_xor_sync(0xffffffffu, ls1, 1);
        ls1 += __shfl_xor_sync(0xffffffffu, ls1, 2);
        lrun0 = lrun0 * al0 + ls0;
        lrun1 = lrun1 * al1 + ls1;
#pragma unroll
        for (int nt = 0; nt < 16; nt++) {
            o[nt][0] *= al0; o[nt][1] *= al0;
            o[nt][2] *= al1; o[nt][3] *= al1;
        }

#pragma unroll
        for (int ks = 0; ks < 4; ks++) {
            uint32_t pa[4];
            pa[0] = packh2(s[2*ks][0],   s[2*ks][1]);
            pa[1] = packh2(s[2*ks][2],   s[2*ks][3]);
            pa[2] = packh2(s[2*ks+1][0], s[2*ks+1][1]);
            pa[3] = packh2(s[2*ks+1][2], s[2*ks+1][3]);
#pragma unroll
            for (int nv = 0; nv < 8; nv++) {
                uint32_t r0, r1, r2, r3;
                uint32_t byte = (uint32_t)(ks * 16 + v_key) * 256 + (nv * 16 + v_col) * 2;
                ldm_x4t(sV + SWK(byte), r0, r1, r2, r3);
                mma16816h(o[2*nv],     pa, r0, r1);
                mma16816h(o[2*nv + 1], pa, r2, r3);
            }
        }
        __syncthreads();
    }

    float il0 = 1.f / lrun0, il1 = 1.f / lrun1;
    size_t row0 = (size_t)bb * T_ + rg0;
    size_t row1 = row0 + 8;
#pragma unroll
    for (int nt = 0; nt < 16; nt++) {
        int c = h * HD_ + nt * 8 + 2 * (lane & 3);
        *(__half2*)&y[row0 * C_ + c] = __floats2half2_rn(o[nt][0] * il0, o[nt][1] * il0);
        *(__half2*)&y[row1 * C_ + c] = __floats2half2_rn(o[nt][2] * il1, o[nt][3] * il1);
    }
}

// ---------------- launch ----------------
extern "C" void kernel_launch(void* const* d_in, const int* in_sizes, int n_in,
                              void* d_out, int out_size) {
    const float* x   = (const float*)d_in[0];
    const float* fc  = (const float*)d_in[1];
    const float* fs  = (const float*)d_in[2];
    const float* anw = (const float*)d_in[3];
    const float* fnw = (const float*)d_in[4];
    const float* wq  = (const float*)d_in[5];
    const float* wk  = (const float*)d_in[6];
    const float* wv  = (const float*)d_in[7];
    const float* wo  = (const float*)d_in[8];
    const float* wg  = (const float*)d_in[9];
    const float* wu  = (const float*)d_in[10];
    const float* wd  = (const float*)d_in[11];
    float* out = (float*)d_out;

    __half *Wqkv, *Wo, *Wgu, *Wd, *XN, *Y, *HN, *PR, *QKV;
    float *Hb;
    cudaGetSymbolAddress((void**)&Wqkv, g_Wqkv);
    cudaGetSymbolAddress((void**)&Wo,   g_Wo);
    cudaGetSymbolAddress((void**)&Wgu,  g_Wgu);
    cudaGetSymbolAddress((void**)&Wd,   g_Wd);
    cudaGetSymbolAddress((void**)&XN,   g_XN);
    cudaGetSymbolAddress((void**)&Y,    g_Y);
    cudaGetSymbolAddress((void**)&HN,   g_HN);
    cudaGetSymbolAddress((void**)&PR,   g_PR);
    cudaGetSymbolAddress((void**)&QKV,  g_QKV);
    cudaGetSymbolAddress((void**)&Hb,   g_Hb);

    cudaFuncSetAttribute(attn_k, cudaFuncAttributeMaxDynamicSharedMemorySize, ATT_SMEM);
    cudaFuncSetAttribute(gemm1_k, cudaFuncAttributeMaxDynamicSharedMemorySize, G1_SMEM);

    build_tables_k<<<1, 1>>>();

    ScaleSrc ss;
    ss.p[0] = wq; ss.p[1] = wk; ss.p[2] = wv; ss.p[3] = wo;
    ss.p[4] = wg; ss.p[5] = wu; ss.p[6] = wd;
    ss.op[0] = ss.op[1] = ss.op[2] = ss.op[3] = 65536;
    ss.op[4] = ss.op[5] = ss.op[6] = 683 * 256;
    scales_part_k<<<dim3(8, 8, 7), 256>>>(ss);
    scales_fin_k<<<1, 56>>>(ss);

    build_qkv_k<<<(NQKV_ * C_ / 2) / 256, 256>>>(wq, wk, wv, Wqkv);
    build_wo_k<<<(C_ * C_ / 2) / 256, 256>>>(wo, Wo);
    build_gu_k<<<(NGU_ * C_ / 2) / 256, 256>>>(wg, wu, Wgu);
    build_d_k<<<(C_ * HIDP_ / 2) / 256, 256>>>(wd, Wd);

    rmsnorm_k<<<BT_, 256>>>(x, anw, XN);

    gemm1_k<<<dim3(NQKV_ / 128, BT_ / 256), 256, G1_SMEM>>>(
        XN, Wqkv, nullptr, QKV, BT_, NQKV_, C_, 2, fc, fs);

    attn_k<<<dim3(64, 8), 256, ATT_SMEM>>>(QKV, Y);

    gemm1_k<<<dim3(C_ / 128, BT_ / 256), 256, G1_SMEM>>>(
        Y, Wo, x, Hb, BT_, C_, C_, 0, nullptr, nullptr);

    rmsnorm_k<<<BT_, 256>>>(Hb, fnw, HN);

    gemm1_k<<<dim3(NGU_ / 128, BT_ / 256), 256, G1_SMEM>>>(
        HN, Wgu, nullptr, PR, BT_, NGU_, C_, 3, nullptr, nullptr);

    gemm1_k<<<dim3(C_ / 128, BT_ / 256), 256, G1_SMEM>>>(
        PR, Wd, Hb, out, BT_, C_, HIDP_, 0, nullptr, nullptr);
}

// round 12
// speedup vs baseline: 1.0627x; 1.0627x over previous
#include <cuda_runtime.h>
#include <cuda_bf16.h>
#include <cuda_fp16.h>
#include <math.h>
#include <stdint.h>

// ---------------- problem constants ----------------
#define BT_    4096          // B*T
#define C_     2048
#define T_     1024
#define H_     16
#define HD_    128
#define HID_   5464
#define HBLK_  688           // padded hidden block
#define HIDP_  5504          // 8*688
#define NQKV_  6144
#define NGU_   11008         // interleaved gate/up

// ---------------- helpers ----------------
__device__ __forceinline__ uint32_t smem_u32(const void* p) {
    uint32_t a;
    asm("{ .reg .u64 t; cvta.to.shared.u64 t, %1; cvt.u32.u64 %0, t; }" : "=r"(a) : "l"(p));
    return a;
}
#define SW128(o) ((o) ^ (((o) >> 3) & 0x70))          // 128B-row swizzle
#define SWK(o)   ((o) ^ ((((o) >> 8) & 7) << 4))      // 256B-row swizzle

__device__ __forceinline__ void cp16(uint32_t s, const void* g) {
    asm volatile("cp.async.cg.shared.global [%0], [%1], 16;"
                 :: "r"(s), "l"(__cvta_generic_to_global(g)));
}
__device__ __forceinline__ void ldm_x4(uint32_t addr, uint32_t& r0, uint32_t& r1,
                                       uint32_t& r2, uint32_t& r3) {
    asm volatile("ldmatrix.sync.aligned.m8n8.x4.shared.b16 {%0,%1,%2,%3}, [%4];"
                 : "=r"(r0), "=r"(r1), "=r"(r2), "=r"(r3) : "r"(addr));
}
__device__ __forceinline__ void ldm_x4t(uint32_t addr, uint32_t& r0, uint32_t& r1,
                                        uint32_t& r2, uint32_t& r3) {
    asm volatile("ldmatrix.sync.aligned.m8n8.x4.trans.shared.b16 {%0,%1,%2,%3}, [%4];"
                 : "=r"(r0), "=r"(r1), "=r"(r2), "=r"(r3) : "r"(addr));
}
__device__ __forceinline__ void mma16816h(float* c, const uint32_t* a, uint32_t b0, uint32_t b1) {
    asm volatile(
        "mma.sync.aligned.m16n8k16.row.col.f32.f16.f16.f32 "
        "{%0,%1,%2,%3}, {%4,%5,%6,%7}, {%8,%9}, {%0,%1,%2,%3};"
        : "+f"(c[0]), "+f"(c[1]), "+f"(c[2]), "+f"(c[3])
        : "r"(a[0]), "r"(a[1]), "r"(a[2]), "r"(a[3]), "r"(b0), "r"(b1));
}
__device__ __forceinline__ uint32_t packh2(float x, float y) {
    __half2 h = __floats2half2_rn(x, y);
    return *(uint32_t*)&h;
}

// ---------------- scratch (device globals, no allocs) ----------------
__device__ __half g_Wqkv[(size_t)NQKV_*C_];
__device__ __half g_Wo  [(size_t)C_*C_];
__device__ __half g_Wgu [(size_t)NGU_*C_];   // interleaved: 16-col groups (8 gate + 8 up)
__device__ __half g_Wd  [(size_t)C_*HIDP_];
__device__ __half g_XN  [(size_t)BT_*C_];
__device__ __half g_Y   [(size_t)BT_*C_];
__device__ __half g_HN  [(size_t)BT_*C_];
__device__ __half g_PR  [(size_t)BT_*HIDP_];
__device__ __half g_QKV [(size_t)BT_*NQKV_];
__device__ float  g_Hb  [(size_t)BT_*C_];
__device__ int    g_Ji[64];
__device__ float  g_Sg[64];
__device__ float  g_scale[56];
__device__ double g_part[7*8*8];

struct ScaleSrc { const float* p[7]; int op[7]; };

// ---------------- octonion table ----------------
__global__ void build_tables_k() {
    int idx[8][8]; float sg[8][8];
    for (int j = 0; j < 8; j++) { idx[0][j] = j; sg[0][j] = 1.f; }
    for (int i = 1; i < 8; i++) {
        idx[i][0] = i; sg[i][0] = 1.f;
        idx[i][i] = 0; sg[i][i] = -1.f;
    }
    const int tr[7][3] = {{1,2,3},{1,4,5},{1,7,6},{2,4,6},{2,5,7},{3,4,7},{3,6,5}};
    for (int t = 0; t < 7; t++) {
        int a = tr[t][0], b = tr[t][1], c = tr[t][2];
        int per[3][3] = {{a,b,c},{b,c,a},{c,a,b}};
        for (int u = 0; u < 3; u++) {
            int p = per[u][0], q = per[u][1], r = per[u][2];
            idx[p][q] = r; sg[p][q] = 1.f;
            idx[q][p] = r; sg[q][p] = -1.f;
        }
    }
    for (int i = 0; i < 8; i++)
        for (int j = 0; j < 8; j++) {
            int k = idx[i][j];
            g_Ji[k*8 + j] = i;
            g_Sg[k*8 + j] = sg[i][j];
        }
}

// ---------------- scales ----------------
__global__ void scales_part_k(ScaleSrc ss) {
    int t = blockIdx.z, i = blockIdx.x, sl = blockIdx.y;
    int OP = ss.op[t];
    const float* Wi = ss.p[t] + (size_t)i * OP;
    int per = (OP + 7) / 8;
    int st = sl * per, en = min(OP, st + per);
    double s = 0.0;
    for (int u = st + threadIdx.x; u < en; u += 256) s += (double)fabsf(Wi[u]);
    __shared__ double red[256];
    red[threadIdx.x] = s; __syncthreads();
    for (int stp = 128; stp > 0; stp >>= 1) {
        if (threadIdx.x < stp) red[threadIdx.x] += red[threadIdx.x + stp];
        __syncthreads();
    }
    if (threadIdx.x == 0) g_part[(t*8 + i)*8 + sl] = red[0];
}
__global__ void scales_fin_k(ScaleSrc ss) {
    int id = threadIdx.x;
    int t = id >> 3, i = id & 7;
    double s = 0.0;
    for (int j = 0; j < 8; j++) s += g_part[(t*8 + i)*8 + j];
    g_scale[id] = (float)(s / (double)ss.op[t]);
}

__device__ __forceinline__ float tsign(float w, float s) {
    float q = rintf(w / (s + 1e-8f));
    return fmaxf(-1.f, fminf(1.f, q));
}

// ---------------- weight builds (half2 per thread) ----------------
__global__ void build_qkv_k(const float* __restrict__ wq, const float* __restrict__ wk,
                            const float* __restrict__ wv, __half* __restrict__ F) {
    int id = blockIdx.x * 256 + threadIdx.x;        // NQKV_*C_/2
    int r = id >> 10, c = (id & 1023) << 1;
    int t = r >> 11, rr = r & 2047;
    int kb = rr >> 8, o = rr & 255, jb = c >> 8, p = c & 255;
    int i = g_Ji[kb*8 + jb];
    const float* src = (t == 0) ? wq : ((t == 1) ? wk : wv);
    float s = g_scale[t*8 + i];
    float sg = g_Sg[kb*8 + jb];
    float2 w = *(const float2*)&src[((size_t)i << 16) + (o << 8) + p];
    *(__half2*)&F[(size_t)r * C_ + c] =
        __floats2half2_rn(sg * tsign(w.x, s) * s, sg * tsign(w.y, s) * s);
}
__global__ void build_wo_k(const float* __restrict__ wo, __half* __restrict__ F) {
    int id = blockIdx.x * 256 + threadIdx.x;        // C_*C_/2
    int r = id >> 10, c = (id & 1023) << 1;
    int kb = r >> 8, o = r & 255, jb = c >> 8, p = c & 255;
    int i = g_Ji[kb*8 + jb];
    float s = g_scale[24 + i];
    float sg = g_Sg[kb*8 + jb];
    float2 w = *(const float2*)&wo[((size_t)i << 16) + (o << 8) + p];
    *(__half2*)&F[(size_t)r * C_ + c] =
        __floats2half2_rn(sg * tsign(w.x, s) * s, sg * tsign(w.y, s) * s);
}
// interleaved GU: row n (0..11007): hid = (n>>4)*8 + (n&7), type = (n>>3)&1
__global__ void build_gu_k(const float* __restrict__ wg, const float* __restrict__ wu,
                           __half* __restrict__ F) {
    int id = blockIdx.x * 256 + threadIdx.x;        // NGU_*C_/2
    int r = id >> 10, c = (id & 1023) << 1;
    int type = (r >> 3) & 1;
    int hid = ((r >> 4) << 3) + (r & 7);
    int kb = hid / HBLK_, o = hid - kb * HBLK_;
    if (o >= 683) { *(__half2*)&F[(size_t)r * C_ + c] = __floats2half2_rn(0.f, 0.f); return; }
    int jb = c >> 8, p = c & 255;
    int i = g_Ji[kb*8 + jb];
    const float* src = type ? wu : wg;
    float s = g_scale[32 + type*8 + i];
    float sg = g_Sg[kb*8 + jb];
    float2 w = *(const float2*)&src[((size_t)i * 683 + o) * 256 + p];
    *(__half2*)&F[(size_t)r * C_ + c] =
        __floats2half2_rn(sg * tsign(w.x, s) * s, sg * tsign(w.y, s) * s);
}
__global__ void build_d_k(const float* __restrict__ wd, __half* __restrict__ F) {
    int id = blockIdx.x * 256 + threadIdx.x;        // C_*HIDP_/2
    int r = id / (HIDP_/2), c = (id - r * (HIDP_/2)) * 2;
    int jb = c / HBLK_, p = c - jb * HBLK_;
    int kb = r >> 8, o = r & 255;
    int i = g_Ji[kb*8 + jb];
    float s = g_scale[48 + i];
    float sg = g_Sg[kb*8 + jb];
    float v0 = 0.f, v1 = 0.f;
    if (p < 683) {
        const float* base = &wd[((size_t)i * 256 + o) * 683 + p];
        v0 = sg * tsign(base[0], s) * s;
        if (p + 1 < 683) v1 = sg * tsign(base[1], s) * s;
    }
    *(__half2*)&F[(size_t)r * HIDP_ + c] = __floats2half2_rn(v0, v1);
}

// ---------------- rmsnorm -> fp16 ----------------
__global__ void rmsnorm_k(const float* __restrict__ x, const float* __restrict__ w,
                          __half* __restrict__ oh) {
    int row = blockIdx.x;
    const float* xr = x + (size_t)row * C_;
    float s = 0.f;
    for (int c = threadIdx.x; c < C_; c += 256) { float v = xr[c]; s += v * v; }
    __shared__ float red[256];
    red[threadIdx.x] = s; __syncthreads();
    for (int st = 128; st > 0; st >>= 1) {
        if (threadIdx.x < st) red[threadIdx.x] += red[threadIdx.x + st];
        __syncthreads();
    }
    float inv = 1.0f / sqrtf(red[0] / (float)C_ + 1e-6f);
    for (int c = threadIdx.x; c < C_; c += 256)
        oh[(size_t)row * C_ + c] = __float2half(xr[c] * inv * w[c]);
}

// ---------------- 128x128x64 fp16 GEMM, 128 threads (4 warps 2x2, warp 64x64), ----------------
// 3 stages, 2 CTAs/SM. Fused epilogues:
// mode 0: float out (+addsrc)
// mode 2: half out with fused RoPE (cols < 4096 get rotated)
// mode 3: interleaved silu(gate)*up -> half out [M, N/2]
#define G1_ABYTES 16384
#define G1_STAGE  32768    // A 16KB | B 16KB
#define G1_SMEM   (3 * G1_STAGE)

__global__ __launch_bounds__(128, 2) void gemm1_k(
    const __half* __restrict__ A, const __half* __restrict__ B,
    const float* __restrict__ addsrc, void* __restrict__ outp,
    int M, int N, int K, int mode,
    const float* __restrict__ fc, const float* __restrict__ fs)
{
    extern __shared__ __align__(1024) char smem[];
    int tid = threadIdx.x, wid = tid >> 5, lane = tid & 31;
    int wr = wid >> 1, wc = wid & 1;
    int bm = blockIdx.y * 128, bn = blockIdx.x * 128;
    uint32_t sbase = smem_u32(smem);
    int total = K >> 6;

    float acc[4][8][4];
#pragma unroll
    for (int mt = 0; mt < 4; mt++)
#pragma unroll
        for (int nt = 0; nt < 8; nt++)
#pragma unroll
            for (int e = 0; e < 4; e++) acc[mt][nt][e] = 0.f;

    int a_row = ((lane >> 3) & 1) * 8 + (lane & 7);
    int a_kb  = (lane >> 4) * 16;
    int b_n   = ((lane >> 4) & 1) * 8 + (lane & 7);
    int b_kb  = ((lane >> 3) & 1) * 16;

#define ISSUE1(ch) do {                                                       \
        int k0_ = (ch) << 6;                                                  \
        uint32_t stg_ = sbase + ((ch) % 3) * G1_STAGE;                        \
        _Pragma("unroll")                                                     \
        for (int u = 0; u < 8; u++) {                                         \
            int i_ = tid + u * 128;                                           \
            int row_ = i_ >> 3, seg_ = i_ & 7;                                \
            uint32_t so_ = SW128(row_ * 128 + seg_ * 16);                     \
            cp16(stg_ + so_, A + (size_t)(bm + row_) * K + k0_ + seg_ * 8);   \
            cp16(stg_ + G1_ABYTES + so_,                                      \
                 B + (size_t)(bn + row_) * K + k0_ + seg_ * 8);               \
        }                                                                     \
        asm volatile("cp.async.commit_group;" ::: "memory");                  \
    } while (0)

    ISSUE1(0);
    if (total > 1) ISSUE1(1);
    for (int ch = 0; ch < total; ch++) {
        if (ch + 2 < total) {
            ISSUE1(ch + 2);
            asm volatile("cp.async.wait_group 2;" ::: "memory");
        } else if (ch + 1 < total) {
            asm volatile("cp.async.wait_group 1;" ::: "memory");
        } else {
            asm volatile("cp.async.wait_group 0;" ::: "memory");
        }
        __syncthreads();

        uint32_t stg = sbase + (ch % 3) * G1_STAGE;
#pragma unroll
        for (int kk = 0; kk < 4; kk++) {
            uint32_t a[4][4];
#pragma unroll
            for (int mt = 0; mt < 4; mt++) {
                uint32_t byte = (uint32_t)(wr * 64 + mt * 16 + a_row) * 128 + kk * 32 + a_kb;
                ldm_x4(stg + SW128(byte), a[mt][0], a[mt][1], a[mt][2], a[mt][3]);
            }
            uint32_t b[4][4];
#pragma unroll
            for (int np = 0; np < 4; np++) {
                uint32_t byte = (uint32_t)(wc * 64 + np * 16 + b_n) * 128 + kk * 32 + b_kb;
                ldm_x4(stg + G1_ABYTES + SW128(byte), b[np][0], b[np][1], b[np][2], b[np][3]);
            }
#pragma unroll
            for (int mt = 0; mt < 4; mt++)
#pragma unroll
                for (int nt = 0; nt < 8; nt++)
                    mma16816h(acc[mt][nt], a[mt], b[nt >> 1][(nt & 1) * 2],
                              b[nt >> 1][(nt & 1) * 2 + 1]);
        }
        __syncthreads();
    }

    // ---------------- epilogue ----------------
    if (mode == 0) {
        float* Cm = (float*)outp;
#pragma unroll
        for (int mt = 0; mt < 4; mt++)
#pragma unroll
            for (int nt = 0; nt < 8; nt++) {
                int r0 = bm + wr * 64 + mt * 16 + (lane >> 2);
                int c  = bn + wc * 64 + nt * 8 + 2 * (lane & 3);
                size_t i0 = (size_t)r0 * N + c;
                size_t i1 = i0 + (size_t)8 * N;
                float2 v0 = make_float2(acc[mt][nt][0], acc[mt][nt][1]);
                float2 v1 = make_float2(acc[mt][nt][2], acc[mt][nt][3]);
                if (addsrc) {
                    float2 s0 = *(const float2*)&addsrc[i0];
                    float2 s1 = *(const float2*)&addsrc[i1];
                    v0.x += s0.x; v0.y += s0.y;
                    v1.x += s1.x; v1.y += s1.y;
                }
                *(float2*)&Cm[i0] = v0;
                *(float2*)&Cm[i1] = v1;
            }
    } else if (mode == 2) {
        __half* Cm = (__half*)outp;
#pragma unroll
        for (int mt = 0; mt < 4; mt++)
#pragma unroll
            for (int nt = 0; nt < 8; nt++) {
                int r0 = bm + wr * 64 + mt * 16 + (lane >> 2);
                int c  = bn + wc * 64 + nt * 8 + 2 * (lane & 3);
                float x0 = acc[mt][nt][0], y0 = acc[mt][nt][1];
                float x1 = acc[mt][nt][2], y1 = acc[mt][nt][3];
                if (c < 4096) {
                    int dp = (c & 127) >> 1;
                    int t0 = r0 & (T_ - 1), t1 = (r0 + 8) & (T_ - 1);
                    float c0 = fc[t0 * 64 + dp], s0 = fs[t0 * 64 + dp];
                    float c1 = fc[t1 * 64 + dp], s1 = fs[t1 * 64 + dp];
                    float nx0 = x0 * c0 - y0 * s0, ny0 = x0 * s0 + y0 * c0;
                    float nx1 = x1 * c1 - y1 * s1, ny1 = x1 * s1 + y1 * c1;
                    x0 = nx0; y0 = ny0; x1 = nx1; y1 = ny1;
                }
                *(__half2*)&Cm[(size_t)r0 * N + c] = __floats2half2_rn(x0, y0);
                *(__half2*)&Cm[(size_t)(r0 + 8) * N + c] = __floats2half2_rn(x1, y1);
            }
    } else {   // mode 3: silu(gate)*up, interleaved 16-col groups, out width N/2
        __half* Cm = (__half*)outp;
        int NO = N >> 1;
#pragma unroll
        for (int mt = 0; mt < 4; mt++)
#pragma unroll
            for (int ntp = 0; ntp < 4; ntp++) {
                int r0 = bm + wr * 64 + mt * 16 + (lane >> 2);
                int n0 = bn + wc * 64 + ntp * 16 + 2 * (lane & 3);
                int hid = ((n0 >> 4) << 3) + (n0 & 7);
                float* gv = acc[mt][2 * ntp];
                float* uv = acc[mt][2 * ntp + 1];
                float p0 = gv[0] / (1.f + __expf(-gv[0])) * uv[0];
                float p1 = gv[1] / (1.f + __expf(-gv[1])) * uv[1];
                float p2 = gv[2] / (1.f + __expf(-gv[2])) * uv[2];
                float p3 = gv[3] / (1.f + __expf(-gv[3])) * uv[3];
                *(__half2*)&Cm[(size_t)r0 * NO + hid] = __floats2half2_rn(p0, p1);
                *(__half2*)&Cm[(size_t)(r0 + 8) * NO + hid] = __floats2half2_rn(p2, p3);
            }
    }
}

// ---------------- HMMA flash attention ----------------
#define ATT_SMEM 98304     // Q 32K | 2 x (K 16K + V 16K)
__global__ __launch_bounds__(256, 1) void attn_k(
    const __half* __restrict__ qkv, __half* __restrict__ y)
{
    extern __shared__ __align__(1024) char smem[];
    uint32_t sQ = smem_u32(smem);
    int tid = threadIdx.x, wid = tid >> 5, lane = tid & 31;
    int bh = blockIdx.x, qt = blockIdx.y;
    int bb = bh >> 4, h = bh & 15;
    const float sc = 0.08838834764831845f;

    int a_row = ((lane >> 3) & 1) * 8 + (lane & 7);
    int a_kb  = (lane >> 4) * 16;
    int b_n   = ((lane >> 4) & 1) * 8 + (lane & 7);
    int b_kb  = ((lane >> 3) & 1) * 16;
    int v_key = ((lane >> 3) & 1) * 8 + (lane & 7);
    int v_col = ((lane >> 4) & 1) * 8;

    int qrow0 = bb * T_ + qt * 128;

#pragma unroll
    for (int u = 0; u < 8; u++) {
        int i = tid + u * 256;
        int row = i >> 4, seg = i & 15;
        cp16(sQ + SWK(row * 256 + seg * 16),
             qkv + (size_t)(qrow0 + row) * NQKV_ + h * HD_ + seg * 8);
    }
    asm volatile("cp.async.commit_group;" ::: "memory");

    int nkt = 2 * qt + 2;
#define ISSUE_KV(kt_) do {                                                    \
        uint32_t stg_ = sQ + 32768 + ((kt_) & 1) * 32768;                     \
        int kb_ = (kt_) * 64;                                                 \
        _Pragma("unroll")                                                     \
        for (int u = 0; u < 4; u++) {                                         \
            int i_ = tid + u * 256;                                           \
            int row_ = i_ >> 4, seg_ = i_ & 15;                               \
            size_t gr_ = (size_t)(bb * T_ + kb_ + row_) * NQKV_ + h * HD_ + seg_ * 8; \
            uint32_t so_ = SWK(row_ * 256 + seg_ * 16);                       \
            cp16(stg_ + so_, qkv + 2048 + gr_);                               \
            cp16(stg_ + 16384 + so_, qkv + 4096 + gr_);                       \
        }                                                                     \
        asm volatile("cp.async.commit_group;" ::: "memory");                  \
    } while (0)

    ISSUE_KV(0);
    asm volatile("cp.async.wait_group 1;" ::: "memory");
    __syncthreads();

    uint32_t qa[8][4];
#pragma unroll
    for (int kk = 0; kk < 8; kk++) {
        uint32_t byte = (uint32_t)(wid * 16 + a_row) * 256 + kk * 32 + a_kb;
        ldm_x4(sQ + SWK(byte), qa[kk][0], qa[kk][1], qa[kk][2], qa[kk][3]);
    }

    float o[16][4];
#pragma unroll
    for (int nt = 0; nt < 16; nt++)
#pragma unroll
        for (int e = 0; e < 4; e++) o[nt][e] = 0.f;
    float mrun0 = -INFINITY, mrun1 = -INFINITY, lrun0 = 0.f, lrun1 = 0.f;

    int rg0 = qt * 128 + wid * 16 + (lane >> 2);
    int rg1 = rg0 + 8;

    for (int kt = 0; kt < nkt; kt++) {
        if (kt + 1 < nkt) {
            ISSUE_KV(kt + 1);
            asm volatile("cp.async.wait_group 1;" ::: "memory");
        } else {
            asm volatile("cp.async.wait_group 0;" ::: "memory");
        }
        __syncthreads();
        uint32_t sK = sQ + 32768 + (kt & 1) * 32768;
        uint32_t sV = sK + 16384;

        float s[8][4];
#pragma unroll
        for (int nt = 0; nt < 8; nt++)
#pragma unroll
            for (int e = 0; e < 4; e++) s[nt][e] = 0.f;
#pragma unroll
        for (int kk = 0; kk < 8; kk++) {
            uint32_t bq[4][4];
#pragma unroll
            for (int np = 0; np < 4; np++) {
                uint32_t byte = (uint32_t)(np * 16 + b_n) * 256 + kk * 32 + b_kb;
                ldm_x4(sK + SWK(byte), bq[np][0], bq[np][1], bq[np][2], bq[np][3]);
            }
#pragma unroll
            for (int nt = 0; nt < 8; nt++)
                mma16816h(s[nt], qa[kk], bq[nt >> 1][(nt & 1) * 2],
                          bq[nt >> 1][(nt & 1) * 2 + 1]);
        }

        int kb0 = kt * 64;
        bool domask = (kt >= 2 * qt);
        float m0 = -INFINITY, m1 = -INFINITY;
#pragma unroll
        for (int nt = 0; nt < 8; nt++) {
            int k0 = kb0 + nt * 8 + 2 * (lane & 3);
#pragma unroll
            for (int e = 0; e < 4; e++) {
                float sv = s[nt][e] * sc;
                if (domask) {
                    int kc = k0 + (e & 1);
                    int rg = (e < 2) ? rg0 : rg1;
                    if (kc > rg) sv = -1e30f;
                }
                s[nt][e] = sv;
            }
            m0 = fmaxf(m0, fmaxf(s[nt][0], s[nt][1]));
            m1 = fmaxf(m1, fmaxf(s[nt][2], s[nt][3]));
        }
        m0 = fmaxf(m0, __shfl_xor_sync(0xffffffffu, m0, 1));
        m0 = fmaxf(m0, __shfl_xor_sync(0xffffffffu, m0, 2));
        m1 = fmaxf(m1, __shfl_xor_sync(0xffffffffu, m1, 1));
        m1 = fmaxf(m1, __shfl_xor_sync(0xffffffffu, m1, 2));
        float mn0 = fmaxf(mrun0, m0), mn1 = fmaxf(mrun1, m1);
        float al0 = __expf(mrun0 - mn0), al1 = __expf(mrun1 - mn1);
        mrun0 = mn0; mrun1 = mn1;
        float ls0 = 0.f, ls1 = 0.f;
#pragma unroll
        for (int nt = 0; nt < 8; nt++) {
            s[nt][0] = __expf(s[nt][0] - mn0);
            s[nt][1] = __expf(s[nt][1] - mn0);
            s[nt][2] = __expf(s[nt][2] - mn1);
            s[nt][3] = __expf(s[nt][3] - mn1);
            ls0 += s[nt][0] + s[nt][1];
            ls1 += s[nt][2] + s[nt][3];
        }
        ls0 += __shfl_xor_sync(0xffffffffu, ls0, 1);
        ls0 += __shfl_xor_sync(0xffffffffu, ls0, 2);
        ls1 += __shfl_xor_sync(0xffffffffu, ls1, 1);
        ls1 += __shfl_xor_sync(0xffffffffu, ls1, 2);
        lrun0 = lrun0 * al0 + ls0;
        lrun1 = lrun1 * al1 + ls1;
#pragma unroll
        for (int nt = 0; nt < 16; nt++) {
            o[nt][0] *= al0; o[nt][1] *= al0;
            o[nt][2] *= al1; o[nt][3] *= al1;
        }

#pragma unroll
        for (int ks = 0; ks < 4; ks++) {
            uint32_t pa[4];
            pa[0] = packh2(s[2*ks][0],   s[2*ks][1]);
            pa[1] = packh2(s[2*ks][2],   s[2*ks][3]);
            pa[2] = packh2(s[2*ks+1][0], s[2*ks+1][1]);
            pa[3] = packh2(s[2*ks+1][2], s[2*ks+1][3]);
#pragma unroll
            for (int nv = 0; nv < 8; nv++) {
                uint32_t r0, r1, r2, r3;
                uint32_t byte = (uint32_t)(ks * 16 + v_key) * 256 + (nv * 16 + v_col) * 2;
                ldm_x4t(sV + SWK(byte), r0, r1, r2, r3);
                mma16816h(o[2*nv],     pa, r0, r1);
                mma16816h(o[2*nv + 1], pa, r2, r3);
            }
        }
        __syncthreads();
    }

    float il0 = 1.f / lrun0, il1 = 1.f / lrun1;
    size_t row0 = (size_t)bb * T_ + rg0;
    size_t row1 = row0 + 8;
#pragma unroll
    for (int nt = 0; nt < 16; nt++) {
        int c = h * HD_ + nt * 8 + 2 * (lane & 3);
        *(__half2*)&y[row0 * C_ + c] = __floats2half2_rn(o[nt][0] * il0, o[nt][1] * il0);
        *(__half2*)&y[row1 * C_ + c] = __floats2half2_rn(o[nt][2] * il1, o[nt][3] * il1);
    }
}

// ---------------- launch ----------------
extern "C" void kernel_launch(void* const* d_in, const int* in_sizes, int n_in,
                              void* d_out, int out_size) {
    const float* x   = (const float*)d_in[0];
    const float* fc  = (const float*)d_in[1];
    const float* fs  = (const float*)d_in[2];
    const float* anw = (const float*)d_in[3];
    const float* fnw = (const float*)d_in[4];
    const float* wq  = (const float*)d_in[5];
    const float* wk  = (const float*)d_in[6];
    const float* wv  = (const float*)d_in[7];
    const float* wo  = (const float*)d_in[8];
    const float* wg  = (const float*)d_in[9];
    const float* wu  = (const float*)d_in[10];
    const float* wd  = (const float*)d_in[11];
    float* out = (float*)d_out;

    __half *Wqkv, *Wo, *Wgu, *Wd, *XN, *Y, *HN, *PR, *QKV;
    float *Hb;
    cudaGetSymbolAddress((void**)&Wqkv, g_Wqkv);
    cudaGetSymbolAddress((void**)&Wo,   g_Wo);
    cudaGetSymbolAddress((void**)&Wgu,  g_Wgu);
    cudaGetSymbolAddress((void**)&Wd,   g_Wd);
    cudaGetSymbolAddress((void**)&XN,   g_XN);
    cudaGetSymbolAddress((void**)&Y,    g_Y);
    cudaGetSymbolAddress((void**)&HN,   g_HN);
    cudaGetSymbolAddress((void**)&PR,   g_PR);
    cudaGetSymbolAddress((void**)&QKV,  g_QKV);
    cudaGetSymbolAddress((void**)&Hb,   g_Hb);

    cudaFuncSetAttribute(attn_k, cudaFuncAttributeMaxDynamicSharedMemorySize, ATT_SMEM);
    cudaFuncSetAttribute(gemm1_k, cudaFuncAttributeMaxDynamicSharedMemorySize, G1_SMEM);

    build_tables_k<<<1, 1>>>();

    ScaleSrc ss;
    ss.p[0] = wq; ss.p[1] = wk; ss.p[2] = wv; ss.p[3] = wo;
    ss.p[4] = wg; ss.p[5] = wu; ss.p[6] = wd;
    ss.op[0] = ss.op[1] = ss.op[2] = ss.op[3] = 65536;
    ss.op[4] = ss.op[5] = ss.op[6] = 683 * 256;
    scales_part_k<<<dim3(8, 8, 7), 256>>>(ss);
    scales_fin_k<<<1, 56>>>(ss);

    build_qkv_k<<<(NQKV_ * C_ / 2) / 256, 256>>>(wq, wk, wv, Wqkv);
    build_wo_k<<<(C_ * C_ / 2) / 256, 256>>>(wo, Wo);
    build_gu_k<<<(NGU_ * C_ / 2) / 256, 256>>>(wg, wu, Wgu);
    build_d_k<<<(C_ * HIDP_ / 2) / 256, 256>>>(wd, Wd);

    rmsnorm_k<<<BT_, 256>>>(x, anw, XN);

    gemm1_k<<<dim3(NQKV_ / 128, BT_ / 128), 128, G1_SMEM>>>(
        XN, Wqkv, nullptr, QKV, BT_, NQKV_, C_, 2, fc, fs);

    attn_k<<<dim3(64, 8), 256, ATT_SMEM>>>(QKV, Y);

    gemm1_k<<<dim3(C_ / 128, BT_ / 128), 128, G1_SMEM>>>(
        Y, Wo, x, Hb, BT_, C_, C_, 0, nullptr, nullptr);

    rmsnorm_k<<<BT_, 256>>>(Hb, fnw, HN);

    gemm1_k<<<dim3(NGU_ / 128, BT_ / 128), 128, G1_SMEM>>>(
        HN, Wgu, nullptr, PR, BT_, NGU_, C_, 3, nullptr, nullptr);

    gemm1_k<<<dim3(C_ / 128, BT_ / 128), 128, G1_SMEM>>>(
        PR, Wd, Hb, out, BT_, C_, HIDP_, 0, nullptr, nullptr);
}

// round 13
// speedup vs baseline: 1.1302x; 1.0635x over previous
#include <cuda_runtime.h>
#include <cuda_bf16.h>
#include <cuda_fp16.h>
#include <math.h>
#include <stdint.h>

// ---------------- problem constants ----------------
#define BT_    4096          // B*T
#define C_     2048
#define T_     1024
#define H_     16
#define HD_    128
#define HID_   5464
#define HBLK_  688           // padded hidden block
#define HIDP_  5504          // 8*688
#define NQKV_  6144
#define NGU_   11008         // interleaved gate/up

// ---------------- helpers ----------------
__device__ __forceinline__ uint32_t smem_u32(const void* p) {
    uint32_t a;
    asm("{ .reg .u64 t; cvta.to.shared.u64 t, %1; cvt.u32.u64 %0, t; }" : "=r"(a) : "l"(p));
    return a;
}
#define SW128(o) ((o) ^ (((o) >> 3) & 0x70))          // 128B-row swizzle
#define SWK(o)   ((o) ^ ((((o) >> 8) & 7) << 4))      // 256B-row swizzle

__device__ __forceinline__ void cp16(uint32_t s, const void* g) {
    asm volatile("cp.async.cg.shared.global [%0], [%1], 16;"
                 :: "r"(s), "l"(__cvta_generic_to_global(g)));
}
__device__ __forceinline__ void ldm_x4(uint32_t addr, uint32_t& r0, uint32_t& r1,
                                       uint32_t& r2, uint32_t& r3) {
    asm volatile("ldmatrix.sync.aligned.m8n8.x4.shared.b16 {%0,%1,%2,%3}, [%4];"
                 : "=r"(r0), "=r"(r1), "=r"(r2), "=r"(r3) : "r"(addr));
}
__device__ __forceinline__ void ldm_x4t(uint32_t addr, uint32_t& r0, uint32_t& r1,
                                        uint32_t& r2, uint32_t& r3) {
    asm volatile("ldmatrix.sync.aligned.m8n8.x4.trans.shared.b16 {%0,%1,%2,%3}, [%4];"
                 : "=r"(r0), "=r"(r1), "=r"(r2), "=r"(r3) : "r"(addr));
}
__device__ __forceinline__ void mma16816h(float* c, const uint32_t* a, uint32_t b0, uint32_t b1) {
    asm volatile(
        "mma.sync.aligned.m16n8k16.row.col.f32.f16.f16.f32 "
        "{%0,%1,%2,%3}, {%4,%5,%6,%7}, {%8,%9}, {%0,%1,%2,%3};"
        : "+f"(c[0]), "+f"(c[1]), "+f"(c[2]), "+f"(c[3])
        : "r"(a[0]), "r"(a[1]), "r"(a[2]), "r"(a[3]), "r"(b0), "r"(b1));
}
__device__ __forceinline__ uint32_t packh2(float x, float y) {
    __half2 h = __floats2half2_rn(x, y);
    return *(uint32_t*)&h;
}

// ---------------- scratch (device globals, no allocs) ----------------
__device__ __half g_Wqkv[(size_t)NQKV_*C_];
__device__ __half g_Wo  [(size_t)C_*C_];
__device__ __half g_Wgu [(size_t)NGU_*C_];   // interleaved: 16-col groups (8 gate + 8 up)
__device__ __half g_Wd  [(size_t)C_*HIDP_];
__device__ __half g_XN  [(size_t)BT_*C_];
__device__ __half g_Y   [(size_t)BT_*C_];
__device__ __half g_HN  [(size_t)BT_*C_];
__device__ __half g_PR  [(size_t)BT_*HIDP_];
__device__ __half g_QKV [(size_t)BT_*NQKV_];
__device__ float  g_Hb  [(size_t)BT_*C_];
__device__ int    g_Ji[64];
__device__ float  g_Sg[64];
__device__ float  g_scale[112];   // [0:56) scale, [56:112) 1/(scale+1e-8)
__device__ double g_part[7*8*8];

struct ScaleSrc { const float* p[7]; int op[7]; };

// ---------------- octonion table ----------------
__global__ void build_tables_k() {
    int idx[8][8]; float sg[8][8];
    for (int j = 0; j < 8; j++) { idx[0][j] = j; sg[0][j] = 1.f; }
    for (int i = 1; i < 8; i++) {
        idx[i][0] = i; sg[i][0] = 1.f;
        idx[i][i] = 0; sg[i][i] = -1.f;
    }
    const int tr[7][3] = {{1,2,3},{1,4,5},{1,7,6},{2,4,6},{2,5,7},{3,4,7},{3,6,5}};
    for (int t = 0; t < 7; t++) {
        int a = tr[t][0], b = tr[t][1], c = tr[t][2];
        int per[3][3] = {{a,b,c},{b,c,a},{c,a,b}};
        for (int u = 0; u < 3; u++) {
            int p = per[u][0], q = per[u][1], r = per[u][2];
            idx[p][q] = r; sg[p][q] = 1.f;
            idx[q][p] = r; sg[q][p] = -1.f;
        }
    }
    for (int i = 0; i < 8; i++)
        for (int j = 0; j < 8; j++) {
            int k = idx[i][j];
            g_Ji[k*8 + j] = i;
            g_Sg[k*8 + j] = sg[i][j];
        }
}

// ---------------- scales ----------------
__global__ void scales_part_k(ScaleSrc ss) {
    int t = blockIdx.z, i = blockIdx.x, sl = blockIdx.y;
    int OP = ss.op[t];
    const float* Wi = ss.p[t] + (size_t)i * OP;
    int per = (OP + 7) / 8;
    int st = sl * per, en = min(OP, st + per);
    double s = 0.0;
    for (int u = st + threadIdx.x; u < en; u += 256) s += (double)fabsf(Wi[u]);
    __shared__ double red[256];
    red[threadIdx.x] = s; __syncthreads();
    for (int stp = 128; stp > 0; stp >>= 1) {
        if (threadIdx.x < stp) red[threadIdx.x] += red[threadIdx.x + stp];
        __syncthreads();
    }
    if (threadIdx.x == 0) g_part[(t*8 + i)*8 + sl] = red[0];
}
__global__ void scales_fin_k(ScaleSrc ss) {
    int id = threadIdx.x;       // 56
    int t = id >> 3, i = id & 7;
    double s = 0.0;
    for (int j = 0; j < 8; j++) s += g_part[(t*8 + i)*8 + j];
    float sc = (float)(s / (double)ss.op[t]);
    g_scale[id] = sc;
    g_scale[56 + id] = 1.0f / (sc + 1e-8f);
}

__device__ __forceinline__ float tsign_r(float w, float inv) {
    float q = rintf(w * inv);
    return fmaxf(-1.f, fminf(1.f, q));
}

// ---------------- weight builds (float4 -> 4 elems/thread, reciprocal) ----------------
__global__ void build_qkv_k(const float* __restrict__ wq, const float* __restrict__ wk,
                            const float* __restrict__ wv, __half* __restrict__ F) {
    int id = blockIdx.x * 256 + threadIdx.x;        // NQKV_*C_/4
    int r = id >> 9, c = (id & 511) << 2;
    int t = r >> 11, rr = r & 2047;
    int kb = rr >> 8, o = rr & 255, jb = c >> 8, p = c & 255;
    int i = g_Ji[kb*8 + jb];
    const float* src = (t == 0) ? wq : ((t == 1) ? wk : wv);
    float inv = g_scale[56 + t*8 + i];
    float ss = g_Sg[kb*8 + jb] * g_scale[t*8 + i];
    float4 w = *(const float4*)&src[((size_t)i << 16) + (o << 8) + p];
    size_t ob = (size_t)r * C_ + c;
    *(__half2*)&F[ob]     = __floats2half2_rn(ss * tsign_r(w.x, inv), ss * tsign_r(w.y, inv));
    *(__half2*)&F[ob + 2] = __floats2half2_rn(ss * tsign_r(w.z, inv), ss * tsign_r(w.w, inv));
}
__global__ void build_wo_k(const float* __restrict__ wo, __half* __restrict__ F) {
    int id = blockIdx.x * 256 + threadIdx.x;        // C_*C_/4
    int r = id >> 9, c = (id & 511) << 2;
    int kb = r >> 8, o = r & 255, jb = c >> 8, p = c & 255;
    int i = g_Ji[kb*8 + jb];
    float inv = g_scale[56 + 24 + i];
    float ss = g_Sg[kb*8 + jb] * g_scale[24 + i];
    float4 w = *(const float4*)&wo[((size_t)i << 16) + (o << 8) + p];
    size_t ob = (size_t)r * C_ + c;
    *(__half2*)&F[ob]     = __floats2half2_rn(ss * tsign_r(w.x, inv), ss * tsign_r(w.y, inv));
    *(__half2*)&F[ob + 2] = __floats2half2_rn(ss * tsign_r(w.z, inv), ss * tsign_r(w.w, inv));
}
// interleaved GU: row n (0..11007): hid = (n>>4)*8 + (n&7), type = (n>>3)&1
__global__ void build_gu_k(const float* __restrict__ wg, const float* __restrict__ wu,
                           __half* __restrict__ F) {
    int id = blockIdx.x * 256 + threadIdx.x;        // NGU_*C_/4
    int r = id >> 9, c = (id & 511) << 2;
    int type = (r >> 3) & 1;
    int hid = ((r >> 4) << 3) + (r & 7);
    int kb = hid / HBLK_, o = hid - kb * HBLK_;
    size_t ob = (size_t)r * C_ + c;
    if (o >= 683) {
        *(__half2*)&F[ob] = __floats2half2_rn(0.f, 0.f);
        *(__half2*)&F[ob + 2] = __floats2half2_rn(0.f, 0.f);
        return;
    }
    int jb = c >> 8, p = c & 255;
    int i = g_Ji[kb*8 + jb];
    const float* src = type ? wu : wg;
    float inv = g_scale[56 + 32 + type*8 + i];
    float ss = g_Sg[kb*8 + jb] * g_scale[32 + type*8 + i];
    float4 w = *(const float4*)&src[((size_t)i * 683 + o) * 256 + p];
    *(__half2*)&F[ob]     = __floats2half2_rn(ss * tsign_r(w.x, inv), ss * tsign_r(w.y, inv));
    *(__half2*)&F[ob + 2] = __floats2half2_rn(ss * tsign_r(w.z, inv), ss * tsign_r(w.w, inv));
}
__global__ void build_d_k(const float* __restrict__ wd, __half* __restrict__ F) {
    int id = blockIdx.x * 256 + threadIdx.x;        // C_*HIDP_/2
    int r = id / (HIDP_/2), c = (id - r * (HIDP_/2)) * 2;
    int jb = c / HBLK_, p = c - jb * HBLK_;
    int kb = r >> 8, o = r & 255;
    int i = g_Ji[kb*8 + jb];
    float inv = g_scale[56 + 48 + i];
    float ss = g_Sg[kb*8 + jb] * g_scale[48 + i];
    float v0 = 0.f, v1 = 0.f;
    if (p < 683) {
        const float* base = &wd[((size_t)i * 256 + o) * 683 + p];
        v0 = ss * tsign_r(base[0], inv);
        if (p + 1 < 683) v1 = ss * tsign_r(base[1], inv);
    }
    *(__half2*)&F[(size_t)r * HIDP_ + c] = __floats2half2_rn(v0, v1);
}

// ---------------- rmsnorm -> fp16 (float4) ----------------
__global__ void rmsnorm_k(const float* __restrict__ x, const float* __restrict__ w,
                          __half* __restrict__ oh) {
    int row = blockIdx.x;
    const float4* xr = (const float4*)(x + (size_t)row * C_);
    const float4* wr = (const float4*)w;
    float4 v0 = xr[threadIdx.x];
    float4 v1 = xr[threadIdx.x + 256];
    float s = v0.x*v0.x + v0.y*v0.y + v0.z*v0.z + v0.w*v0.w
            + v1.x*v1.x + v1.y*v1.y + v1.z*v1.z + v1.w*v1.w;
    __shared__ float red[256];
    red[threadIdx.x] = s; __syncthreads();
    for (int st = 128; st > 0; st >>= 1) {
        if (threadIdx.x < st) red[threadIdx.x] += red[threadIdx.x + st];
        __syncthreads();
    }
    float inv = 1.0f / sqrtf(red[0] / (float)C_ + 1e-6f);
    float4 w0 = wr[threadIdx.x];
    float4 w1 = wr[threadIdx.x + 256];
    size_t base = (size_t)row * C_;
    int c0 = threadIdx.x * 4;
    *(__half2*)&oh[base + c0]     = __floats2half2_rn(v0.x*inv*w0.x, v0.y*inv*w0.y);
    *(__half2*)&oh[base + c0 + 2] = __floats2half2_rn(v0.z*inv*w0.z, v0.w*inv*w0.w);
    int c1 = c0 + 1024;
    *(__half2*)&oh[base + c1]     = __floats2half2_rn(v1.x*inv*w1.x, v1.y*inv*w1.y);
    *(__half2*)&oh[base + c1 + 2] = __floats2half2_rn(v1.z*inv*w1.z, v1.w*inv*w1.w);
}

// ---------------- 128x128x64 fp16 GEMM, 256 threads, 2 CTAs/SM, fused epilogues ----------------
// (exact R10 configuration — best measured)
// mode 0: float out (+addsrc)
// mode 2: half out with fused RoPE (cols < 4096 get rotated)
// mode 3: interleaved silu(gate)*up -> half out [M, N/2]
#define G1_ABYTES 16384
#define G1_STAGE  32768    // A 16KB | B 16KB
#define G1_SMEM   (3 * G1_STAGE)

__global__ __launch_bounds__(256, 2) void gemm1_k(
    const __half* __restrict__ A, const __half* __restrict__ B,
    const float* __restrict__ addsrc, void* __restrict__ outp,
    int M, int N, int K, int mode,
    const float* __restrict__ fc, const float* __restrict__ fs)
{
    extern __shared__ __align__(1024) char smem[];
    int tid = threadIdx.x, wid = tid >> 5, lane = tid & 31;
    int wr = wid >> 1, wc = wid & 1;
    int bm = blockIdx.y * 128, bn = blockIdx.x * 128;
    uint32_t sbase = smem_u32(smem);
    int total = K >> 6;

    float acc[2][8][4];
#pragma unroll
    for (int mt = 0; mt < 2; mt++)
#pragma unroll
        for (int nt = 0; nt < 8; nt++)
#pragma unroll
            for (int e = 0; e < 4; e++) acc[mt][nt][e] = 0.f;

    int a_row = ((lane >> 3) & 1) * 8 + (lane & 7);
    int a_kb  = (lane >> 4) * 16;
    int b_n   = ((lane >> 4) & 1) * 8 + (lane & 7);
    int b_kb  = ((lane >> 3) & 1) * 16;

#define ISSUE1(ch) do {                                                       \
        int k0_ = (ch) << 6;                                                  \
        uint32_t stg_ = sbase + ((ch) % 3) * G1_STAGE;                        \
        _Pragma("unroll")                                                     \
        for (int u = 0; u < 4; u++) {                                         \
            int i_ = tid + u * 256;                                           \
            int row_ = i_ >> 3, seg_ = i_ & 7;                                \
            uint32_t so_ = SW128(row_ * 128 + seg_ * 16);                     \
            cp16(stg_ + so_, A + (size_t)(bm + row_) * K + k0_ + seg_ * 8);   \
            cp16(stg_ + G1_ABYTES + so_,                                      \
                 B + (size_t)(bn + row_) * K + k0_ + seg_ * 8);               \
        }                                                                     \
        asm volatile("cp.async.commit_group;" ::: "memory");                  \
    } while (0)

    ISSUE1(0);
    if (total > 1) ISSUE1(1);
    for (int ch = 0; ch < total; ch++) {
        if (ch + 2 < total) {
            ISSUE1(ch + 2);
            asm volatile("cp.async.wait_group 2;" ::: "memory");
        } else if (ch + 1 < total) {
            asm volatile("cp.async.wait_group 1;" ::: "memory");
        } else {
            asm volatile("cp.async.wait_group 0;" ::: "memory");
        }
        __syncthreads();

        uint32_t stg = sbase + (ch % 3) * G1_STAGE;
#pragma unroll
        for (int kk = 0; kk < 4; kk++) {
            uint32_t a[2][4];
#pragma unroll
            for (int mt = 0; mt < 2; mt++) {
                uint32_t byte = (uint32_t)(wr * 32 + mt * 16 + a_row) * 128 + kk * 32 + a_kb;
                ldm_x4(stg + SW128(byte), a[mt][0], a[mt][1], a[mt][2], a[mt][3]);
            }
            uint32_t b[4][4];
#pragma unroll
            for (int np = 0; np < 4; np++) {
                uint32_t byte = (uint32_t)(wc * 64 + np * 16 + b_n) * 128 + kk * 32 + b_kb;
                ldm_x4(stg + G1_ABYTES + SW128(byte), b[np][0], b[np][1], b[np][2], b[np][3]);
            }
#pragma unroll
            for (int mt = 0; mt < 2; mt++)
#pragma unroll
                for (int nt = 0; nt < 8; nt++)
                    mma16816h(acc[mt][nt], a[mt], b[nt >> 1][(nt & 1) * 2],
                              b[nt >> 1][(nt & 1) * 2 + 1]);
        }
        __syncthreads();
    }

    // ---------------- epilogue ----------------
    if (mode == 0) {
        float* Cm = (float*)outp;
#pragma unroll
        for (int mt = 0; mt < 2; mt++)
#pragma unroll
            for (int nt = 0; nt < 8; nt++) {
                int r0 = bm + wr * 32 + mt * 16 + (lane >> 2);
                int c  = bn + wc * 64 + nt * 8 + 2 * (lane & 3);
                size_t i0 = (size_t)r0 * N + c;
                size_t i1 = i0 + (size_t)8 * N;
                float2 v0 = make_float2(acc[mt][nt][0], acc[mt][nt][1]);
                float2 v1 = make_float2(acc[mt][nt][2], acc[mt][nt][3]);
                if (addsrc) {
                    float2 s0 = *(const float2*)&addsrc[i0];
                    float2 s1 = *(const float2*)&addsrc[i1];
                    v0.x += s0.x; v0.y += s0.y;
                    v1.x += s1.x; v1.y += s1.y;
                }
                *(float2*)&Cm[i0] = v0;
                *(float2*)&Cm[i1] = v1;
            }
    } else if (mode == 2) {
        __half* Cm = (__half*)outp;
#pragma unroll
        for (int mt = 0; mt < 2; mt++)
#pragma unroll
            for (int nt = 0; nt < 8; nt++) {
                int r0 = bm + wr * 32 + mt * 16 + (lane >> 2);
                int c  = bn + wc * 64 + nt * 8 + 2 * (lane & 3);
                float x0 = acc[mt][nt][0], y0 = acc[mt][nt][1];
                float x1 = acc[mt][nt][2], y1 = acc[mt][nt][3];
                if (c < 4096) {
                    int dp = (c & 127) >> 1;
                    int t0 = r0 & (T_ - 1), t1 = (r0 + 8) & (T_ - 1);
                    float c0 = fc[t0 * 64 + dp], s0 = fs[t0 * 64 + dp];
                    float c1 = fc[t1 * 64 + dp], s1 = fs[t1 * 64 + dp];
                    float nx0 = x0 * c0 - y0 * s0, ny0 = x0 * s0 + y0 * c0;
                    float nx1 = x1 * c1 - y1 * s1, ny1 = x1 * s1 + y1 * c1;
                    x0 = nx0; y0 = ny0; x1 = nx1; y1 = ny1;
                }
                *(__half2*)&Cm[(size_t)r0 * N + c] = __floats2half2_rn(x0, y0);
                *(__half2*)&Cm[(size_t)(r0 + 8) * N + c] = __floats2half2_rn(x1, y1);
            }
    } else {   // mode 3: silu(gate)*up, interleaved 16-col groups, out width N/2
        __half* Cm = (__half*)outp;
        int NO = N >> 1;
#pragma unroll
        for (int mt = 0; mt < 2; mt++)
#pragma unroll
            for (int ntp = 0; ntp < 4; ntp++) {
                int r0 = bm + wr * 32 + mt * 16 + (lane >> 2);
                int n0 = bn + wc * 64 + ntp * 16 + 2 * (lane & 3);
                int hid = ((n0 >> 4) << 3) + (n0 & 7);
                float* gv = acc[mt][2 * ntp];
                float* uv = acc[mt][2 * ntp + 1];
                float p0 = gv[0] / (1.f + __expf(-gv[0])) * uv[0];
                float p1 = gv[1] / (1.f + __expf(-gv[1])) * uv[1];
                float p2 = gv[2] / (1.f + __expf(-gv[2])) * uv[2];
                float p3 = gv[3] / (1.f + __expf(-gv[3])) * uv[3];
                *(__half2*)&Cm[(size_t)r0 * NO + hid] = __floats2half2_rn(p0, p1);
                *(__half2*)&Cm[(size_t)(r0 + 8) * NO + hid] = __floats2half2_rn(p2, p3);
            }
    }
}

// ---------------- HMMA flash attention ----------------
#define ATT_SMEM 98304     // Q 32K | 2 x (K 16K + V 16K)
__global__ __launch_bounds__(256, 1) void attn_k(
    const __half* __restrict__ qkv, __half* __restrict__ y)
{
    extern __shared__ __align__(1024) char smem[];
    uint32_t sQ = smem_u32(smem);
    int tid = threadIdx.x, wid = tid >> 5, lane = tid & 31;
    int bh = blockIdx.x, qt = blockIdx.y;
    int bb = bh >> 4, h = bh & 15;
    const float sc = 0.08838834764831845f;

    int a_row = ((lane >> 3) & 1) * 8 + (lane & 7);
    int a_kb  = (lane >> 4) * 16;
    int b_n   = ((lane >> 4) & 1) * 8 + (lane & 7);
    int b_kb  = ((lane >> 3) & 1) * 16;
    int v_key = ((lane >> 3) & 1) * 8 + (lane & 7);
    int v_col = ((lane >> 4) & 1) * 8;

    int qrow0 = bb * T_ + qt * 128;

#pragma unroll
    for (int u = 0; u < 8; u++) {
        int i = tid + u * 256;
        int row = i >> 4, seg = i & 15;
        cp16(sQ + SWK(row * 256 + seg * 16),
             qkv + (size_t)(qrow0 + row) * NQKV_ + h * HD_ + seg * 8);
    }
    asm volatile("cp.async.commit_group;" ::: "memory");

    int nkt = 2 * qt + 2;
#define ISSUE_KV(kt_) do {                                                    \
        uint32_t stg_ = sQ + 32768 + ((kt_) & 1) * 32768;                     \
        int kb_ = (kt_) * 64;                                                 \
        _Pragma("unroll")                                                     \
        for (int u = 0; u < 4; u++) {                                         \
            int i_ = tid + u * 256;                                           \
            int row_ = i_ >> 4, seg_ = i_ & 15;                               \
            size_t gr_ = (size_t)(bb * T_ + kb_ + row_) * NQKV_ + h * HD_ + seg_ * 8; \
            uint32_t so_ = SWK(row_ * 256 + seg_ * 16);                       \
            cp16(stg_ + so_, qkv + 2048 + gr_);                               \
            cp16(stg_ + 16384 + so_, qkv + 4096 + gr_);                       \
        }                                                                     \
        asm volatile("cp.async.commit_group;" ::: "memory");                  \
    } while (0)

    ISSUE_KV(0);
    asm volatile("cp.async.wait_group 1;" ::: "memory");
    __syncthreads();

    uint32_t qa[8][4];
#pragma unroll
    for (int kk = 0; kk < 8; kk++) {
        uint32_t byte = (uint32_t)(wid * 16 + a_row) * 256 + kk * 32 + a_kb;
        ldm_x4(sQ + SWK(byte), qa[kk][0], qa[kk][1], qa[kk][2], qa[kk][3]);
    }

    float o[16][4];
#pragma unroll
    for (int nt = 0; nt < 16; nt++)
#pragma unroll
        for (int e = 0; e < 4; e++) o[nt][e] = 0.f;
    float mrun0 = -INFINITY, mrun1 = -INFINITY, lrun0 = 0.f, lrun1 = 0.f;

    int rg0 = qt * 128 + wid * 16 + (lane >> 2);
    int rg1 = rg0 + 8;

    for (int kt = 0; kt < nkt; kt++) {
        if (kt + 1 < nkt) {
            ISSUE_KV(kt + 1);
            asm volatile("cp.async.wait_group 1;" ::: "memory");
        } else {
            asm volatile("cp.async.wait_group 0;" ::: "memory");
        }
        __syncthreads();
        uint32_t sK = sQ + 32768 + (kt & 1) * 32768;
        uint32_t sV = sK + 16384;

        float s[8][4];
#pragma unroll
        for (int nt = 0; nt < 8; nt++)
#pragma unroll
            for (int e = 0; e < 4; e++) s[nt][e] = 0.f;
#pragma unroll
        for (int kk = 0; kk < 8; kk++) {
            uint32_t bq[4][4];
#pragma unroll
            for (int np = 0; np < 4; np++) {
                uint32_t byte = (uint32_t)(np * 16 + b_n) * 256 + kk * 32 + b_kb;
                ldm_x4(sK + SWK(byte), bq[np][0], bq[np][1], bq[np][2], bq[np][3]);
            }
#pragma unroll
            for (int nt = 0; nt < 8; nt++)
                mma16816h(s[nt], qa[kk], bq[nt >> 1][(nt & 1) * 2],
                          bq[nt >> 1][(nt & 1) * 2 + 1]);
        }

        int kb0 = kt * 64;
        bool domask = (kt >= 2 * qt);
        float m0 = -INFINITY, m1 = -INFINITY;
#pragma unroll
        for (int nt = 0; nt < 8; nt++) {
            int k0 = kb0 + nt * 8 + 2 * (lane & 3);
#pragma unroll
            for (int e = 0; e < 4; e++) {
                float sv = s[nt][e] * sc;
                if (domask) {
                    int kc = k0 + (e & 1);
                    int rg = (e < 2) ? rg0 : rg1;
                    if (kc > rg) sv = -1e30f;
                }
                s[nt][e] = sv;
            }
            m0 = fmaxf(m0, fmaxf(s[nt][0], s[nt][1]));
            m1 = fmaxf(m1, fmaxf(s[nt][2], s[nt][3]));
        }
        m0 = fmaxf(m0, __shfl_xor_sync(0xffffffffu, m0, 1));
        m0 = fmaxf(m0, __shfl_xor_sync(0xffffffffu, m0, 2));
        m1 = fmaxf(m1, __shfl_xor_sync(0xffffffffu, m1, 1));
        m1 = fmaxf(m1, __shfl_xor_sync(0xffffffffu, m1, 2));
        float mn0 = fmaxf(mrun0, m0), mn1 = fmaxf(mrun1, m1);
        float al0 = __expf(mrun0 - mn0), al1 = __expf(mrun1 - mn1);
        mrun0 = mn0; mrun1 = mn1;
        float ls0 = 0.f, ls1 = 0.f;
#pragma unroll
        for (int nt = 0; nt < 8; nt++) {
            s[nt][0] = __expf(s[nt][0] - mn0);
            s[nt][1] = __expf(s[nt][1] - mn0);
            s[nt][2] = __expf(s[nt][2] - mn1);
            s[nt][3] = __expf(s[nt][3] - mn1);
            ls0 += s[nt][0] + s[nt][1];
            ls1 += s[nt][2] + s[nt][3];
        }
        ls0 += __shfl_xor_sync(0xffffffffu, ls0, 1);
        ls0 += __shfl_xor_sync(0xffffffffu, ls0, 2);
        ls1 += __shfl_xor_sync(0xffffffffu, ls1, 1);
        ls1 += __shfl_xor_sync(0xffffffffu, ls1, 2);
        lrun0 = lrun0 * al0 + ls0;
        lrun1 = lrun1 * al1 + ls1;
#pragma unroll
        for (int nt = 0; nt < 16; nt++) {
            o[nt][0] *= al0; o[nt][1] *= al0;
            o[nt][2] *= al1; o[nt][3] *= al1;
        }

#pragma unroll
        for (int ks = 0; ks < 4; ks++) {
            uint32_t pa[4];
            pa[0] = packh2(s[2*ks][0],   s[2*ks][1]);
            pa[1] = packh2(s[2*ks][2],   s[2*ks][3]);
            pa[2] = packh2(s[2*ks+1][0], s[2*ks+1][1]);
            pa[3] = packh2(s[2*ks+1][2], s[2*ks+1][3]);
#pragma unroll
            for (int nv = 0; nv < 8; nv++) {
                uint32_t r0, r1, r2, r3;
                uint32_t byte = (uint32_t)(ks * 16 + v_key) * 256 + (nv * 16 + v_col) * 2;
                ldm_x4t(sV + SWK(byte), r0, r1, r2, r3);
                mma16816h(o[2*nv],     pa, r0, r1);
                mma16816h(o[2*nv + 1], pa, r2, r3);
            }
        }
        __syncthreads();
    }

    float il0 = 1.f / lrun0, il1 = 1.f / lrun1;
    size_t row0 = (size_t)bb * T_ + rg0;
    size_t row1 = row0 + 8;
#pragma unroll
    for (int nt = 0; nt < 16; nt++) {
        int c = h * HD_ + nt * 8 + 2 * (lane & 3);
        *(__half2*)&y[row0 * C_ + c] = __floats2half2_rn(o[nt][0] * il0, o[nt][1] * il0);
        *(__half2*)&y[row1 * C_ + c] = __floats2half2_rn(o[nt][2] * il1, o[nt][3] * il1);
    }
}

// ---------------- launch ----------------
extern "C" void kernel_launch(void* const* d_in, const int* in_sizes, int n_in,
                              void* d_out, int out_size) {
    const float* x   = (const float*)d_in[0];
    const float* fc  = (const float*)d_in[1];
    const float* fs  = (const float*)d_in[2];
    const float* anw = (const float*)d_in[3];
    const float* fnw = (const float*)d_in[4];
    const float* wq  = (const float*)d_in[5];
    const float* wk  = (const float*)d_in[6];
    const float* wv  = (const float*)d_in[7];
    const float* wo  = (const float*)d_in[8];
    const float* wg  = (const float*)d_in[9];
    const float* wu  = (const float*)d_in[10];
    const float* wd  = (const float*)d_in[11];
    float* out = (float*)d_out;

    __half *Wqkv, *Wo, *Wgu, *Wd, *XN, *Y, *HN, *PR, *QKV;
    float *Hb;
    cudaGetSymbolAddress((void**)&Wqkv, g_Wqkv);
    cudaGetSymbolAddress((void**)&Wo,   g_Wo);
    cudaGetSymbolAddress((void**)&Wgu,  g_Wgu);
    cudaGetSymbolAddress((void**)&Wd,   g_Wd);
    cudaGetSymbolAddress((void**)&XN,   g_XN);
    cudaGetSymbolAddress((void**)&Y,    g_Y);
    cudaGetSymbolAddress((void**)&HN,   g_HN);
    cudaGetSymbolAddress((void**)&PR,   g_PR);
    cudaGetSymbolAddress((void**)&QKV,  g_QKV);
    cudaGetSymbolAddress((void**)&Hb,   g_Hb);

    cudaFuncSetAttribute(attn_k, cudaFuncAttributeMaxDynamicSharedMemorySize, ATT_SMEM);
    cudaFuncSetAttribute(gemm1_k, cudaFuncAttributeMaxDynamicSharedMemorySize, G1_SMEM);

    build_tables_k<<<1, 1>>>();

    ScaleSrc ss;
    ss.p[0] = wq; ss.p[1] = wk; ss.p[2] = wv; ss.p[3] = wo;
    ss.p[4] = wg; ss.p[5] = wu; ss.p[6] = wd;
    ss.op[0] = ss.op[1] = ss.op[2] = ss.op[3] = 65536;
    ss.op[4] = ss.op[5] = ss.op[6] = 683 * 256;
    scales_part_k<<<dim3(8, 8, 7), 256>>>(ss);
    scales_fin_k<<<1, 56>>>(ss);

    build_qkv_k<<<(NQKV_ * C_ / 4) / 256, 256>>>(wq, wk, wv, Wqkv);
    build_wo_k<<<(C_ * C_ / 4) / 256, 256>>>(wo, Wo);
    build_gu_k<<<(NGU_ * C_ / 4) / 256, 256>>>(wg, wu, Wgu);
    build_d_k<<<(C_ * HIDP_ / 2) / 256, 256>>>(wd, Wd);

    rmsnorm_k<<<BT_, 256>>>(x, anw, XN);

    gemm1_k<<<dim3(NQKV_ / 128, BT_ / 128), 256, G1_SMEM>>>(
        XN, Wqkv, nullptr, QKV, BT_, NQKV_, C_, 2, fc, fs);

    attn_k<<<dim3(64, 8), 256, ATT_SMEM>>>(QKV, Y);

    gemm1_k<<<dim3(C_ / 128, BT_ / 128), 256, G1_SMEM>>>(
        Y, Wo, x, Hb, BT_, C_, C_, 0, nullptr, nullptr);

    rmsnorm_k<<<BT_, 256>>>(Hb, fnw, HN);

    gemm1_k<<<dim3(NGU_ / 128, BT_ / 128), 256, G1_SMEM>>>(
        HN, Wgu, nullptr, PR, BT_, NGU_, C_, 3, nullptr, nullptr);

    gemm1_k<<<dim3(C_ / 128, BT_ / 128), 256, G1_SMEM>>>(
        PR, Wd, Hb, out, BT_, C_, HIDP_, 0, nullptr, nullptr);
}

// round 14
// speedup vs baseline: 1.1445x; 1.0126x over previous
#include <cuda_runtime.h>
#include <cuda_bf16.h>
#include <cuda_fp16.h>
#include <math.h>
#include <stdint.h>

// ---------------- problem constants ----------------
#define BT_    4096          // B*T
#define C_     2048
#define T_     1024
#define H_     16
#define HD_    128
#define HID_   5464
#define HBLK_  688           // padded hidden block
#define HIDP_  5504          // 8*688
#define NQKV_  6144
#define NGU_   11008         // interleaved gate/up

// ---------------- helpers ----------------
__device__ __forceinline__ uint32_t smem_u32(const void* p) {
    uint32_t a;
    asm("{ .reg .u64 t; cvta.to.shared.u64 t, %1; cvt.u32.u64 %0, t; }" : "=r"(a) : "l"(p));
    return a;
}
#define SW128(o) ((o) ^ (((o) >> 3) & 0x70))          // 128B-row swizzle
#define SWK(o)   ((o) ^ ((((o) >> 8) & 7) << 4))      // 256B-row swizzle

__device__ __forceinline__ void cp16(uint32_t s, const void* g) {
    asm volatile("cp.async.cg.shared.global [%0], [%1], 16;"
                 :: "r"(s), "l"(__cvta_generic_to_global(g)));
}
__device__ __forceinline__ void ldm_x4(uint32_t addr, uint32_t& r0, uint32_t& r1,
                                       uint32_t& r2, uint32_t& r3) {
    asm volatile("ldmatrix.sync.aligned.m8n8.x4.shared.b16 {%0,%1,%2,%3}, [%4];"
                 : "=r"(r0), "=r"(r1), "=r"(r2), "=r"(r3) : "r"(addr));
}
__device__ __forceinline__ void ldm_x4t(uint32_t addr, uint32_t& r0, uint32_t& r1,
                                        uint32_t& r2, uint32_t& r3) {
    asm volatile("ldmatrix.sync.aligned.m8n8.x4.trans.shared.b16 {%0,%1,%2,%3}, [%4];"
                 : "=r"(r0), "=r"(r1), "=r"(r2), "=r"(r3) : "r"(addr));
}
__device__ __forceinline__ void mma16816h(float* c, const uint32_t* a, uint32_t b0, uint32_t b1) {
    asm volatile(
        "mma.sync.aligned.m16n8k16.row.col.f32.f16.f16.f32 "
        "{%0,%1,%2,%3}, {%4,%5,%6,%7}, {%8,%9}, {%0,%1,%2,%3};"
        : "+f"(c[0]), "+f"(c[1]), "+f"(c[2]), "+f"(c[3])
        : "r"(a[0]), "r"(a[1]), "r"(a[2]), "r"(a[3]), "r"(b0), "r"(b1));
}
__device__ __forceinline__ uint32_t packh2(float x, float y) {
    __half2 h = __floats2half2_rn(x, y);
    return *(uint32_t*)&h;
}

// ---------------- scratch (device globals, no allocs) ----------------
__device__ __half g_Wqkv[(size_t)NQKV_*C_];
__device__ __half g_Wo  [(size_t)C_*C_];
__device__ __half g_Wgu [(size_t)NGU_*C_];   // interleaved: 16-col groups (8 gate + 8 up)
__device__ __half g_Wd  [(size_t)C_*HIDP_];
__device__ __half g_XN  [(size_t)BT_*C_];
__device__ __half g_Y   [(size_t)BT_*C_];
__device__ __half g_HN  [(size_t)BT_*C_];
__device__ __half g_PR  [(size_t)BT_*HIDP_];
__device__ __half g_QKV [(size_t)BT_*NQKV_];
__device__ float  g_Hb  [(size_t)BT_*C_];
__device__ int    g_Ji[64];
__device__ float  g_Sg[64];
__device__ float  g_scale[112];   // [0:56) scale, [56:112) 1/(scale+1e-8)
__device__ double g_part[7*8*8];

struct ScaleSrc { const float* p[7]; int op[7]; };

// ---------------- octonion table ----------------
__global__ void build_tables_k() {
    int idx[8][8]; float sg[8][8];
    for (int j = 0; j < 8; j++) { idx[0][j] = j; sg[0][j] = 1.f; }
    for (int i = 1; i < 8; i++) {
        idx[i][0] = i; sg[i][0] = 1.f;
        idx[i][i] = 0; sg[i][i] = -1.f;
    }
    const int tr[7][3] = {{1,2,3},{1,4,5},{1,7,6},{2,4,6},{2,5,7},{3,4,7},{3,6,5}};
    for (int t = 0; t < 7; t++) {
        int a = tr[t][0], b = tr[t][1], c = tr[t][2];
        int per[3][3] = {{a,b,c},{b,c,a},{c,a,b}};
        for (int u = 0; u < 3; u++) {
            int p = per[u][0], q = per[u][1], r = per[u][2];
            idx[p][q] = r; sg[p][q] = 1.f;
            idx[q][p] = r; sg[q][p] = -1.f;
        }
    }
    for (int i = 0; i < 8; i++)
        for (int j = 0; j < 8; j++) {
            int k = idx[i][j];
            g_Ji[k*8 + j] = i;
            g_Sg[k*8 + j] = sg[i][j];
        }
}

// ---------------- scales ----------------
__global__ void scales_part_k(ScaleSrc ss) {
    int t = blockIdx.z, i = blockIdx.x, sl = blockIdx.y;
    int OP = ss.op[t];
    const float* Wi = ss.p[t] + (size_t)i * OP;
    int per = (OP + 7) / 8;
    int st = sl * per, en = min(OP, st + per);
    double s = 0.0;
    for (int u = st + threadIdx.x; u < en; u += 256) s += (double)fabsf(Wi[u]);
    __shared__ double red[256];
    red[threadIdx.x] = s; __syncthreads();
    for (int stp = 128; stp > 0; stp >>= 1) {
        if (threadIdx.x < stp) red[threadIdx.x] += red[threadIdx.x + stp];
        __syncthreads();
    }
    if (threadIdx.x == 0) g_part[(t*8 + i)*8 + sl] = red[0];
}
__global__ void scales_fin_k(ScaleSrc ss) {
    int id = threadIdx.x;       // 56
    int t = id >> 3, i = id & 7;
    double s = 0.0;
    for (int j = 0; j < 8; j++) s += g_part[(t*8 + i)*8 + j];
    float sc = (float)(s / (double)ss.op[t]);
    g_scale[id] = sc;
    g_scale[56 + id] = 1.0f / (sc + 1e-8f);
}

__device__ __forceinline__ float tsign_r(float w, float inv) {
    float q = rintf(w * inv);
    return fmaxf(-1.f, fminf(1.f, q));
}

// ---------------- weight builds (float4 -> 4 elems/thread, reciprocal) ----------------
__global__ void build_qkv_k(const float* __restrict__ wq, const float* __restrict__ wk,
                            const float* __restrict__ wv, __half* __restrict__ F) {
    int id = blockIdx.x * 256 + threadIdx.x;        // NQKV_*C_/4
    int r = id >> 9, c = (id & 511) << 2;
    int t = r >> 11, rr = r & 2047;
    int kb = rr >> 8, o = rr & 255, jb = c >> 8, p = c & 255;
    int i = g_Ji[kb*8 + jb];
    const float* src = (t == 0) ? wq : ((t == 1) ? wk : wv);
    float inv = g_scale[56 + t*8 + i];
    float ss = g_Sg[kb*8 + jb] * g_scale[t*8 + i];
    float4 w = *(const float4*)&src[((size_t)i << 16) + (o << 8) + p];
    size_t ob = (size_t)r * C_ + c;
    *(__half2*)&F[ob]     = __floats2half2_rn(ss * tsign_r(w.x, inv), ss * tsign_r(w.y, inv));
    *(__half2*)&F[ob + 2] = __floats2half2_rn(ss * tsign_r(w.z, inv), ss * tsign_r(w.w, inv));
}
__global__ void build_wo_k(const float* __restrict__ wo, __half* __restrict__ F) {
    int id = blockIdx.x * 256 + threadIdx.x;        // C_*C_/4
    int r = id >> 9, c = (id & 511) << 2;
    int kb = r >> 8, o = r & 255, jb = c >> 8, p = c & 255;
    int i = g_Ji[kb*8 + jb];
    float inv = g_scale[56 + 24 + i];
    float ss = g_Sg[kb*8 + jb] * g_scale[24 + i];
    float4 w = *(const float4*)&wo[((size_t)i << 16) + (o << 8) + p];
    size_t ob = (size_t)r * C_ + c;
    *(__half2*)&F[ob]     = __floats2half2_rn(ss * tsign_r(w.x, inv), ss * tsign_r(w.y, inv));
    *(__half2*)&F[ob + 2] = __floats2half2_rn(ss * tsign_r(w.z, inv), ss * tsign_r(w.w, inv));
}
// interleaved GU: row n (0..11007): hid = (n>>4)*8 + (n&7), type = (n>>3)&1
__global__ void build_gu_k(const float* __restrict__ wg, const float* __restrict__ wu,
                           __half* __restrict__ F) {
    int id = blockIdx.x * 256 + threadIdx.x;        // NGU_*C_/4
    int r = id >> 9, c = (id & 511) << 2;
    int type = (r >> 3) & 1;
    int hid = ((r >> 4) << 3) + (r & 7);
    int kb = hid / HBLK_, o = hid - kb * HBLK_;
    size_t ob = (size_t)r * C_ + c;
    if (o >= 683) {
        *(__half2*)&F[ob] = __floats2half2_rn(0.f, 0.f);
        *(__half2*)&F[ob + 2] = __floats2half2_rn(0.f, 0.f);
        return;
    }
    int jb = c >> 8, p = c & 255;
    int i = g_Ji[kb*8 + jb];
    const float* src = type ? wu : wg;
    float inv = g_scale[56 + 32 + type*8 + i];
    float ss = g_Sg[kb*8 + jb] * g_scale[32 + type*8 + i];
    float4 w = *(const float4*)&src[((size_t)i * 683 + o) * 256 + p];
    *(__half2*)&F[ob]     = __floats2half2_rn(ss * tsign_r(w.x, inv), ss * tsign_r(w.y, inv));
    *(__half2*)&F[ob + 2] = __floats2half2_rn(ss * tsign_r(w.z, inv), ss * tsign_r(w.w, inv));
}
__global__ void build_d_k(const float* __restrict__ wd, __half* __restrict__ F) {
    int id = blockIdx.x * 256 + threadIdx.x;        // C_*HIDP_/2
    int r = id / (HIDP_/2), c = (id - r * (HIDP_/2)) * 2;
    int jb = c / HBLK_, p = c - jb * HBLK_;
    int kb = r >> 8, o = r & 255;
    int i = g_Ji[kb*8 + jb];
    float inv = g_scale[56 + 48 + i];
    float ss = g_Sg[kb*8 + jb] * g_scale[48 + i];
    float v0 = 0.f, v1 = 0.f;
    if (p < 683) {
        const float* base = &wd[((size_t)i * 256 + o) * 683 + p];
        v0 = ss * tsign_r(base[0], inv);
        if (p + 1 < 683) v1 = ss * tsign_r(base[1], inv);
    }
    *(__half2*)&F[(size_t)r * HIDP_ + c] = __floats2half2_rn(v0, v1);
}

// ---------------- rmsnorm -> fp16 (float4) ----------------
__global__ void rmsnorm_k(const float* __restrict__ x, const float* __restrict__ w,
                          __half* __restrict__ oh) {
    int row = blockIdx.x;
    const float4* xr = (const float4*)(x + (size_t)row * C_);
    const float4* wr = (const float4*)w;
    float4 v0 = xr[threadIdx.x];
    float4 v1 = xr[threadIdx.x + 256];
    float s = v0.x*v0.x + v0.y*v0.y + v0.z*v0.z + v0.w*v0.w
            + v1.x*v1.x + v1.y*v1.y + v1.z*v1.z + v1.w*v1.w;
    __shared__ float red[256];
    red[threadIdx.x] = s; __syncthreads();
    for (int st = 128; st > 0; st >>= 1) {
        if (threadIdx.x < st) red[threadIdx.x] += red[threadIdx.x + st];
        __syncthreads();
    }
    float inv = 1.0f / sqrtf(red[0] / (float)C_ + 1e-6f);
    float4 w0 = wr[threadIdx.x];
    float4 w1 = wr[threadIdx.x + 256];
    size_t base = (size_t)row * C_;
    int c0 = threadIdx.x * 4;
    *(__half2*)&oh[base + c0]     = __floats2half2_rn(v0.x*inv*w0.x, v0.y*inv*w0.y);
    *(__half2*)&oh[base + c0 + 2] = __floats2half2_rn(v0.z*inv*w0.z, v0.w*inv*w0.w);
    int c1 = c0 + 1024;
    *(__half2*)&oh[base + c1]     = __floats2half2_rn(v1.x*inv*w1.x, v1.y*inv*w1.y);
    *(__half2*)&oh[base + c1 + 2] = __floats2half2_rn(v1.z*inv*w1.z, v1.w*inv*w1.w);
}

// ---------------- 128x128x64 fp16 GEMM, 256 threads, 2 CTAs/SM, 1 sync/chunk ----------------
// mode 0: float out (+addsrc)
// mode 2: half out with fused RoPE (cols < 4096 get rotated)
// mode 3: interleaved silu(gate)*up -> half out [M, N/2]
#define G1_ABYTES 16384
#define G1_STAGE  32768    // A 16KB | B 16KB
#define G1_SMEM   (3 * G1_STAGE)

__global__ __launch_bounds__(256, 2) void gemm1_k(
    const __half* __restrict__ A, const __half* __restrict__ B,
    const float* __restrict__ addsrc, void* __restrict__ outp,
    int M, int N, int K, int mode,
    const float* __restrict__ fc, const float* __restrict__ fs)
{
    extern __shared__ __align__(1024) char smem[];
    int tid = threadIdx.x, wid = tid >> 5, lane = tid & 31;
    int wr = wid >> 1, wc = wid & 1;
    int bm = blockIdx.y * 128, bn = blockIdx.x * 128;
    uint32_t sbase = smem_u32(smem);
    int total = K >> 6;

    float acc[2][8][4];
#pragma unroll
    for (int mt = 0; mt < 2; mt++)
#pragma unroll
        for (int nt = 0; nt < 8; nt++)
#pragma unroll
            for (int e = 0; e < 4; e++) acc[mt][nt][e] = 0.f;

    int a_row = ((lane >> 3) & 1) * 8 + (lane & 7);
    int a_kb  = (lane >> 4) * 16;
    int b_n   = ((lane >> 4) & 1) * 8 + (lane & 7);
    int b_kb  = ((lane >> 3) & 1) * 16;

#define ISSUE1(ch) do {                                                       \
        int k0_ = (ch) << 6;                                                  \
        uint32_t stg_ = sbase + ((ch) % 3) * G1_STAGE;                        \
        _Pragma("unroll")                                                     \
        for (int u = 0; u < 4; u++) {                                         \
            int i_ = tid + u * 256;                                           \
            int row_ = i_ >> 3, seg_ = i_ & 7;                                \
            uint32_t so_ = SW128(row_ * 128 + seg_ * 16);                     \
            cp16(stg_ + so_, A + (size_t)(bm + row_) * K + k0_ + seg_ * 8);   \
            cp16(stg_ + G1_ABYTES + so_,                                      \
                 B + (size_t)(bn + row_) * K + k0_ + seg_ * 8);               \
        }                                                                     \
        asm volatile("cp.async.commit_group;" ::: "memory");                  \
    } while (0)

    ISSUE1(0);
    if (total > 1) ISSUE1(1);
    for (int ch = 0; ch < total; ch++) {
        if (ch + 1 < total) {
            asm volatile("cp.async.wait_group 1;" ::: "memory");
        } else {
            asm volatile("cp.async.wait_group 0;" ::: "memory");
        }
        __syncthreads();
        if (ch + 2 < total) ISSUE1(ch + 2);   // writes stage consumed at ch-1; safe after sync

        uint32_t stg = sbase + (ch % 3) * G1_STAGE;
#pragma unroll
        for (int kk = 0; kk < 4; kk++) {
            uint32_t a[2][4];
#pragma unroll
            for (int mt = 0; mt < 2; mt++) {
                uint32_t byte = (uint32_t)(wr * 32 + mt * 16 + a_row) * 128 + kk * 32 + a_kb;
                ldm_x4(stg + SW128(byte), a[mt][0], a[mt][1], a[mt][2], a[mt][3]);
            }
            uint32_t b[4][4];
#pragma unroll
            for (int np = 0; np < 4; np++) {
                uint32_t byte = (uint32_t)(wc * 64 + np * 16 + b_n) * 128 + kk * 32 + b_kb;
                ldm_x4(stg + G1_ABYTES + SW128(byte), b[np][0], b[np][1], b[np][2], b[np][3]);
            }
#pragma unroll
            for (int mt = 0; mt < 2; mt++)
#pragma unroll
                for (int nt = 0; nt < 8; nt++)
                    mma16816h(acc[mt][nt], a[mt], b[nt >> 1][(nt & 1) * 2],
                              b[nt >> 1][(nt & 1) * 2 + 1]);
        }
    }

    // ---------------- epilogue ----------------
    if (mode == 0) {
        float* Cm = (float*)outp;
#pragma unroll
        for (int mt = 0; mt < 2; mt++)
#pragma unroll
            for (int nt = 0; nt < 8; nt++) {
                int r0 = bm + wr * 32 + mt * 16 + (lane >> 2);
                int c  = bn + wc * 64 + nt * 8 + 2 * (lane & 3);
                size_t i0 = (size_t)r0 * N + c;
                size_t i1 = i0 + (size_t)8 * N;
                float2 v0 = make_float2(acc[mt][nt][0], acc[mt][nt][1]);
                float2 v1 = make_float2(acc[mt][nt][2], acc[mt][nt][3]);
                if (addsrc) {
                    float2 s0 = *(const float2*)&addsrc[i0];
                    float2 s1 = *(const float2*)&addsrc[i1];
                    v0.x += s0.x; v0.y += s0.y;
                    v1.x += s1.x; v1.y += s1.y;
                }
                *(float2*)&Cm[i0] = v0;
                *(float2*)&Cm[i1] = v1;
            }
    } else if (mode == 2) {
        __half* Cm = (__half*)outp;
#pragma unroll
        for (int mt = 0; mt < 2; mt++)
#pragma unroll
            for (int nt = 0; nt < 8; nt++) {
                int r0 = bm + wr * 32 + mt * 16 + (lane >> 2);
                int c  = bn + wc * 64 + nt * 8 + 2 * (lane & 3);
                float x0 = acc[mt][nt][0], y0 = acc[mt][nt][1];
                float x1 = acc[mt][nt][2], y1 = acc[mt][nt][3];
                if (c < 4096) {
                    int dp = (c & 127) >> 1;
                    int t0 = r0 & (T_ - 1), t1 = (r0 + 8) & (T_ - 1);
                    float c0 = fc[t0 * 64 + dp], s0 = fs[t0 * 64 + dp];
                    float c1 = fc[t1 * 64 + dp], s1 = fs[t1 * 64 + dp];
                    float nx0 = x0 * c0 - y0 * s0, ny0 = x0 * s0 + y0 * c0;
                    float nx1 = x1 * c1 - y1 * s1, ny1 = x1 * s1 + y1 * c1;
                    x0 = nx0; y0 = ny0; x1 = nx1; y1 = ny1;
                }
                *(__half2*)&Cm[(size_t)r0 * N + c] = __floats2half2_rn(x0, y0);
                *(__half2*)&Cm[(size_t)(r0 + 8) * N + c] = __floats2half2_rn(x1, y1);
            }
    } else {   // mode 3: silu(gate)*up, interleaved 16-col groups, out width N/2
        __half* Cm = (__half*)outp;
        int NO = N >> 1;
#pragma unroll
        for (int mt = 0; mt < 2; mt++)
#pragma unroll
            for (int ntp = 0; ntp < 4; ntp++) {
                int r0 = bm + wr * 32 + mt * 16 + (lane >> 2);
                int n0 = bn + wc * 64 + ntp * 16 + 2 * (lane & 3);
                int hid = ((n0 >> 4) << 3) + (n0 & 7);
                float* gv = acc[mt][2 * ntp];
                float* uv = acc[mt][2 * ntp + 1];
                float p0 = gv[0] / (1.f + __expf(-gv[0])) * uv[0];
                float p1 = gv[1] / (1.f + __expf(-gv[1])) * uv[1];
                float p2 = gv[2] / (1.f + __expf(-gv[2])) * uv[2];
                float p3 = gv[3] / (1.f + __expf(-gv[3])) * uv[3];
                *(__half2*)&Cm[(size_t)r0 * NO + hid] = __floats2half2_rn(p0, p1);
                *(__half2*)&Cm[(size_t)(r0 + 8) * NO + hid] = __floats2half2_rn(p2, p3);
            }
    }
}

// ---------------- HMMA flash attention (1 sync/tile, heavy tiles first) ----------------
#define ATT_SMEM 98304     // Q 32K | 2 x (K 16K + V 16K)
__global__ __launch_bounds__(256, 1) void attn_k(
    const __half* __restrict__ qkv, __half* __restrict__ y)
{
    extern __shared__ __align__(1024) char smem[];
    uint32_t sQ = smem_u32(smem);
    int tid = threadIdx.x, wid = tid >> 5, lane = tid & 31;
    int bh = blockIdx.x;
    int qt = (int)(gridDim.y - 1 - blockIdx.y);   // heavy (large-qt) CTAs launch first
    int bb = bh >> 4, h = bh & 15;
    const float sc = 0.08838834764831845f;

    int a_row = ((lane >> 3) & 1) * 8 + (lane & 7);
    int a_kb  = (lane >> 4) * 16;
    int b_n   = ((lane >> 4) & 1) * 8 + (lane & 7);
    int b_kb  = ((lane >> 3) & 1) * 16;
    int v_key = ((lane >> 3) & 1) * 8 + (lane & 7);
    int v_col = ((lane >> 4) & 1) * 8;

    int qrow0 = bb * T_ + qt * 128;

#pragma unroll
    for (int u = 0; u < 8; u++) {
        int i = tid + u * 256;
        int row = i >> 4, seg = i & 15;
        cp16(sQ + SWK(row * 256 + seg * 16),
             qkv + (size_t)(qrow0 + row) * NQKV_ + h * HD_ + seg * 8);
    }
    asm volatile("cp.async.commit_group;" ::: "memory");

    int nkt = 2 * qt + 2;
#define ISSUE_KV(kt_) do {                                                    \
        uint32_t stg_ = sQ + 32768 + ((kt_) & 1) * 32768;                     \
        int kb_ = (kt_) * 64;                                                 \
        _Pragma("unroll")                                                     \
        for (int u = 0; u < 4; u++) {                                         \
            int i_ = tid + u * 256;                                           \
            int row_ = i_ >> 4, seg_ = i_ & 15;                               \
            size_t gr_ = (size_t)(bb * T_ + kb_ + row_) * NQKV_ + h * HD_ + seg_ * 8; \
            uint32_t so_ = SWK(row_ * 256 + seg_ * 16);                       \
            cp16(stg_ + so_, qkv + 2048 + gr_);                               \
            cp16(stg_ + 16384 + so_, qkv + 4096 + gr_);                       \
        }                                                                     \
        asm volatile("cp.async.commit_group;" ::: "memory");                  \
    } while (0)

    ISSUE_KV(0);
    asm volatile("cp.async.wait_group 1;" ::: "memory");   // Q ready
    __syncthreads();

    uint32_t qa[8][4];
#pragma unroll
    for (int kk = 0; kk < 8; kk++) {
        uint32_t byte = (uint32_t)(wid * 16 + a_row) * 256 + kk * 32 + a_kb;
        ldm_x4(sQ + SWK(byte), qa[kk][0], qa[kk][1], qa[kk][2], qa[kk][3]);
    }

    float o[16][4];
#pragma unroll
    for (int nt = 0; nt < 16; nt++)
#pragma unroll
        for (int e = 0; e < 4; e++) o[nt][e] = 0.f;
    float mrun0 = -INFINITY, mrun1 = -INFINITY, lrun0 = 0.f, lrun1 = 0.f;

    int rg0 = qt * 128 + wid * 16 + (lane >> 2);
    int rg1 = rg0 + 8;

    for (int kt = 0; kt < nkt; kt++) {
        asm volatile("cp.async.wait_group 0;" ::: "memory");
        __syncthreads();
        if (kt + 1 < nkt) ISSUE_KV(kt + 1);   // safe after sync; overlaps compute below
        uint32_t sK = sQ + 32768 + (kt & 1) * 32768;
        uint32_t sV = sK + 16384;

        float s[8][4];
#pragma unroll
        for (int nt = 0; nt < 8; nt++)
#pragma unroll
            for (int e = 0; e < 4; e++) s[nt][e] = 0.f;
#pragma unroll
        for (int kk = 0; kk < 8; kk++) {
            uint32_t bq[4][4];
#pragma unroll
            for (int np = 0; np < 4; np++) {
                uint32_t byte = (uint32_t)(np * 16 + b_n) * 256 + kk * 32 + b_kb;
                ldm_x4(sK + SWK(byte), bq[np][0], bq[np][1], bq[np][2], bq[np][3]);
            }
#pragma unroll
            for (int nt = 0; nt < 8; nt++)
                mma16816h(s[nt], qa[kk], bq[nt >> 1][(nt & 1) * 2],
                          bq[nt >> 1][(nt & 1) * 2 + 1]);
        }

        int kb0 = kt * 64;
        bool domask = (kt >= 2 * qt);
        float m0 = -INFINITY, m1 = -INFINITY;
#pragma unroll
        for (int nt = 0; nt < 8; nt++) {
            int k0 = kb0 + nt * 8 + 2 * (lane & 3);
#pragma unroll
            for (int e = 0; e < 4; e++) {
                float sv = s[nt][e] * sc;
                if (domask) {
                    int kc = k0 + (e & 1);
                    int rg = (e < 2) ? rg0 : rg1;
                    if (kc > rg) sv = -1e30f;
                }
                s[nt][e] = sv;
            }
            m0 = fmaxf(m0, fmaxf(s[nt][0], s[nt][1]));
            m1 = fmaxf(m1, fmaxf(s[nt][2], s[nt][3]));
        }
        m0 = fmaxf(m0, __shfl_xor_sync(0xffffffffu, m0, 1));
        m0 = fmaxf(m0, __shfl_xor_sync(0xffffffffu, m0, 2));
        m1 = fmaxf(m1, __shfl_xor_sync(0xffffffffu, m1, 1));
        m1 = fmaxf(m1, __shfl_xor_sync(0xffffffffu, m1, 2));
        float mn0 = fmaxf(mrun0, m0), mn1 = fmaxf(mrun1, m1);
        float al0 = __expf(mrun0 - mn0), al1 = __expf(mrun1 - mn1);
        mrun0 = mn0; mrun1 = mn1;
        float ls0 = 0.f, ls1 = 0.f;
#pragma unroll
        for (int nt = 0; nt < 8; nt++) {
            s[nt][0] = __expf(s[nt][0] - mn0);
            s[nt][1] = __expf(s[nt][1] - mn0);
            s[nt][2] = __expf(s[nt][2] - mn1);
            s[nt][3] = __expf(s[nt][3] - mn1);
            ls0 += s[nt][0] + s[nt][1];
            ls1 += s[nt][2] + s[nt][3];
        }
        ls0 += __shfl_xor_sync(0xffffffffu, ls0, 1);
        ls0 += __shfl_xor_sync(0xffffffffu, ls0, 2);
        ls1 += __shfl_xor_sync(0xffffffffu, ls1, 1);
        ls1 += __shfl_xor_sync(0xffffffffu, ls1, 2);
        lrun0 = lrun0 * al0 + ls0;
        lrun1 = lrun1 * al1 + ls1;
#pragma unroll
        for (int nt = 0; nt < 16; nt++) {
            o[nt][0] *= al0; o[nt][1] *= al0;
            o[nt][2] *= al1; o[nt][3] *= al1;
        }

#pragma unroll
        for (int ks = 0; ks < 4; ks++) {
            uint32_t pa[4];
            pa[0] = packh2(s[2*ks][0],   s[2*ks][1]);
            pa[1] = packh2(s[2*ks][2],   s[2*ks][3]);
            pa[2] = packh2(s[2*ks+1][0], s[2*ks+1][1]);
            pa[3] = packh2(s[2*ks+1][2], s[2*ks+1][3]);
#pragma unroll
            for (int nv = 0; nv < 8; nv++) {
                uint32_t r0, r1, r2, r3;
                uint32_t byte = (uint32_t)(ks * 16 + v_key) * 256 + (nv * 16 + v_col) * 2;
                ldm_x4t(sV + SWK(byte), r0, r1, r2, r3);
                mma16816h(o[2*nv],     pa, r0, r1);
                mma16816h(o[2*nv + 1], pa, r2, r3);
            }
        }
    }

    float il0 = 1.f / lrun0, il1 = 1.f / lrun1;
    size_t row0 = (size_t)bb * T_ + rg0;
    size_t row1 = row0 + 8;
#pragma unroll
    for (int nt = 0; nt < 16; nt++) {
        int c = h * HD_ + nt * 8 + 2 * (lane & 3);
        *(__half2*)&y[row0 * C_ + c] = __floats2half2_rn(o[nt][0] * il0, o[nt][1] * il0);
        *(__half2*)&y[row1 * C_ + c] = __floats2half2_rn(o[nt][2] * il1, o[nt][3] * il1);
    }
}

// ---------------- launch ----------------
extern "C" void kernel_launch(void* const* d_in, const int* in_sizes, int n_in,
                              void* d_out, int out_size) {
    const float* x   = (const float*)d_in[0];
    const float* fc  = (const float*)d_in[1];
    const float* fs  = (const float*)d_in[2];
    const float* anw = (const float*)d_in[3];
    const float* fnw = (const float*)d_in[4];
    const float* wq  = (const float*)d_in[5];
    const float* wk  = (const float*)d_in[6];
    const float* wv  = (const float*)d_in[7];
    const float* wo  = (const float*)d_in[8];
    const float* wg  = (const float*)d_in[9];
    const float* wu  = (const float*)d_in[10];
    const float* wd  = (const float*)d_in[11];
    float* out = (float*)d_out;

    __half *Wqkv, *Wo, *Wgu, *Wd, *XN, *Y, *HN, *PR, *QKV;
    float *Hb;
    cudaGetSymbolAddress((void**)&Wqkv, g_Wqkv);
    cudaGetSymbolAddress((void**)&Wo,   g_Wo);
    cudaGetSymbolAddress((void**)&Wgu,  g_Wgu);
    cudaGetSymbolAddress((void**)&Wd,   g_Wd);
    cudaGetSymbolAddress((void**)&XN,   g_XN);
    cudaGetSymbolAddress((void**)&Y,    g_Y);
    cudaGetSymbolAddress((void**)&HN,   g_HN);
    cudaGetSymbolAddress((void**)&PR,   g_PR);
    cudaGetSymbolAddress((void**)&QKV,  g_QKV);
    cudaGetSymbolAddress((void**)&Hb,   g_Hb);

    cudaFuncSetAttribute(attn_k, cudaFuncAttributeMaxDynamicSharedMemorySize, ATT_SMEM);
    cudaFuncSetAttribute(gemm1_k, cudaFuncAttributeMaxDynamicSharedMemorySize, G1_SMEM);

    build_tables_k<<<1, 1>>>();

    ScaleSrc ss;
    ss.p[0] = wq; ss.p[1] = wk; ss.p[2] = wv; ss.p[3] = wo;
    ss.p[4] = wg; ss.p[5] = wu; ss.p[6] = wd;
    ss.op[0] = ss.op[1] = ss.op[2] = ss.op[3] = 65536;
    ss.op[4] = ss.op[5] = ss.op[6] = 683 * 256;
    scales_part_k<<<dim3(8, 8, 7), 256>>>(ss);
    scales_fin_k<<<1, 56>>>(ss);

    build_qkv_k<<<(NQKV_ * C_ / 4) / 256, 256>>>(wq, wk, wv, Wqkv);
    build_wo_k<<<(C_ * C_ / 4) / 256, 256>>>(wo, Wo);
    build_gu_k<<<(NGU_ * C_ / 4) / 256, 256>>>(wg, wu, Wgu);
    build_d_k<<<(C_ * HIDP_ / 2) / 256, 256>>>(wd, Wd);

    rmsnorm_k<<<BT_, 256>>>(x, anw, XN);

    gemm1_k<<<dim3(NQKV_ / 128, BT_ / 128), 256, G1_SMEM>>>(
        XN, Wqkv, nullptr, QKV, BT_, NQKV_, C_, 2, fc, fs);

    attn_k<<<dim3(64, 8), 256, ATT_SMEM>>>(QKV, Y);

    gemm1_k<<<dim3(C_ / 128, BT_ / 128), 256, G1_SMEM>>>(
        Y, Wo, x, Hb, BT_, C_, C_, 0, nullptr, nullptr);

    rmsnorm_k<<<BT_, 256>>>(Hb, fnw, HN);

    gemm1_k<<<dim3(NGU_ / 128, BT_ / 128), 256, G1_SMEM>>>(
        HN, Wgu, nullptr, PR, BT_, NGU_, C_, 3, nullptr, nullptr);

    gemm1_k<<<dim3(C_ / 128, BT_ / 128), 256, G1_SMEM>>>(
        PR, Wd, Hb, out, BT_, C_, HIDP_, 0, nullptr, nullptr);
}

// round 15
// speedup vs baseline: 1.1505x; 1.0053x over previous
#include <cuda_runtime.h>
#include <cuda_bf16.h>
#include <cuda_fp16.h>
#include <math.h>
#include <stdint.h>

// ---------------- problem constants ----------------
#define BT_    4096          // B*T
#define C_     2048
#define T_     1024
#define H_     16
#define HD_    128
#define HID_   5464
#define HBLK_  688           // padded hidden block
#define HIDP_  5504          // 8*688
#define NQKV_  6144
#define NGU_   11008         // interleaved gate/up

// ---------------- helpers ----------------
__device__ __forceinline__ uint32_t smem_u32(const void* p) {
    uint32_t a;
    asm("{ .reg .u64 t; cvta.to.shared.u64 t, %1; cvt.u32.u64 %0, t; }" : "=r"(a) : "l"(p));
    return a;
}
#define SW128(o) ((o) ^ (((o) >> 3) & 0x70))          // 128B-row swizzle
#define SWK(o)   ((o) ^ ((((o) >> 8) & 7) << 4))      // 256B-row swizzle

__device__ __forceinline__ void cp16(uint32_t s, const void* g) {
    asm volatile("cp.async.cg.shared.global [%0], [%1], 16;"
                 :: "r"(s), "l"(__cvta_generic_to_global(g)));
}
__device__ __forceinline__ void ldm_x4(uint32_t addr, uint32_t& r0, uint32_t& r1,
                                       uint32_t& r2, uint32_t& r3) {
    asm volatile("ldmatrix.sync.aligned.m8n8.x4.shared.b16 {%0,%1,%2,%3}, [%4];"
                 : "=r"(r0), "=r"(r1), "=r"(r2), "=r"(r3) : "r"(addr));
}
__device__ __forceinline__ void ldm_x4t(uint32_t addr, uint32_t& r0, uint32_t& r1,
                                        uint32_t& r2, uint32_t& r3) {
    asm volatile("ldmatrix.sync.aligned.m8n8.x4.trans.shared.b16 {%0,%1,%2,%3}, [%4];"
                 : "=r"(r0), "=r"(r1), "=r"(r2), "=r"(r3) : "r"(addr));
}
__device__ __forceinline__ void mma16816h(float* c, const uint32_t* a, uint32_t b0, uint32_t b1) {
    asm volatile(
        "mma.sync.aligned.m16n8k16.row.col.f32.f16.f16.f32 "
        "{%0,%1,%2,%3}, {%4,%5,%6,%7}, {%8,%9}, {%0,%1,%2,%3};"
        : "+f"(c[0]), "+f"(c[1]), "+f"(c[2]), "+f"(c[3])
        : "r"(a[0]), "r"(a[1]), "r"(a[2]), "r"(a[3]), "r"(b0), "r"(b1));
}
__device__ __forceinline__ uint32_t packh2(float x, float y) {
    __half2 h = __floats2half2_rn(x, y);
    return *(uint32_t*)&h;
}

// ---------------- scratch (device globals, no allocs) ----------------
__device__ __half g_Wqkv[(size_t)NQKV_*C_];
__device__ __half g_Wo  [(size_t)C_*C_];
__device__ __half g_Wgu [(size_t)NGU_*C_];   // interleaved: 16-col groups (8 gate + 8 up)
__device__ __half g_Wd  [(size_t)C_*HIDP_];
__device__ __half g_XN  [(size_t)BT_*C_];
__device__ __half g_Y   [(size_t)BT_*C_];
__device__ __half g_HN  [(size_t)BT_*C_];
__device__ __half g_PR  [(size_t)BT_*HIDP_];
__device__ __half g_QKV [(size_t)BT_*NQKV_];
__device__ float  g_Hb  [(size_t)BT_*C_];
__device__ int    g_Ji[64];
__device__ float  g_Sg[64];
__device__ float  g_scale[112];   // [0:56) scale, [56:112) 1/(scale+1e-8)
__device__ double g_part[7*8*8];

struct ScaleSrc { const float* p[7]; int op[7]; };

// ---------------- scales (+ octonion table folded into fin) ----------------
__global__ void scales_part_k(ScaleSrc ss) {
    int t = blockIdx.z, i = blockIdx.x, sl = blockIdx.y;
    int OP = ss.op[t];
    const float* Wi = ss.p[t] + (size_t)i * OP;
    int per = (OP + 7) / 8;
    int st = sl * per, en = min(OP, st + per);
    double s = 0.0;
    for (int u = st + threadIdx.x; u < en; u += 256) s += (double)fabsf(Wi[u]);
    __shared__ double red[256];
    red[threadIdx.x] = s; __syncthreads();
    for (int stp = 128; stp > 0; stp >>= 1) {
        if (threadIdx.x < stp) red[threadIdx.x] += red[threadIdx.x + stp];
        __syncthreads();
    }
    if (threadIdx.x == 0) g_part[(t*8 + i)*8 + sl] = red[0];
}
__global__ void scales_fin_k(ScaleSrc ss) {
    int id = threadIdx.x;       // 64 threads
    if (id < 56) {
        int t = id >> 3, i = id & 7;
        double s = 0.0;
        for (int j = 0; j < 8; j++) s += g_part[(t*8 + i)*8 + j];
        float sc = (float)(s / (double)ss.op[t]);
        g_scale[id] = sc;
        g_scale[56 + id] = 1.0f / (sc + 1e-8f);
    } else if (id == 63) {
        int idx[8][8]; float sg[8][8];
        for (int j = 0; j < 8; j++) { idx[0][j] = j; sg[0][j] = 1.f; }
        for (int i = 1; i < 8; i++) {
            idx[i][0] = i; sg[i][0] = 1.f;
            idx[i][i] = 0; sg[i][i] = -1.f;
        }
        const int tr[7][3] = {{1,2,3},{1,4,5},{1,7,6},{2,4,6},{2,5,7},{3,4,7},{3,6,5}};
        for (int t = 0; t < 7; t++) {
            int a = tr[t][0], b = tr[t][1], c = tr[t][2];
            int per[3][3] = {{a,b,c},{b,c,a},{c,a,b}};
            for (int u = 0; u < 3; u++) {
                int p = per[u][0], q = per[u][1], r = per[u][2];
                idx[p][q] = r; sg[p][q] = 1.f;
                idx[q][p] = r; sg[q][p] = -1.f;
            }
        }
        for (int i = 0; i < 8; i++)
            for (int j = 0; j < 8; j++) {
                int k = idx[i][j];
                g_Ji[k*8 + j] = i;
                g_Sg[k*8 + j] = sg[i][j];
            }
    }
}

__device__ __forceinline__ float tsign_r(float w, float inv) {
    float q = rintf(w * inv);
    return fmaxf(-1.f, fminf(1.f, q));
}

// ---------------- merged weight builds (one kernel, region dispatch) ----------------
#define NB_QKV 12288   // NQKV_*C_/4/256
#define NB_WO  4096    // C_*C_/4/256
#define NB_GU  22016   // NGU_*C_/4/256
#define NB_D   22016   // C_*HIDP_/2/256
#define NB_ALL (NB_QKV + NB_WO + NB_GU + NB_D)

__global__ void build_all_k(const float* __restrict__ wq, const float* __restrict__ wk,
                            const float* __restrict__ wv, const float* __restrict__ wo,
                            const float* __restrict__ wg, const float* __restrict__ wu,
                            const float* __restrict__ wd,
                            __half* __restrict__ Fqkv, __half* __restrict__ Fo,
                            __half* __restrict__ Fgu, __half* __restrict__ Fd) {
    int b = blockIdx.x;
    if (b < NB_QKV) {
        int id = b * 256 + threadIdx.x;
        int r = id >> 9, c = (id & 511) << 2;
        int t = r >> 11, rr = r & 2047;
        int kb = rr >> 8, o = rr & 255, jb = c >> 8, p = c & 255;
        int i = g_Ji[kb*8 + jb];
        const float* src = (t == 0) ? wq : ((t == 1) ? wk : wv);
        float inv = g_scale[56 + t*8 + i];
        float ss = g_Sg[kb*8 + jb] * g_scale[t*8 + i];
        float4 w = *(const float4*)&src[((size_t)i << 16) + (o << 8) + p];
        size_t ob = (size_t)r * C_ + c;
        *(__half2*)&Fqkv[ob]     = __floats2half2_rn(ss * tsign_r(w.x, inv), ss * tsign_r(w.y, inv));
        *(__half2*)&Fqkv[ob + 2] = __floats2half2_rn(ss * tsign_r(w.z, inv), ss * tsign_r(w.w, inv));
    } else if (b < NB_QKV + NB_WO) {
        int id = (b - NB_QKV) * 256 + threadIdx.x;
        int r = id >> 9, c = (id & 511) << 2;
        int kb = r >> 8, o = r & 255, jb = c >> 8, p = c & 255;
        int i = g_Ji[kb*8 + jb];
        float inv = g_scale[56 + 24 + i];
        float ss = g_Sg[kb*8 + jb] * g_scale[24 + i];
        float4 w = *(const float4*)&wo[((size_t)i << 16) + (o << 8) + p];
        size_t ob = (size_t)r * C_ + c;
        *(__half2*)&Fo[ob]     = __floats2half2_rn(ss * tsign_r(w.x, inv), ss * tsign_r(w.y, inv));
        *(__half2*)&Fo[ob + 2] = __floats2half2_rn(ss * tsign_r(w.z, inv), ss * tsign_r(w.w, inv));
    } else if (b < NB_QKV + NB_WO + NB_GU) {
        int id = (b - NB_QKV - NB_WO) * 256 + threadIdx.x;
        int r = id >> 9, c = (id & 511) << 2;
        int type = (r >> 3) & 1;
        int hid = ((r >> 4) << 3) + (r & 7);
        int kb = hid / HBLK_, o = hid - kb * HBLK_;
        size_t ob = (size_t)r * C_ + c;
        if (o >= 683) {
            *(__half2*)&Fgu[ob] = __floats2half2_rn(0.f, 0.f);
            *(__half2*)&Fgu[ob + 2] = __floats2half2_rn(0.f, 0.f);
            return;
        }
        int jb = c >> 8, p = c & 255;
        int i = g_Ji[kb*8 + jb];
        const float* src = type ? wu : wg;
        float inv = g_scale[56 + 32 + type*8 + i];
        float ss = g_Sg[kb*8 + jb] * g_scale[32 + type*8 + i];
        float4 w = *(const float4*)&src[((size_t)i * 683 + o) * 256 + p];
        *(__half2*)&Fgu[ob]     = __floats2half2_rn(ss * tsign_r(w.x, inv), ss * tsign_r(w.y, inv));
        *(__half2*)&Fgu[ob + 2] = __floats2half2_rn(ss * tsign_r(w.z, inv), ss * tsign_r(w.w, inv));
    } else {
        int id = (b - NB_QKV - NB_WO - NB_GU) * 256 + threadIdx.x;
        int r = id / (HIDP_/2), c = (id - r * (HIDP_/2)) * 2;
        int jb = c / HBLK_, p = c - jb * HBLK_;
        int kb = r >> 8, o = r & 255;
        int i = g_Ji[kb*8 + jb];
        float inv = g_scale[56 + 48 + i];
        float ss = g_Sg[kb*8 + jb] * g_scale[48 + i];
        float v0 = 0.f, v1 = 0.f;
        if (p < 683) {
            const float* base = &wd[((size_t)i * 256 + o) * 683 + p];
            v0 = ss * tsign_r(base[0], inv);
            if (p + 1 < 683) v1 = ss * tsign_r(base[1], inv);
        }
        *(__half2*)&Fd[(size_t)r * HIDP_ + c] = __floats2half2_rn(v0, v1);
    }
}

// ---------------- rmsnorm -> fp16 (float4) ----------------
__global__ void rmsnorm_k(const float* __restrict__ x, const float* __restrict__ w,
                          __half* __restrict__ oh) {
    int row = blockIdx.x;
    const float4* xr = (const float4*)(x + (size_t)row * C_);
    const float4* wr = (const float4*)w;
    float4 v0 = xr[threadIdx.x];
    float4 v1 = xr[threadIdx.x + 256];
    float s = v0.x*v0.x + v0.y*v0.y + v0.z*v0.z + v0.w*v0.w
            + v1.x*v1.x + v1.y*v1.y + v1.z*v1.z + v1.w*v1.w;
    __shared__ float red[256];
    red[threadIdx.x] = s; __syncthreads();
    for (int st = 128; st > 0; st >>= 1) {
        if (threadIdx.x < st) red[threadIdx.x] += red[threadIdx.x + st];
        __syncthreads();
    }
    float inv = 1.0f / sqrtf(red[0] / (float)C_ + 1e-6f);
    float4 w0 = wr[threadIdx.x];
    float4 w1 = wr[threadIdx.x + 256];
    size_t base = (size_t)row * C_;
    int c0 = threadIdx.x * 4;
    *(__half2*)&oh[base + c0]     = __floats2half2_rn(v0.x*inv*w0.x, v0.y*inv*w0.y);
    *(__half2*)&oh[base + c0 + 2] = __floats2half2_rn(v0.z*inv*w0.z, v0.w*inv*w0.w);
    int c1 = c0 + 1024;
    *(__half2*)&oh[base + c1]     = __floats2half2_rn(v1.x*inv*w1.x, v1.y*inv*w1.y);
    *(__half2*)&oh[base + c1 + 2] = __floats2half2_rn(v1.z*inv*w1.z, v1.w*inv*w1.w);
}

// ---------------- 128x128x64 fp16 GEMM, 256 threads, 2 CTAs/SM, 1 sync/chunk ----------------
// mode 0: float out (+addsrc)
// mode 2: half out with fused RoPE (cols < 4096 get rotated)
// mode 3: interleaved silu(gate)*up -> half out [M, N/2]
#define G1_ABYTES 16384
#define G1_STAGE  32768    // A 16KB | B 16KB
#define G1_SMEM   (3 * G1_STAGE)

__global__ __launch_bounds__(256, 2) void gemm1_k(
    const __half* __restrict__ A, const __half* __restrict__ B,
    const float* __restrict__ addsrc, void* __restrict__ outp,
    int M, int N, int K, int mode,
    const float* __restrict__ fc, const float* __restrict__ fs)
{
    extern __shared__ __align__(1024) char smem[];
    int tid = threadIdx.x, wid = tid >> 5, lane = tid & 31;
    int wr = wid >> 1, wc = wid & 1;
    int bm = blockIdx.y * 128, bn = blockIdx.x * 128;
    uint32_t sbase = smem_u32(smem);
    int total = K >> 6;

    float acc[2][8][4];
#pragma unroll
    for (int mt = 0; mt < 2; mt++)
#pragma unroll
        for (int nt = 0; nt < 8; nt++)
#pragma unroll
            for (int e = 0; e < 4; e++) acc[mt][nt][e] = 0.f;

    int a_row = ((lane >> 3) & 1) * 8 + (lane & 7);
    int a_kb  = (lane >> 4) * 16;
    int b_n   = ((lane >> 4) & 1) * 8 + (lane & 7);
    int b_kb  = ((lane >> 3) & 1) * 16;

#define ISSUE1(ch) do {                                                       \
        int k0_ = (ch) << 6;                                                  \
        uint32_t stg_ = sbase + ((ch) % 3) * G1_STAGE;                        \
        _Pragma("unroll")                                                     \
        for (int u = 0; u < 4; u++) {                                         \
            int i_ = tid + u * 256;                                           \
            int row_ = i_ >> 3, seg_ = i_ & 7;                                \
            uint32_t so_ = SW128(row_ * 128 + seg_ * 16);                     \
            cp16(stg_ + so_, A + (size_t)(bm + row_) * K + k0_ + seg_ * 8);   \
            cp16(stg_ + G1_ABYTES + so_,                                      \
                 B + (size_t)(bn + row_) * K + k0_ + seg_ * 8);               \
        }                                                                     \
        asm volatile("cp.async.commit_group;" ::: "memory");                  \
    } while (0)

    ISSUE1(0);
    if (total > 1) ISSUE1(1);
    for (int ch = 0; ch < total; ch++) {
        if (ch + 1 < total) {
            asm volatile("cp.async.wait_group 1;" ::: "memory");
        } else {
            asm volatile("cp.async.wait_group 0;" ::: "memory");
        }
        __syncthreads();
        if (ch + 2 < total) ISSUE1(ch + 2);   // writes stage consumed at ch-1; safe after sync

        uint32_t stg = sbase + (ch % 3) * G1_STAGE;
#pragma unroll
        for (int kk = 0; kk < 4; kk++) {
            uint32_t a[2][4];
#pragma unroll
            for (int mt = 0; mt < 2; mt++) {
                uint32_t byte = (uint32_t)(wr * 32 + mt * 16 + a_row) * 128 + kk * 32 + a_kb;
                ldm_x4(stg + SW128(byte), a[mt][0], a[mt][1], a[mt][2], a[mt][3]);
            }
            uint32_t b[4][4];
#pragma unroll
            for (int np = 0; np < 4; np++) {
                uint32_t byte = (uint32_t)(wc * 64 + np * 16 + b_n) * 128 + kk * 32 + b_kb;
                ldm_x4(stg + G1_ABYTES + SW128(byte), b[np][0], b[np][1], b[np][2], b[np][3]);
            }
#pragma unroll
            for (int mt = 0; mt < 2; mt++)
#pragma unroll
                for (int nt = 0; nt < 8; nt++)
                    mma16816h(acc[mt][nt], a[mt], b[nt >> 1][(nt & 1) * 2],
                              b[nt >> 1][(nt & 1) * 2 + 1]);
        }
    }

    // ---------------- epilogue ----------------
    if (mode == 0) {
        float* Cm = (float*)outp;
#pragma unroll
        for (int mt = 0; mt < 2; mt++)
#pragma unroll
            for (int nt = 0; nt < 8; nt++) {
                int r0 = bm + wr * 32 + mt * 16 + (lane >> 2);
                int c  = bn + wc * 64 + nt * 8 + 2 * (lane & 3);
                size_t i0 = (size_t)r0 * N + c;
                size_t i1 = i0 + (size_t)8 * N;
                float2 v0 = make_float2(acc[mt][nt][0], acc[mt][nt][1]);
                float2 v1 = make_float2(acc[mt][nt][2], acc[mt][nt][3]);
                if (addsrc) {
                    float2 s0 = *(const float2*)&addsrc[i0];
                    float2 s1 = *(const float2*)&addsrc[i1];
                    v0.x += s0.x; v0.y += s0.y;
                    v1.x += s1.x; v1.y += s1.y;
                }
                *(float2*)&Cm[i0] = v0;
                *(float2*)&Cm[i1] = v1;
            }
    } else if (mode == 2) {
        __half* Cm = (__half*)outp;
#pragma unroll
        for (int mt = 0; mt < 2; mt++)
#pragma unroll
            for (int nt = 0; nt < 8; nt++) {
                int r0 = bm + wr * 32 + mt * 16 + (lane >> 2);
                int c  = bn + wc * 64 + nt * 8 + 2 * (lane & 3);
                float x0 = acc[mt][nt][0], y0 = acc[mt][nt][1];
                float x1 = acc[mt][nt][2], y1 = acc[mt][nt][3];
                if (c < 4096) {
                    int dp = (c & 127) >> 1;
                    int t0 = r0 & (T_ - 1), t1 = (r0 + 8) & (T_ - 1);
                    float c0 = fc[t0 * 64 + dp], s0 = fs[t0 * 64 + dp];
                    float c1 = fc[t1 * 64 + dp], s1 = fs[t1 * 64 + dp];
                    float nx0 = x0 * c0 - y0 * s0, ny0 = x0 * s0 + y0 * c0;
                    float nx1 = x1 * c1 - y1 * s1, ny1 = x1 * s1 + y1 * c1;
                    x0 = nx0; y0 = ny0; x1 = nx1; y1 = ny1;
                }
                *(__half2*)&Cm[(size_t)r0 * N + c] = __floats2half2_rn(x0, y0);
                *(__half2*)&Cm[(size_t)(r0 + 8) * N + c] = __floats2half2_rn(x1, y1);
            }
    } else {   // mode 3: silu(gate)*up, interleaved 16-col groups, out width N/2
        __half* Cm = (__half*)outp;
        int NO = N >> 1;
#pragma unroll
        for (int mt = 0; mt < 2; mt++)
#pragma unroll
            for (int ntp = 0; ntp < 4; ntp++) {
                int r0 = bm + wr * 32 + mt * 16 + (lane >> 2);
                int n0 = bn + wc * 64 + ntp * 16 + 2 * (lane & 3);
                int hid = ((n0 >> 4) << 3) + (n0 & 7);
                float* gv = acc[mt][2 * ntp];
                float* uv = acc[mt][2 * ntp + 1];
                float p0 = gv[0] / (1.f + __expf(-gv[0])) * uv[0];
                float p1 = gv[1] / (1.f + __expf(-gv[1])) * uv[1];
                float p2 = gv[2] / (1.f + __expf(-gv[2])) * uv[2];
                float p3 = gv[3] / (1.f + __expf(-gv[3])) * uv[3];
                *(__half2*)&Cm[(size_t)r0 * NO + hid] = __floats2half2_rn(p0, p1);
                *(__half2*)&Cm[(size_t)(r0 + 8) * NO + hid] = __floats2half2_rn(p2, p3);
            }
    }
}

// ---------------- HMMA flash attention: 64-row Q tiles, 32-key KV, 3 CTAs/SM ----------------
#define ATT_SMEM 49152     // Q 16K | 2 x (K 8K + V 8K)
__global__ __launch_bounds__(128, 3) void attn_k(
    const __half* __restrict__ qkv, __half* __restrict__ y)
{
    extern __shared__ __align__(1024) char smem[];
    uint32_t sQ = smem_u32(smem);
    int tid = threadIdx.x, wid = tid >> 5, lane = tid & 31;
    int bh = blockIdx.x;
    int qt = (int)(gridDim.y - 1 - blockIdx.y);   // heavy tiles first
    int bb = bh >> 4, h = bh & 15;
    const float sc = 0.08838834764831845f;

    int a_row = ((lane >> 3) & 1) * 8 + (lane & 7);
    int a_kb  = (lane >> 4) * 16;
    int b_n   = ((lane >> 4) & 1) * 8 + (lane & 7);
    int b_kb  = ((lane >> 3) & 1) * 16;
    int v_key = ((lane >> 3) & 1) * 8 + (lane & 7);
    int v_col = ((lane >> 4) & 1) * 8;

    int qrow0 = bb * T_ + qt * 64;

    // Q tile 64x128 fp16
#pragma unroll
    for (int u = 0; u < 8; u++) {
        int i = tid + u * 128;
        int row = i >> 4, seg = i & 15;
        cp16(sQ + SWK(row * 256 + seg * 16),
             qkv + (size_t)(qrow0 + row) * NQKV_ + h * HD_ + seg * 8);
    }
    asm volatile("cp.async.commit_group;" ::: "memory");

    int nkt = 2 * qt + 2;     // 32-key tiles
#define ISSUE_KV(kt_) do {                                                    \
        uint32_t stg_ = sQ + 16384 + ((kt_) & 1) * 16384;                     \
        int kb_ = (kt_) * 32;                                                 \
        _Pragma("unroll")                                                     \
        for (int u = 0; u < 4; u++) {                                         \
            int i_ = tid + u * 128;                                           \
            int row_ = i_ >> 4, seg_ = i_ & 15;                               \
            size_t gr_ = (size_t)(bb * T_ + kb_ + row_) * NQKV_ + h * HD_ + seg_ * 8; \
            uint32_t so_ = SWK(row_ * 256 + seg_ * 16);                       \
            cp16(stg_ + so_, qkv + 2048 + gr_);                               \
            cp16(stg_ + 8192 + so_, qkv + 4096 + gr_);                        \
        }                                                                     \
        asm volatile("cp.async.commit_group;" ::: "memory");                  \
    } while (0)

    ISSUE_KV(0);
    asm volatile("cp.async.wait_group 1;" ::: "memory");   // Q ready
    __syncthreads();

    uint32_t qa[8][4];
#pragma unroll
    for (int kk = 0; kk < 8; kk++) {
        uint32_t byte = (uint32_t)(wid * 16 + a_row) * 256 + kk * 32 + a_kb;
        ldm_x4(sQ + SWK(byte), qa[kk][0], qa[kk][1], qa[kk][2], qa[kk][3]);
    }

    float o[16][4];
#pragma unroll
    for (int nt = 0; nt < 16; nt++)
#pragma unroll
        for (int e = 0; e < 4; e++) o[nt][e] = 0.f;
    float mrun0 = -INFINITY, mrun1 = -INFINITY, lrun0 = 0.f, lrun1 = 0.f;

    int rg0 = qt * 64 + wid * 16 + (lane >> 2);
    int rg1 = rg0 + 8;

    for (int kt = 0; kt < nkt; kt++) {
        asm volatile("cp.async.wait_group 0;" ::: "memory");
        __syncthreads();
        if (kt + 1 < nkt) ISSUE_KV(kt + 1);   // other stage, consumed at kt-1; safe
        uint32_t sK = sQ + 16384 + (kt & 1) * 16384;
        uint32_t sV = sK + 8192;

        // S = Q K^T : 16 q-rows x 32 keys per warp
        float s[4][4];
#pragma unroll
        for (int nt = 0; nt < 4; nt++)
#pragma unroll
            for (int e = 0; e < 4; e++) s[nt][e] = 0.f;
#pragma unroll
        for (int kk = 0; kk < 8; kk++) {
            uint32_t bq[2][4];
#pragma unroll
            for (int np = 0; np < 2; np++) {
                uint32_t byte = (uint32_t)(np * 16 + b_n) * 256 + kk * 32 + b_kb;
                ldm_x4(sK + SWK(byte), bq[np][0], bq[np][1], bq[np][2], bq[np][3]);
            }
#pragma unroll
            for (int nt = 0; nt < 4; nt++)
                mma16816h(s[nt], qa[kk], bq[nt >> 1][(nt & 1) * 2],
                          bq[nt >> 1][(nt & 1) * 2 + 1]);
        }

        int kb0 = kt * 32;
        bool domask = (kt >= 2 * qt);
        float m0 = -INFINITY, m1 = -INFINITY;
#pragma unroll
        for (int nt = 0; nt < 4; nt++) {
            int k0 = kb0 + nt * 8 + 2 * (lane & 3);
#pragma unroll
            for (int e = 0; e < 4; e++) {
                float sv = s[nt][e] * sc;
                if (domask) {
                    int kc = k0 + (e & 1);
                    int rg = (e < 2) ? rg0 : rg1;
                    if (kc > rg) sv = -1e30f;
                }
                s[nt][e] = sv;
            }
            m0 = fmaxf(m0, fmaxf(s[nt][0], s[nt][1]));
            m1 = fmaxf(m1, fmaxf(s[nt][2], s[nt][3]));
        }
        m0 = fmaxf(m0, __shfl_xor_sync(0xffffffffu, m0, 1));
        m0 = fmaxf(m0, __shfl_xor_sync(0xffffffffu, m0, 2));
        m1 = fmaxf(m1, __shfl_xor_sync(0xffffffffu, m1, 1));
        m1 = fmaxf(m1, __shfl_xor_sync(0xffffffffu, m1, 2));
        float mn0 = fmaxf(mrun0, m0), mn1 = fmaxf(mrun1, m1);
        float al0 = __expf(mrun0 - mn0), al1 = __expf(mrun1 - mn1);
        mrun0 = mn0; mrun1 = mn1;
        float ls0 = 0.f, ls1 = 0.f;
#pragma unroll
        for (int nt = 0; nt < 4; nt++) {
            s[nt][0] = __expf(s[nt][0] - mn0);
            s[nt][1] = __expf(s[nt][1] - mn0);
            s[nt][2] = __expf(s[nt][2] - mn1);
            s[nt][3] = __expf(s[nt][3] - mn1);
            ls0 += s[nt][0] + s[nt][1];
            ls1 += s[nt][2] + s[nt][3];
        }
        ls0 += __shfl_xor_sync(0xffffffffu, ls0, 1);
        ls0 += __shfl_xor_sync(0xffffffffu, ls0, 2);
        ls1 += __shfl_xor_sync(0xffffffffu, ls1, 1);
        ls1 += __shfl_xor_sync(0xffffffffu, ls1, 2);
        lrun0 = lrun0 * al0 + ls0;
        lrun1 = lrun1 * al1 + ls1;
#pragma unroll
        for (int nt = 0; nt < 16; nt++) {
            o[nt][0] *= al0; o[nt][1] *= al0;
            o[nt][2] *= al1; o[nt][3] *= al1;
        }

        // O += P V  (32 keys in 2 k16 steps)
#pragma unroll
        for (int ks = 0; ks < 2; ks++) {
            uint32_t pa[4];
            pa[0] = packh2(s[2*ks][0],   s[2*ks][1]);
            pa[1] = packh2(s[2*ks][2],   s[2*ks][3]);
            pa[2] = packh2(s[2*ks+1][0], s[2*ks+1][1]);
            pa[3] = packh2(s[2*ks+1][2], s[2*ks+1][3]);
#pragma unroll
            for (int nv = 0; nv < 8; nv++) {
                uint32_t r0, r1, r2, r3;
                uint32_t byte = (uint32_t)(ks * 16 + v_key) * 256 + (nv * 16 + v_col) * 2;
                ldm_x4t(sV + SWK(byte), r0, r1, r2, r3);
                mma16816h(o[2*nv],     pa, r0, r1);
                mma16816h(o[2*nv + 1], pa, r2, r3);
            }
        }
    }

    float il0 = 1.f / lrun0, il1 = 1.f / lrun1;
    size_t row0 = (size_t)bb * T_ + rg0;
    size_t row1 = row0 + 8;
#pragma unroll
    for (int nt = 0; nt < 16; nt++) {
        int c = h * HD_ + nt * 8 + 2 * (lane & 3);
        *(__half2*)&y[row0 * C_ + c] = __floats2half2_rn(o[nt][0] * il0, o[nt][1] * il0);
        *(__half2*)&y[row1 * C_ + c] = __floats2half2_rn(o[nt][2] * il1, o[nt][3] * il1);
    }
}

// ---------------- launch ----------------
extern "C" void kernel_launch(void* const* d_in, const int* in_sizes, int n_in,
                              void* d_out, int out_size) {
    const float* x   = (const float*)d_in[0];
    const float* fc  = (const float*)d_in[1];
    const float* fs  = (const float*)d_in[2];
    const float* anw = (const float*)d_in[3];
    const float* fnw = (const float*)d_in[4];
    const float* wq  = (const float*)d_in[5];
    const float* wk  = (const float*)d_in[6];
    const float* wv  = (const float*)d_in[7];
    const float* wo  = (const float*)d_in[8];
    const float* wg  = (const float*)d_in[9];
    const float* wu  = (const float*)d_in[10];
    const float* wd  = (const float*)d_in[11];
    float* out = (float*)d_out;

    __half *Wqkv, *Wo, *Wgu, *Wd, *XN, *Y, *HN, *PR, *QKV;
    float *Hb;
    cudaGetSymbolAddress((void**)&Wqkv, g_Wqkv);
    cudaGetSymbolAddress((void**)&Wo,   g_Wo);
    cudaGetSymbolAddress((void**)&Wgu,  g_Wgu);
    cudaGetSymbolAddress((void**)&Wd,   g_Wd);
    cudaGetSymbolAddress((void**)&XN,   g_XN);
    cudaGetSymbolAddress((void**)&Y,    g_Y);
    cudaGetSymbolAddress((void**)&HN,   g_HN);
    cudaGetSymbolAddress((void**)&PR,   g_PR);
    cudaGetSymbolAddress((void**)&QKV,  g_QKV);
    cudaGetSymbolAddress((void**)&Hb,   g_Hb);

    cudaFuncSetAttribute(attn_k, cudaFuncAttributeMaxDynamicSharedMemorySize, ATT_SMEM);
    cudaFuncSetAttribute(gemm1_k, cudaFuncAttributeMaxDynamicSharedMemorySize, G1_SMEM);

    ScaleSrc ss;
    ss.p[0] = wq; ss.p[1] = wk; ss.p[2] = wv; ss.p[3] = wo;
    ss.p[4] = wg; ss.p[5] = wu; ss.p[6] = wd;
    ss.op[0] = ss.op[1] = ss.op[2] = ss.op[3] = 65536;
    ss.op[4] = ss.op[5] = ss.op[6] = 683 * 256;
    scales_part_k<<<dim3(8, 8, 7), 256>>>(ss);
    scales_fin_k<<<1, 64>>>(ss);

    build_all_k<<<NB_ALL, 256>>>(wq, wk, wv, wo, wg, wu, wd, Wqkv, Wo, Wgu, Wd);

    rmsnorm_k<<<BT_, 256>>>(x, anw, XN);

    gemm1_k<<<dim3(NQKV_ / 128, BT_ / 128), 256, G1_SMEM>>>(
        XN, Wqkv, nullptr, QKV, BT_, NQKV_, C_, 2, fc, fs);

    attn_k<<<dim3(64, 16), 128, ATT_SMEM>>>(QKV, Y);

    gemm1_k<<<dim3(C_ / 128, BT_ / 128), 256, G1_SMEM>>>(
        Y, Wo, x, Hb, BT_, C_, C_, 0, nullptr, nullptr);

    rmsnorm_k<<<BT_, 256>>>(Hb, fnw, HN);

    gemm1_k<<<dim3(NGU_ / 128, BT_ / 128), 256, G1_SMEM>>>(
        HN, Wgu, nullptr, PR, BT_, NGU_, C_, 3, nullptr, nullptr);

    gemm1_k<<<dim3(C_ / 128, BT_ / 128), 256, G1_SMEM>>>(
        PR, Wd, Hb, out, BT_, C_, HIDP_, 0, nullptr, nullptr);
}

// round 16
// speedup vs baseline: 1.1670x; 1.0143x over previous
#include <cuda_runtime.h>
#include <cuda_bf16.h>
#include <cuda_fp16.h>
#include <math.h>
#include <stdint.h>

// ---------------- problem constants ----------------
#define BT_    4096          // B*T
#define C_     2048
#define T_     1024
#define H_     16
#define HD_    128
#define HID_   5464
#define HBLK_  688           // padded hidden block
#define HIDP_  5504          // 8*688
#define NQKV_  6144
#define NGU_   11008         // interleaved gate/up
#define NTK_C  32            // K=2048 -> 32 chunks
#define NTK_H  86            // K=5504 -> 86 chunks

// ---------------- helpers ----------------
__device__ __forceinline__ uint32_t smem_u32(const void* p) {
    uint32_t a;
    asm("{ .reg .u64 t; cvta.to.shared.u64 t, %1; cvt.u32.u64 %0, t; }" : "=r"(a) : "l"(p));
    return a;
}
#define SW128(o) ((o) ^ (((o) >> 3) & 0x70))          // 128B-row swizzle
#define SWK(o)   ((o) ^ ((((o) >> 8) & 7) << 4))      // 256B-row swizzle

__device__ __forceinline__ void cp16(uint32_t s, const void* g) {
    asm volatile("cp.async.cg.shared.global [%0], [%1], 16;"
                 :: "r"(s), "l"(__cvta_generic_to_global(g)));
}
__device__ __forceinline__ void ldm_x4(uint32_t addr, uint32_t& r0, uint32_t& r1,
                                       uint32_t& r2, uint32_t& r3) {
    asm volatile("ldmatrix.sync.aligned.m8n8.x4.shared.b16 {%0,%1,%2,%3}, [%4];"
                 : "=r"(r0), "=r"(r1), "=r"(r2), "=r"(r3) : "r"(addr));
}
__device__ __forceinline__ void ldm_x4t(uint32_t addr, uint32_t& r0, uint32_t& r1,
                                        uint32_t& r2, uint32_t& r3) {
    asm volatile("ldmatrix.sync.aligned.m8n8.x4.trans.shared.b16 {%0,%1,%2,%3}, [%4];"
                 : "=r"(r0), "=r"(r1), "=r"(r2), "=r"(r3) : "r"(addr));
}
__device__ __forceinline__ void mma16816h(float* c, const uint32_t* a, uint32_t b0, uint32_t b1) {
    asm volatile(
        "mma.sync.aligned.m16n8k16.row.col.f32.f16.f16.f32 "
        "{%0,%1,%2,%3}, {%4,%5,%6,%7}, {%8,%9}, {%0,%1,%2,%3};"
        : "+f"(c[0]), "+f"(c[1]), "+f"(c[2]), "+f"(c[3])
        : "r"(a[0]), "r"(a[1]), "r"(a[2]), "r"(a[3]), "r"(b0), "r"(b1));
}
__device__ __forceinline__ uint32_t packh2(float x, float y) {
    __half2 h = __floats2half2_rn(x, y);
    return *(uint32_t*)&h;
}
#define MBAR_INIT(mb, c) asm volatile("mbarrier.init.shared.b64 [%0], %1;" :: "r"(mb), "r"(c) : "memory")
__device__ __forceinline__ void mbar_wait(uint32_t mb, uint32_t parity) {
    asm volatile(
        "{\n\t.reg .pred P1;\n\t"
        "W_%=:\n\t"
        "mbarrier.try_wait.parity.shared.b64 P1, [%0], %1;\n\t"
        "@P1 bra.uni D_%=;\n\t"
        "bra.uni W_%=;\n\t"
        "D_%=:\n\t}"
        :: "r"(mb), "r"(parity) : "memory");
}
__device__ __forceinline__ void bulk_cp(uint32_t dst, const void* src, uint32_t bytes, uint32_t mb) {
    asm volatile(
        "cp.async.bulk.shared::cluster.global.mbarrier::complete_tx::bytes [%0], [%1], %2, [%3];"
        :: "r"(dst), "l"(__cvta_generic_to_global(src)), "r"(bytes), "r"(mb) : "memory");
}
// tiled (128x64, SW128-preswizzled) element address
__device__ __forceinline__ __half2* tptr(__half* base, int r, int c, int ntk) {
    uint32_t b = (uint32_t)((r & 127) * 128 + (c & 63) * 2);
    size_t off = ((size_t)((r >> 7) * ntk + (c >> 6)) << 14) + SW128(b);
    return (__half2*)((char*)base + off);
}

// ---------------- scratch (device globals, no allocs) ----------------
__device__ __half g_Wqkv[(size_t)NQKV_*C_];     // tiled
__device__ __half g_Wo  [(size_t)C_*C_];        // tiled
__device__ __half g_Wgu [(size_t)NGU_*C_];      // tiled, interleaved 16-col groups
__device__ __half g_Wd  [(size_t)C_*HIDP_];     // tiled
__device__ __half g_XN  [(size_t)BT_*C_];       // tiled
__device__ __half g_Y   [(size_t)BT_*C_];       // tiled
__device__ __half g_HN  [(size_t)BT_*C_];       // tiled
__device__ __half g_PR  [(size_t)BT_*HIDP_];    // tiled
__device__ __half g_QKV [(size_t)BT_*NQKV_];    // row-major (attention input)
__device__ float  g_Hb  [(size_t)BT_*C_];
__device__ int    g_Ji[64];
__device__ float  g_Sg[64];
__device__ float  g_scale[112];
__device__ double g_part[7*8*8];

struct ScaleSrc { const float* p[7]; int op[7]; };

// ---------------- scales (+ octonion table folded into fin) ----------------
__global__ void scales_part_k(ScaleSrc ss) {
    int t = blockIdx.z, i = blockIdx.x, sl = blockIdx.y;
    int OP = ss.op[t];
    const float* Wi = ss.p[t] + (size_t)i * OP;
    int per = (OP + 7) / 8;
    int st = sl * per, en = min(OP, st + per);
    double s = 0.0;
    for (int u = st + threadIdx.x; u < en; u += 256) s += (double)fabsf(Wi[u]);
    __shared__ double red[256];
    red[threadIdx.x] = s; __syncthreads();
    for (int stp = 128; stp > 0; stp >>= 1) {
        if (threadIdx.x < stp) red[threadIdx.x] += red[threadIdx.x + stp];
        __syncthreads();
    }
    if (threadIdx.x == 0) g_part[(t*8 + i)*8 + sl] = red[0];
}
__global__ void scales_fin_k(ScaleSrc ss) {
    int id = threadIdx.x;
    if (id < 56) {
        int t = id >> 3, i = id & 7;
        double s = 0.0;
        for (int j = 0; j < 8; j++) s += g_part[(t*8 + i)*8 + j];
        float sc = (float)(s / (double)ss.op[t]);
        g_scale[id] = sc;
        g_scale[56 + id] = 1.0f / (sc + 1e-8f);
    } else if (id == 63) {
        int idx[8][8]; float sg[8][8];
        for (int j = 0; j < 8; j++) { idx[0][j] = j; sg[0][j] = 1.f; }
        for (int i = 1; i < 8; i++) {
            idx[i][0] = i; sg[i][0] = 1.f;
            idx[i][i] = 0; sg[i][i] = -1.f;
        }
        const int tr[7][3] = {{1,2,3},{1,4,5},{1,7,6},{2,4,6},{2,5,7},{3,4,7},{3,6,5}};
        for (int t = 0; t < 7; t++) {
            int a = tr[t][0], b = tr[t][1], c = tr[t][2];
            int per[3][3] = {{a,b,c},{b,c,a},{c,a,b}};
            for (int u = 0; u < 3; u++) {
                int p = per[u][0], q = per[u][1], r = per[u][2];
                idx[p][q] = r; sg[p][q] = 1.f;
                idx[q][p] = r; sg[q][p] = -1.f;
            }
        }
        for (int i = 0; i < 8; i++)
            for (int j = 0; j < 8; j++) {
                int k = idx[i][j];
                g_Ji[k*8 + j] = i;
                g_Sg[k*8 + j] = sg[i][j];
            }
    }
}

__device__ __forceinline__ float tsign_r(float w, float inv) {
    float q = rintf(w * inv);
    return fmaxf(-1.f, fminf(1.f, q));
}

// ---------------- merged weight builds -> tiled layout ----------------
#define NB_QKV 12288
#define NB_WO  4096
#define NB_GU  22016
#define NB_D   22016
#define NB_ALL (NB_QKV + NB_WO + NB_GU + NB_D)

__global__ void build_all_k(const float* __restrict__ wq, const float* __restrict__ wk,
                            const float* __restrict__ wv, const float* __restrict__ wo,
                            const float* __restrict__ wg, const float* __restrict__ wu,
                            const float* __restrict__ wd,
                            __half* __restrict__ Fqkv, __half* __restrict__ Fo,
                            __half* __restrict__ Fgu, __half* __restrict__ Fd) {
    int b = blockIdx.x;
    if (b < NB_QKV) {
        int id = b * 256 + threadIdx.x;
        int r = id >> 9, c = (id & 511) << 2;
        int t = r >> 11, rr = r & 2047;
        int kb = rr >> 8, o = rr & 255, jb = c >> 8, p = c & 255;
        int i = g_Ji[kb*8 + jb];
        const float* src = (t == 0) ? wq : ((t == 1) ? wk : wv);
        float inv = g_scale[56 + t*8 + i];
        float ss = g_Sg[kb*8 + jb] * g_scale[t*8 + i];
        float4 w = *(const float4*)&src[((size_t)i << 16) + (o << 8) + p];
        *tptr(Fqkv, r, c, NTK_C)     = __floats2half2_rn(ss * tsign_r(w.x, inv), ss * tsign_r(w.y, inv));
        *tptr(Fqkv, r, c + 2, NTK_C) = __floats2half2_rn(ss * tsign_r(w.z, inv), ss * tsign_r(w.w, inv));
    } else if (b < NB_QKV + NB_WO) {
        int id = (b - NB_QKV) * 256 + threadIdx.x;
        int r = id >> 9, c = (id & 511) << 2;
        int kb = r >> 8, o = r & 255, jb = c >> 8, p = c & 255;
        int i = g_Ji[kb*8 + jb];
        float inv = g_scale[56 + 24 + i];
        float ss = g_Sg[kb*8 + jb] * g_scale[24 + i];
        float4 w = *(const float4*)&wo[((size_t)i << 16) + (o << 8) + p];
        *tptr(Fo, r, c, NTK_C)     = __floats2half2_rn(ss * tsign_r(w.x, inv), ss * tsign_r(w.y, inv));
        *tptr(Fo, r, c + 2, NTK_C) = __floats2half2_rn(ss * tsign_r(w.z, inv), ss * tsign_r(w.w, inv));
    } else if (b < NB_QKV + NB_WO + NB_GU) {
        int id = (b - NB_QKV - NB_WO) * 256 + threadIdx.x;
        int r = id >> 9, c = (id & 511) << 2;
        int type = (r >> 3) & 1;
        int hid = ((r >> 4) << 3) + (r & 7);
        int kb = hid / HBLK_, o = hid - kb * HBLK_;
        if (o >= 683) {
            *tptr(Fgu, r, c, NTK_C)     = __floats2half2_rn(0.f, 0.f);
            *tptr(Fgu, r, c + 2, NTK_C) = __floats2half2_rn(0.f, 0.f);
            return;
        }
        int jb = c >> 8, p = c & 255;
        int i = g_Ji[kb*8 + jb];
        const float* src = type ? wu : wg;
        float inv = g_scale[56 + 32 + type*8 + i];
        float ss = g_Sg[kb*8 + jb] * g_scale[32 + type*8 + i];
        float4 w = *(const float4*)&src[((size_t)i * 683 + o) * 256 + p];
        *tptr(Fgu, r, c, NTK_C)     = __floats2half2_rn(ss * tsign_r(w.x, inv), ss * tsign_r(w.y, inv));
        *tptr(Fgu, r, c + 2, NTK_C) = __floats2half2_rn(ss * tsign_r(w.z, inv), ss * tsign_r(w.w, inv));
    } else {
        int id = (b - NB_QKV - NB_WO - NB_GU) * 256 + threadIdx.x;
        int r = id / (HIDP_/2), c = (id - r * (HIDP_/2)) * 2;
        int jb = c / HBLK_, p = c - jb * HBLK_;
        int kb = r >> 8, o = r & 255;
        int i = g_Ji[kb*8 + jb];
        float inv = g_scale[56 + 48 + i];
        float ss = g_Sg[kb*8 + jb] * g_scale[48 + i];
        float v0 = 0.f, v1 = 0.f;
        if (p < 683) {
            const float* base = &wd[((size_t)i * 256 + o) * 683 + p];
            v0 = ss * tsign_r(base[0], inv);
            if (p + 1 < 683) v1 = ss * tsign_r(base[1], inv);
        }
        *tptr(Fd, r, c, NTK_H) = __floats2half2_rn(v0, v1);
    }
}

// ---------------- rmsnorm -> fp16 tiled ----------------
__global__ void rmsnorm_k(const float* __restrict__ x, const float* __restrict__ w,
                          __half* __restrict__ oh) {
    int row = blockIdx.x;
    const float4* xr = (const float4*)(x + (size_t)row * C_);
    const float4* wr = (const float4*)w;
    float4 v0 = xr[threadIdx.x];
    float4 v1 = xr[threadIdx.x + 256];
    float s = v0.x*v0.x + v0.y*v0.y + v0.z*v0.z + v0.w*v0.w
            + v1.x*v1.x + v1.y*v1.y + v1.z*v1.z + v1.w*v1.w;
    __shared__ float red[256];
    red[threadIdx.x] = s; __syncthreads();
    for (int st = 128; st > 0; st >>= 1) {
        if (threadIdx.x < st) red[threadIdx.x] += red[threadIdx.x + st];
        __syncthreads();
    }
    float inv = 1.0f / sqrtf(red[0] / (float)C_ + 1e-6f);
    float4 w0 = wr[threadIdx.x];
    float4 w1 = wr[threadIdx.x + 256];
    int c0 = threadIdx.x * 4;
    *tptr(oh, row, c0, NTK_C)     = __floats2half2_rn(v0.x*inv*w0.x, v0.y*inv*w0.y);
    *tptr(oh, row, c0 + 2, NTK_C) = __floats2half2_rn(v0.z*inv*w0.z, v0.w*inv*w0.w);
    int c1 = c0 + 1024;
    *tptr(oh, row, c1, NTK_C)     = __floats2half2_rn(v1.x*inv*w1.x, v1.y*inv*w1.y);
    *tptr(oh, row, c1 + 2, NTK_C) = __floats2half2_rn(v1.z*inv*w1.z, v1.w*inv*w1.w);
}

// ---------------- 128x128x64 fp16 GEMM, bulk-DMA fill, mbarrier pipeline ----------------
// A, B are TILED (128x64 pre-swizzled 16KB tiles). ntk == K/64 == total.
// mode 0: float out (+addsrc)  mode 2: half row-major + fused RoPE
// mode 3: interleaved silu(gate)*up -> half TILED out [M, N/2] (ntk_out = NTK_H)
#define G1_ABYTES 16384
#define G1_STAGE  32768
#define G1_SMEM   (3 * G1_STAGE + 64)

__global__ __launch_bounds__(256, 2) void gemm1_k(
    const __half* __restrict__ A, const __half* __restrict__ B,
    const float* __restrict__ addsrc, void* __restrict__ outp,
    int M, int N, int K, int mode,
    const float* __restrict__ fc, const float* __restrict__ fs)
{
    extern __shared__ __align__(1024) char smem[];
    int tid = threadIdx.x, wid = tid >> 5, lane = tid & 31;
    int wr = wid >> 1, wc = wid & 1;
    int bm = blockIdx.y * 128, bn = blockIdx.x * 128;
    uint32_t sbase = smem_u32(smem);
    uint32_t mbar = sbase + 3 * G1_STAGE;
    int total = K >> 6;

    if (tid == 0) {
        MBAR_INIT(mbar, 1);
        MBAR_INIT(mbar + 8, 1);
        MBAR_INIT(mbar + 16, 1);
    }
    __syncthreads();

    float acc[2][8][4];
#pragma unroll
    for (int mt = 0; mt < 2; mt++)
#pragma unroll
        for (int nt = 0; nt < 8; nt++)
#pragma unroll
            for (int e = 0; e < 4; e++) acc[mt][nt][e] = 0.f;

    int a_row = ((lane >> 3) & 1) * 8 + (lane & 7);
    int a_kb  = (lane >> 4) * 16;
    int b_n   = ((lane >> 4) & 1) * 8 + (lane & 7);
    int b_kb  = ((lane >> 3) & 1) * 16;

#define ISSUE_T(ch) do {                                                      \
        if (tid == 0) {                                                       \
            int s_ = (ch) % 3;                                                \
            uint32_t mb_ = mbar + s_ * 8;                                     \
            asm volatile("mbarrier.arrive.expect_tx.shared.b64 _, [%0], %1;"  \
                         :: "r"(mb_), "r"(32768u) : "memory");                \
            uint32_t dst_ = sbase + s_ * G1_STAGE;                            \
            bulk_cp(dst_, A + (((size_t)(bm >> 7) * total + (ch)) << 13),     \
                    16384u, mb_);                                             \
            bulk_cp(dst_ + G1_ABYTES,                                         \
                    B + (((size_t)(bn >> 7) * total + (ch)) << 13),           \
                    16384u, mb_);                                             \
        }                                                                     \
    } while (0)

    ISSUE_T(0);
    if (total > 1) ISSUE_T(1);
    for (int ch = 0; ch < total; ch++) {
        mbar_wait(mbar + (ch % 3) * 8, (uint32_t)((ch / 3) & 1));

        uint32_t stg = sbase + (ch % 3) * G1_STAGE;
#pragma unroll
        for (int kk = 0; kk < 4; kk++) {
            uint32_t a[2][4];
#pragma unroll
            for (int mt = 0; mt < 2; mt++) {
                uint32_t byte = (uint32_t)(wr * 32 + mt * 16 + a_row) * 128 + kk * 32 + a_kb;
                ldm_x4(stg + SW128(byte), a[mt][0], a[mt][1], a[mt][2], a[mt][3]);
            }
            uint32_t b[4][4];
#pragma unroll
            for (int np = 0; np < 4; np++) {
                uint32_t byte = (uint32_t)(wc * 64 + np * 16 + b_n) * 128 + kk * 32 + b_kb;
                ldm_x4(stg + G1_ABYTES + SW128(byte), b[np][0], b[np][1], b[np][2], b[np][3]);
            }
#pragma unroll
            for (int mt = 0; mt < 2; mt++)
#pragma unroll
                for (int nt = 0; nt < 8; nt++)
                    mma16816h(acc[mt][nt], a[mt], b[nt >> 1][(nt & 1) * 2],
                              b[nt >> 1][(nt & 1) * 2 + 1]);
        }
        __syncthreads();                       // all warps done with stage (ch-1)%3 == (ch+2)%3
        if (ch + 2 < total) ISSUE_T(ch + 2);
    }

    // ---------------- epilogue ----------------
    if (mode == 0) {
        float* Cm = (float*)outp;
#pragma unroll
        for (int mt = 0; mt < 2; mt++)
#pragma unroll
            for (int nt = 0; nt < 8; nt++) {
                int r0 = bm + wr * 32 + mt * 16 + (lane >> 2);
                int c  = bn + wc * 64 + nt * 8 + 2 * (lane & 3);
                size_t i0 = (size_t)r0 * N + c;
                size_t i1 = i0 + (size_t)8 * N;
                float2 v0 = make_float2(acc[mt][nt][0], acc[mt][nt][1]);
                float2 v1 = make_float2(acc[mt][nt][2], acc[mt][nt][3]);
                if (addsrc) {
                    float2 s0 = *(const float2*)&addsrc[i0];
                    float2 s1 = *(const float2*)&addsrc[i1];
                    v0.x += s0.x; v0.y += s0.y;
                    v1.x += s1.x; v1.y += s1.y;
                }
                *(float2*)&Cm[i0] = v0;
                *(float2*)&Cm[i1] = v1;
            }
    } else if (mode == 2) {
        __half* Cm = (__half*)outp;
#pragma unroll
        for (int mt = 0; mt < 2; mt++)
#pragma unroll
            for (int nt = 0; nt < 8; nt++) {
                int r0 = bm + wr * 32 + mt * 16 + (lane >> 2);
                int c  = bn + wc * 64 + nt * 8 + 2 * (lane & 3);
                float x0 = acc[mt][nt][0], y0 = acc[mt][nt][1];
                float x1 = acc[mt][nt][2], y1 = acc[mt][nt][3];
                if (c < 4096) {
                    int dp = (c & 127) >> 1;
                    int t0 = r0 & (T_ - 1), t1 = (r0 + 8) & (T_ - 1);
                    float c0 = fc[t0 * 64 + dp], s0 = fs[t0 * 64 + dp];
                    float c1 = fc[t1 * 64 + dp], s1 = fs[t1 * 64 + dp];
                    float nx0 = x0 * c0 - y0 * s0, ny0 = x0 * s0 + y0 * c0;
                    float nx1 = x1 * c1 - y1 * s1, ny1 = x1 * s1 + y1 * c1;
                    x0 = nx0; y0 = ny0; x1 = nx1; y1 = ny1;
                }
                *(__half2*)&Cm[(size_t)r0 * N + c] = __floats2half2_rn(x0, y0);
                *(__half2*)&Cm[(size_t)(r0 + 8) * N + c] = __floats2half2_rn(x1, y1);
            }
    } else {   // mode 3: silu(gate)*up -> TILED half out, K-width HIDP_
        __half* Cm = (__half*)outp;
#pragma unroll
        for (int mt = 0; mt < 2; mt++)
#pragma unroll
            for (int ntp = 0; ntp < 4; ntp++) {
                int r0 = bm + wr * 32 + mt * 16 + (lane >> 2);
                int n0 = bn + wc * 64 + ntp * 16 + 2 * (lane & 3);
                int hid = ((n0 >> 4) << 3) + (n0 & 7);
                float* gv = acc[mt][2 * ntp];
                float* uv = acc[mt][2 * ntp + 1];
                float p0 = gv[0] / (1.f + __expf(-gv[0])) * uv[0];
                float p1 = gv[1] / (1.f + __expf(-gv[1])) * uv[1];
                float p2 = gv[2] / (1.f + __expf(-gv[2])) * uv[2];
                float p3 = gv[3] / (1.f + __expf(-gv[3])) * uv[3];
                *tptr(Cm, r0, hid, NTK_H)     = __floats2half2_rn(p0, p1);
                *tptr(Cm, r0 + 8, hid, NTK_H) = __floats2half2_rn(p2, p3);
            }
    }
}

// ---------------- HMMA flash attention: 64-row Q tiles, 32-key KV, 3 CTAs/SM ----------------
// reads row-major QKV, writes TILED Y
#define ATT_SMEM 49152
__global__ __launch_bounds__(128, 3) void attn_k(
    const __half* __restrict__ qkv, __half* __restrict__ y)
{
    extern __shared__ __align__(1024) char smem[];
    uint32_t sQ = smem_u32(smem);
    int tid = threadIdx.x, wid = tid >> 5, lane = tid & 31;
    int bh = blockIdx.x;
    int qt = (int)(gridDim.y - 1 - blockIdx.y);
    int bb = bh >> 4, h = bh & 15;
    const float sc = 0.08838834764831845f;

    int a_row = ((lane >> 3) & 1) * 8 + (lane & 7);
    int a_kb  = (lane >> 4) * 16;
    int b_n   = ((lane >> 4) & 1) * 8 + (lane & 7);
    int b_kb  = ((lane >> 3) & 1) * 16;
    int v_key = ((lane >> 3) & 1) * 8 + (lane & 7);
    int v_col = ((lane >> 4) & 1) * 8;

    int qrow0 = bb * T_ + qt * 64;

#pragma unroll
    for (int u = 0; u < 8; u++) {
        int i = tid + u * 128;
        int row = i >> 4, seg = i & 15;
        cp16(sQ + SWK(row * 256 + seg * 16),
             qkv + (size_t)(qrow0 + row) * NQKV_ + h * HD_ + seg * 8);
    }
    asm volatile("cp.async.commit_group;" ::: "memory");

    int nkt = 2 * qt + 2;
#define ISSUE_KV(kt_) do {                                                    \
        uint32_t stg_ = sQ + 16384 + ((kt_) & 1) * 16384;                     \
        int kb_ = (kt_) * 32;                                                 \
        _Pragma("unroll")                                                     \
        for (int u = 0; u < 4; u++) {                                         \
            int i_ = tid + u * 128;                                           \
            int row_ = i_ >> 4, seg_ = i_ & 15;                               \
            size_t gr_ = (size_t)(bb * T_ + kb_ + row_) * NQKV_ + h * HD_ + seg_ * 8; \
            uint32_t so_ = SWK(row_ * 256 + seg_ * 16);                       \
            cp16(stg_ + so_, qkv + 2048 + gr_);                               \
            cp16(stg_ + 8192 + so_, qkv + 4096 + gr_);                        \
        }                                                                     \
        asm volatile("cp.async.commit_group;" ::: "memory");                  \
    } while (0)

    ISSUE_KV(0);
    asm volatile("cp.async.wait_group 1;" ::: "memory");
    __syncthreads();

    uint32_t qa[8][4];
#pragma unroll
    for (int kk = 0; kk < 8; kk++) {
        uint32_t byte = (uint32_t)(wid * 16 + a_row) * 256 + kk * 32 + a_kb;
        ldm_x4(sQ + SWK(byte), qa[kk][0], qa[kk][1], qa[kk][2], qa[kk][3]);
    }

    float o[16][4];
#pragma unroll
    for (int nt = 0; nt < 16; nt++)
#pragma unroll
        for (int e = 0; e < 4; e++) o[nt][e] = 0.f;
    float mrun0 = -INFINITY, mrun1 = -INFINITY, lrun0 = 0.f, lrun1 = 0.f;

    int rg0 = qt * 64 + wid * 16 + (lane >> 2);
    int rg1 = rg0 + 8;

    for (int kt = 0; kt < nkt; kt++) {
        asm volatile("cp.async.wait_group 0;" ::: "memory");
        __syncthreads();
        if (kt + 1 < nkt) ISSUE_KV(kt + 1);
        uint32_t sK = sQ + 16384 + (kt & 1) * 16384;
        uint32_t sV = sK + 8192;

        float s[4][4];
#pragma unroll
        for (int nt = 0; nt < 4; nt++)
#pragma unroll
            for (int e = 0; e < 4; e++) s[nt][e] = 0.f;
#pragma unroll
        for (int kk = 0; kk < 8; kk++) {
            uint32_t bq[2][4];
#pragma unroll
            for (int np = 0; np < 2; np++) {
                uint32_t byte = (uint32_t)(np * 16 + b_n) * 256 + kk * 32 + b_kb;
                ldm_x4(sK + SWK(byte), bq[np][0], bq[np][1], bq[np][2], bq[np][3]);
            }
#pragma unroll
            for (int nt = 0; nt < 4; nt++)
                mma16816h(s[nt], qa[kk], bq[nt >> 1][(nt & 1) * 2],
                          bq[nt >> 1][(nt & 1) * 2 + 1]);
        }

        int kb0 = kt * 32;
        bool domask = (kt >= 2 * qt);
        float m0 = -INFINITY, m1 = -INFINITY;
#pragma unroll
        for (int nt = 0; nt < 4; nt++) {
            int k0 = kb0 + nt * 8 + 2 * (lane & 3);
#pragma unroll
            for (int e = 0; e < 4; e++) {
                float sv = s[nt][e] * sc;
                if (domask) {
                    int kc = k0 + (e & 1);
                    int rg = (e < 2) ? rg0 : rg1;
                    if (kc > rg) sv = -1e30f;
                }
                s[nt][e] = sv;
            }
            m0 = fmaxf(m0, fmaxf(s[nt][0], s[nt][1]));
            m1 = fmaxf(m1, fmaxf(s[nt][2], s[nt][3]));
        }
        m0 = fmaxf(m0, __shfl_xor_sync(0xffffffffu, m0, 1));
        m0 = fmaxf(m0, __shfl_xor_sync(0xffffffffu, m0, 2));
        m1 = fmaxf(m1, __shfl_xor_sync(0xffffffffu, m1, 1));
        m1 = fmaxf(m1, __shfl_xor_sync(0xffffffffu, m1, 2));
        float mn0 = fmaxf(mrun0, m0), mn1 = fmaxf(mrun1, m1);
        float al0 = __expf(mrun0 - mn0), al1 = __expf(mrun1 - mn1);
        mrun0 = mn0; mrun1 = mn1;
        float ls0 = 0.f, ls1 = 0.f;
#pragma unroll
        for (int nt = 0; nt < 4; nt++) {
            s[nt][0] = __expf(s[nt][0] - mn0);
            s[nt][1] = __expf(s[nt][1] - mn0);
            s[nt][2] = __expf(s[nt][2] - mn1);
            s[nt][3] = __expf(s[nt][3] - mn1);
            ls0 += s[nt][0] + s[nt][1];
            ls1 += s[nt][2] + s[nt][3];
        }
        ls0 += __shfl_xor_sync(0xffffffffu, ls0, 1);
        ls0 += __shfl_xor_sync(0xffffffffu, ls0, 2);
        ls1 += __shfl_xor_sync(0xffffffffu, ls1, 1);
        ls1 += __shfl_xor_sync(0xffffffffu, ls1, 2);
        lrun0 = lrun0 * al0 + ls0;
        lrun1 = lrun1 * al1 + ls1;
#pragma unroll
        for (int nt = 0; nt < 16; nt++) {
            o[nt][0] *= al0; o[nt][1] *= al0;
            o[nt][2] *= al1; o[nt][3] *= al1;
        }

#pragma unroll
        for (int ks = 0; ks < 2; ks++) {
            uint32_t pa[4];
            pa[0] = packh2(s[2*ks][0],   s[2*ks][1]);
            pa[1] = packh2(s[2*ks][2],   s[2*ks][3]);
            pa[2] = packh2(s[2*ks+1][0], s[2*ks+1][1]);
            pa[3] = packh2(s[2*ks+1][2], s[2*ks+1][3]);
#pragma unroll
            for (int nv = 0; nv < 8; nv++) {
                uint32_t r0, r1, r2, r3;
                uint32_t byte = (uint32_t)(ks * 16 + v_key) * 256 + (nv * 16 + v_col) * 2;
                ldm_x4t(sV + SWK(byte), r0, r1, r2, r3);
                mma16816h(o[2*nv],     pa, r0, r1);
                mma16816h(o[2*nv + 1], pa, r2, r3);
            }
        }
    }

    float il0 = 1.f / lrun0, il1 = 1.f / lrun1;
    int row0 = bb * T_ + rg0;
    int row1 = row0 + 8;
#pragma unroll
    for (int nt = 0; nt < 16; nt++) {
        int c = h * HD_ + nt * 8 + 2 * (lane & 3);
        *tptr(y, row0, c, NTK_C) = __floats2half2_rn(o[nt][0] * il0, o[nt][1] * il0);
        *tptr(y, row1, c, NTK_C) = __floats2half2_rn(o[nt][2] * il1, o[nt][3] * il1);
    }
}

// ---------------- launch ----------------
extern "C" void kernel_launch(void* const* d_in, const int* in_sizes, int n_in,
                              void* d_out, int out_size) {
    const float* x   = (const float*)d_in[0];
    const float* fc  = (const float*)d_in[1];
    const float* fs  = (const float*)d_in[2];
    const float* anw = (const float*)d_in[3];
    const float* fnw = (const float*)d_in[4];
    const float* wq  = (const float*)d_in[5];
    const float* wk  = (const float*)d_in[6];
    const float* wv  = (const float*)d_in[7];
    const float* wo  = (const float*)d_in[8];
    const float* wg  = (const float*)d_in[9];
    const float* wu  = (const float*)d_in[10];
    const float* wd  = (const float*)d_in[11];
    float* out = (float*)d_out;

    __half *Wqkv, *Wo, *Wgu, *Wd, *XN, *Y, *HN, *PR, *QKV;
    float *Hb;
    cudaGetSymbolAddress((void**)&Wqkv, g_Wqkv);
    cudaGetSymbolAddress((void**)&Wo,   g_Wo);
    cudaGetSymbolAddress((void**)&Wgu,  g_Wgu);
    cudaGetSymbolAddress((void**)&Wd,   g_Wd);
    cudaGetSymbolAddress((void**)&XN,   g_XN);
    cudaGetSymbolAddress((void**)&Y,    g_Y);
    cudaGetSymbolAddress((void**)&HN,   g_HN);
    cudaGetSymbolAddress((void**)&PR,   g_PR);
    cudaGetSymbolAddress((void**)&QKV,  g_QKV);
    cudaGetSymbolAddress((void**)&Hb,   g_Hb);

    cudaFuncSetAttribute(attn_k, cudaFuncAttributeMaxDynamicSharedMemorySize, ATT_SMEM);
    cudaFuncSetAttribute(gemm1_k, cudaFuncAttributeMaxDynamicSharedMemorySize, G1_SMEM);

    ScaleSrc ss;
    ss.p[0] = wq; ss.p[1] = wk; ss.p[2] = wv; ss.p[3] = wo;
    ss.p[4] = wg; ss.p[5] = wu; ss.p[6] = wd;
    ss.op[0] = ss.op[1] = ss.op[2] = ss.op[3] = 65536;
    ss.op[4] = ss.op[5] = ss.op[6] = 683 * 256;
    scales_part_k<<<dim3(8, 8, 7), 256>>>(ss);
    scales_fin_k<<<1, 64>>>(ss);

    build_all_k<<<NB_ALL, 256>>>(wq, wk, wv, wo, wg, wu, wd, Wqkv, Wo, Wgu, Wd);

    rmsnorm_k<<<BT_, 256>>>(x, anw, XN);

    gemm1_k<<<dim3(NQKV_ / 128, BT_ / 128), 256, G1_SMEM>>>(
        XN, Wqkv, nullptr, QKV, BT_, NQKV_, C_, 2, fc, fs);

    attn_k<<<dim3(64, 16), 128, ATT_SMEM>>>(QKV, Y);

    gemm1_k<<<dim3(C_ / 128, BT_ / 128), 256, G1_SMEM>>>(
        Y, Wo, x, Hb, BT_, C_, C_, 0, nullptr, nullptr);

    rmsnorm_k<<<BT_, 256>>>(Hb, fnw, HN);

    gemm1_k<<<dim3(NGU_ / 128, BT_ / 128), 256, G1_SMEM>>>(
        HN, Wgu, nullptr, PR, BT_, NGU_, C_, 3, nullptr, nullptr);

    gemm1_k<<<dim3(C_ / 128, BT_ / 128), 256, G1_SMEM>>>(
        PR, Wd, Hb, out, BT_, C_, HIDP_, 0, nullptr, nullptr);
}

// round 17
// speedup vs baseline: 1.1706x; 1.0032x over previous
#include <cuda_runtime.h>
#include <cuda_bf16.h>
#include <cuda_fp16.h>
#include <math.h>
#include <stdint.h>

// ---------------- problem constants ----------------
#define BT_    4096          // B*T
#define C_     2048
#define T_     1024
#define H_     16
#define HD_    128
#define HID_   5464
#define HBLK_  688           // padded hidden block
#define HIDP_  5504          // 8*688
#define NQKV_  6144
#define NGU_   11008         // interleaved gate/up
#define NTK_C  32            // K=2048 -> 32 chunks
#define NTK_H  86            // K=5504 -> 86 chunks

// ---------------- helpers ----------------
__device__ __forceinline__ uint32_t smem_u32(const void* p) {
    uint32_t a;
    asm("{ .reg .u64 t; cvta.to.shared.u64 t, %1; cvt.u32.u64 %0, t; }" : "=r"(a) : "l"(p));
    return a;
}
#define SW128(o) ((o) ^ (((o) >> 3) & 0x70))          // 128B-row swizzle
#define SWK(o)   ((o) ^ ((((o) >> 8) & 7) << 4))      // 256B-row swizzle

__device__ __forceinline__ void cp16(uint32_t s, const void* g) {
    asm volatile("cp.async.cg.shared.global [%0], [%1], 16;"
                 :: "r"(s), "l"(__cvta_generic_to_global(g)));
}
__device__ __forceinline__ void ldm_x4(uint32_t addr, uint32_t& r0, uint32_t& r1,
                                       uint32_t& r2, uint32_t& r3) {
    asm volatile("ldmatrix.sync.aligned.m8n8.x4.shared.b16 {%0,%1,%2,%3}, [%4];"
                 : "=r"(r0), "=r"(r1), "=r"(r2), "=r"(r3) : "r"(addr));
}
__device__ __forceinline__ void ldm_x4t(uint32_t addr, uint32_t& r0, uint32_t& r1,
                                        uint32_t& r2, uint32_t& r3) {
    asm volatile("ldmatrix.sync.aligned.m8n8.x4.trans.shared.b16 {%0,%1,%2,%3}, [%4];"
                 : "=r"(r0), "=r"(r1), "=r"(r2), "=r"(r3) : "r"(addr));
}
__device__ __forceinline__ void mma16816h(float* c, const uint32_t* a, uint32_t b0, uint32_t b1) {
    asm volatile(
        "mma.sync.aligned.m16n8k16.row.col.f32.f16.f16.f32 "
        "{%0,%1,%2,%3}, {%4,%5,%6,%7}, {%8,%9}, {%0,%1,%2,%3};"
        : "+f"(c[0]), "+f"(c[1]), "+f"(c[2]), "+f"(c[3])
        : "r"(a[0]), "r"(a[1]), "r"(a[2]), "r"(a[3]), "r"(b0), "r"(b1));
}
__device__ __forceinline__ uint32_t packh2(float x, float y) {
    __half2 h = __floats2half2_rn(x, y);
    return *(uint32_t*)&h;
}
#define MBAR_INIT(mb, c) asm volatile("mbarrier.init.shared.b64 [%0], %1;" :: "r"(mb), "r"(c) : "memory")
__device__ __forceinline__ void mbar_wait(uint32_t mb, uint32_t parity) {
    asm volatile(
        "{\n\t.reg .pred P1;\n\t"
        "W_%=:\n\t"
        "mbarrier.try_wait.parity.shared.b64 P1, [%0], %1;\n\t"
        "@P1 bra.uni D_%=;\n\t"
        "bra.uni W_%=;\n\t"
        "D_%=:\n\t}"
        :: "r"(mb), "r"(parity) : "memory");
}
__device__ __forceinline__ void bulk_cp(uint32_t dst, const void* src, uint32_t bytes, uint32_t mb) {
    asm volatile(
        "cp.async.bulk.shared::cluster.global.mbarrier::complete_tx::bytes [%0], [%1], %2, [%3];"
        :: "r"(dst), "l"(__cvta_generic_to_global(src)), "r"(bytes), "r"(mb) : "memory");
}
// tiled (128x64, SW128-preswizzled) element address
__device__ __forceinline__ __half2* tptr(__half* base, int r, int c, int ntk) {
    uint32_t b = (uint32_t)((r & 127) * 128 + (c & 63) * 2);
    size_t off = ((size_t)((r >> 7) * ntk + (c >> 6)) << 14) + SW128(b);
    return (__half2*)((char*)base + off);
}

// ---------------- scratch (device globals, no allocs) ----------------
__device__ __half g_Wqkv[(size_t)NQKV_*C_];     // tiled
__device__ __half g_Wo  [(size_t)C_*C_];        // tiled
__device__ __half g_Wgu [(size_t)NGU_*C_];      // tiled, interleaved 16-col groups
__device__ __half g_Wd  [(size_t)C_*HIDP_];     // tiled
__device__ __half g_XN  [(size_t)BT_*C_];       // tiled
__device__ __half g_Y   [(size_t)BT_*C_];       // tiled
__device__ __half g_HN  [(size_t)BT_*C_];       // tiled
__device__ __half g_PR  [(size_t)BT_*HIDP_];    // tiled
__device__ __half g_QKV [(size_t)BT_*NQKV_];    // row-major (attention input)
__device__ float  g_Hb  [(size_t)BT_*C_];
__device__ int    g_Ji[64];
__device__ float  g_Sg[64];
__device__ float  g_scale[112];
__device__ double g_part[7*8*8];

struct ScaleSrc { const float* p[7]; int op[7]; };

// ---------------- scales (+ octonion table folded into fin) ----------------
__global__ void scales_part_k(ScaleSrc ss) {
    int t = blockIdx.z, i = blockIdx.x, sl = blockIdx.y;
    int OP = ss.op[t];
    const float* Wi = ss.p[t] + (size_t)i * OP;
    int per = (OP + 7) / 8;
    int st = sl * per, en = min(OP, st + per);
    double s = 0.0;
    for (int u = st + threadIdx.x; u < en; u += 256) s += (double)fabsf(Wi[u]);
    __shared__ double red[256];
    red[threadIdx.x] = s; __syncthreads();
    for (int stp = 128; stp > 0; stp >>= 1) {
        if (threadIdx.x < stp) red[threadIdx.x] += red[threadIdx.x + stp];
        __syncthreads();
    }
    if (threadIdx.x == 0) g_part[(t*8 + i)*8 + sl] = red[0];
}
__global__ void scales_fin_k(ScaleSrc ss) {
    int id = threadIdx.x;
    if (id < 56) {
        int t = id >> 3, i = id & 7;
        double s = 0.0;
        for (int j = 0; j < 8; j++) s += g_part[(t*8 + i)*8 + j];
        float sc = (float)(s / (double)ss.op[t]);
        g_scale[id] = sc;
        g_scale[56 + id] = 1.0f / (sc + 1e-8f);
    } else if (id == 63) {
        int idx[8][8]; float sg[8][8];
        for (int j = 0; j < 8; j++) { idx[0][j] = j; sg[0][j] = 1.f; }
        for (int i = 1; i < 8; i++) {
            idx[i][0] = i; sg[i][0] = 1.f;
            idx[i][i] = 0; sg[i][i] = -1.f;
        }
        const int tr[7][3] = {{1,2,3},{1,4,5},{1,7,6},{2,4,6},{2,5,7},{3,4,7},{3,6,5}};
        for (int t = 0; t < 7; t++) {
            int a = tr[t][0], b = tr[t][1], c = tr[t][2];
            int per[3][3] = {{a,b,c},{b,c,a},{c,a,b}};
            for (int u = 0; u < 3; u++) {
                int p = per[u][0], q = per[u][1], r = per[u][2];
                idx[p][q] = r; sg[p][q] = 1.f;
                idx[q][p] = r; sg[q][p] = -1.f;
            }
        }
        for (int i = 0; i < 8; i++)
            for (int j = 0; j < 8; j++) {
                int k = idx[i][j];
                g_Ji[k*8 + j] = i;
                g_Sg[k*8 + j] = sg[i][j];
            }
    }
}

__device__ __forceinline__ float tsign_r(float w, float inv) {
    float q = rintf(w * inv);
    return fmaxf(-1.f, fminf(1.f, q));
}

// ---------------- build QKV + fused rmsnorm #1 (region dispatch) ----------------
#define NB_QKV 12288
#define NB_WO  4096
#define NB_GU  22016
#define NB_D   22016
#define NB_QR  (NB_QKV + BT_)
#define NB_REST (NB_WO + NB_GU + NB_D)

__global__ void build_qr_k(const float* __restrict__ wq, const float* __restrict__ wk,
                           const float* __restrict__ wv,
                           const float* __restrict__ x, const float* __restrict__ anw,
                           __half* __restrict__ Fqkv, __half* __restrict__ XN) {
    int b = blockIdx.x;
    if (b < NB_QKV) {
        int id = b * 256 + threadIdx.x;
        int r = id >> 9, c = (id & 511) << 2;
        int t = r >> 11, rr = r & 2047;
        int kb = rr >> 8, o = rr & 255, jb = c >> 8, p = c & 255;
        int i = g_Ji[kb*8 + jb];
        const float* src = (t == 0) ? wq : ((t == 1) ? wk : wv);
        float inv = g_scale[56 + t*8 + i];
        float ss = g_Sg[kb*8 + jb] * g_scale[t*8 + i];
        float4 w = *(const float4*)&src[((size_t)i << 16) + (o << 8) + p];
        *tptr(Fqkv, r, c, NTK_C)     = __floats2half2_rn(ss * tsign_r(w.x, inv), ss * tsign_r(w.y, inv));
        *tptr(Fqkv, r, c + 2, NTK_C) = __floats2half2_rn(ss * tsign_r(w.z, inv), ss * tsign_r(w.w, inv));
    } else {
        int row = b - NB_QKV;
        const float4* xr = (const float4*)(x + (size_t)row * C_);
        const float4* wr = (const float4*)anw;
        float4 v0 = xr[threadIdx.x];
        float4 v1 = xr[threadIdx.x + 256];
        float s = v0.x*v0.x + v0.y*v0.y + v0.z*v0.z + v0.w*v0.w
                + v1.x*v1.x + v1.y*v1.y + v1.z*v1.z + v1.w*v1.w;
        __shared__ float red[256];
        red[threadIdx.x] = s; __syncthreads();
        for (int st = 128; st > 0; st >>= 1) {
            if (threadIdx.x < st) red[threadIdx.x] += red[threadIdx.x + st];
            __syncthreads();
        }
        float inv = 1.0f / sqrtf(red[0] / (float)C_ + 1e-6f);
        float4 w0 = wr[threadIdx.x];
        float4 w1 = wr[threadIdx.x + 256];
        int c0 = threadIdx.x * 4;
        *tptr(XN, row, c0, NTK_C)     = __floats2half2_rn(v0.x*inv*w0.x, v0.y*inv*w0.y);
        *tptr(XN, row, c0 + 2, NTK_C) = __floats2half2_rn(v0.z*inv*w0.z, v0.w*inv*w0.w);
        int c1 = c0 + 1024;
        *tptr(XN, row, c1, NTK_C)     = __floats2half2_rn(v1.x*inv*w1.x, v1.y*inv*w1.y);
        *tptr(XN, row, c1 + 2, NTK_C) = __floats2half2_rn(v1.z*inv*w1.z, v1.w*inv*w1.w);
    }
}

// ---------------- build WO | GU | WD (side stream) ----------------
__global__ void build_rest_k(const float* __restrict__ wo,
                             const float* __restrict__ wg, const float* __restrict__ wu,
                             const float* __restrict__ wd,
                             __half* __restrict__ Fo, __half* __restrict__ Fgu,
                             __half* __restrict__ Fd) {
    int b = blockIdx.x;
    if (b < NB_WO) {
        int id = b * 256 + threadIdx.x;
        int r = id >> 9, c = (id & 511) << 2;
        int kb = r >> 8, o = r & 255, jb = c >> 8, p = c & 255;
        int i = g_Ji[kb*8 + jb];
        float inv = g_scale[56 + 24 + i];
        float ss = g_Sg[kb*8 + jb] * g_scale[24 + i];
        float4 w = *(const float4*)&wo[((size_t)i << 16) + (o << 8) + p];
        *tptr(Fo, r, c, NTK_C)     = __floats2half2_rn(ss * tsign_r(w.x, inv), ss * tsign_r(w.y, inv));
        *tptr(Fo, r, c + 2, NTK_C) = __floats2half2_rn(ss * tsign_r(w.z, inv), ss * tsign_r(w.w, inv));
    } else if (b < NB_WO + NB_GU) {
        int id = (b - NB_WO) * 256 + threadIdx.x;
        int r = id >> 9, c = (id & 511) << 2;
        int type = (r >> 3) & 1;
        int hid = ((r >> 4) << 3) + (r & 7);
        int kb = hid / HBLK_, o = hid - kb * HBLK_;
        if (o >= 683) {
            *tptr(Fgu, r, c, NTK_C)     = __floats2half2_rn(0.f, 0.f);
            *tptr(Fgu, r, c + 2, NTK_C) = __floats2half2_rn(0.f, 0.f);
            return;
        }
        int jb = c >> 8, p = c & 255;
        int i = g_Ji[kb*8 + jb];
        const float* src = type ? wu : wg;
        float inv = g_scale[56 + 32 + type*8 + i];
        float ss = g_Sg[kb*8 + jb] * g_scale[32 + type*8 + i];
        float4 w = *(const float4*)&src[((size_t)i * 683 + o) * 256 + p];
        *tptr(Fgu, r, c, NTK_C)     = __floats2half2_rn(ss * tsign_r(w.x, inv), ss * tsign_r(w.y, inv));
        *tptr(Fgu, r, c + 2, NTK_C) = __floats2half2_rn(ss * tsign_r(w.z, inv), ss * tsign_r(w.w, inv));
    } else {
        int id = (b - NB_WO - NB_GU) * 256 + threadIdx.x;
        int r = id / (HIDP_/2), c = (id - r * (HIDP_/2)) * 2;
        int jb = c / HBLK_, p = c - jb * HBLK_;
        int kb = r >> 8, o = r & 255;
        int i = g_Ji[kb*8 + jb];
        float inv = g_scale[56 + 48 + i];
        float ss = g_Sg[kb*8 + jb] * g_scale[48 + i];
        float v0 = 0.f, v1 = 0.f;
        if (p < 683) {
            const float* base = &wd[((size_t)i * 256 + o) * 683 + p];
            v0 = ss * tsign_r(base[0], inv);
            if (p + 1 < 683) v1 = ss * tsign_r(base[1], inv);
        }
        *tptr(Fd, r, c, NTK_H) = __floats2half2_rn(v0, v1);
    }
}

// ---------------- rmsnorm #2 -> fp16 tiled ----------------
__global__ void rmsnorm_k(const float* __restrict__ x, const float* __restrict__ w,
                          __half* __restrict__ oh) {
    int row = blockIdx.x;
    const float4* xr = (const float4*)(x + (size_t)row * C_);
    const float4* wr = (const float4*)w;
    float4 v0 = xr[threadIdx.x];
    float4 v1 = xr[threadIdx.x + 256];
    float s = v0.x*v0.x + v0.y*v0.y + v0.z*v0.z + v0.w*v0.w
            + v1.x*v1.x + v1.y*v1.y + v1.z*v1.z + v1.w*v1.w;
    __shared__ float red[256];
    red[threadIdx.x] = s; __syncthreads();
    for (int st = 128; st > 0; st >>= 1) {
        if (threadIdx.x < st) red[threadIdx.x] += red[threadIdx.x + st];
        __syncthreads();
    }
    float inv = 1.0f / sqrtf(red[0] / (float)C_ + 1e-6f);
    float4 w0 = wr[threadIdx.x];
    float4 w1 = wr[threadIdx.x + 256];
    int c0 = threadIdx.x * 4;
    *tptr(oh, row, c0, NTK_C)     = __floats2half2_rn(v0.x*inv*w0.x, v0.y*inv*w0.y);
    *tptr(oh, row, c0 + 2, NTK_C) = __floats2half2_rn(v0.z*inv*w0.z, v0.w*inv*w0.w);
    int c1 = c0 + 1024;
    *tptr(oh, row, c1, NTK_C)     = __floats2half2_rn(v1.x*inv*w1.x, v1.y*inv*w1.y);
    *tptr(oh, row, c1 + 2, NTK_C) = __floats2half2_rn(v1.z*inv*w1.z, v1.w*inv*w1.w);
}

// ---------------- 128x128x64 fp16 GEMM, bulk-DMA fill, mbarrier pipeline ----------------
#define G1_ABYTES 16384
#define G1_STAGE  32768
#define G1_SMEM   (3 * G1_STAGE + 64)

__global__ __launch_bounds__(256, 2) void gemm1_k(
    const __half* __restrict__ A, const __half* __restrict__ B,
    const float* __restrict__ addsrc, void* __restrict__ outp,
    int M, int N, int K, int mode,
    const float* __restrict__ fc, const float* __restrict__ fs)
{
    extern __shared__ __align__(1024) char smem[];
    int tid = threadIdx.x, wid = tid >> 5, lane = tid & 31;
    int wr = wid >> 1, wc = wid & 1;
    int bm = blockIdx.y * 128, bn = blockIdx.x * 128;
    uint32_t sbase = smem_u32(smem);
    uint32_t mbar = sbase + 3 * G1_STAGE;
    int total = K >> 6;

    if (tid == 0) {
        MBAR_INIT(mbar, 1);
        MBAR_INIT(mbar + 8, 1);
        MBAR_INIT(mbar + 16, 1);
    }
    __syncthreads();

    float acc[2][8][4];
#pragma unroll
    for (int mt = 0; mt < 2; mt++)
#pragma unroll
        for (int nt = 0; nt < 8; nt++)
#pragma unroll
            for (int e = 0; e < 4; e++) acc[mt][nt][e] = 0.f;

    int a_row = ((lane >> 3) & 1) * 8 + (lane & 7);
    int a_kb  = (lane >> 4) * 16;
    int b_n   = ((lane >> 4) & 1) * 8 + (lane & 7);
    int b_kb  = ((lane >> 3) & 1) * 16;

#define ISSUE_T(ch) do {                                                      \
        if (tid == 0) {                                                       \
            int s_ = (ch) % 3;                                                \
            uint32_t mb_ = mbar + s_ * 8;                                     \
            asm volatile("mbarrier.arrive.expect_tx.shared.b64 _, [%0], %1;"  \
                         :: "r"(mb_), "r"(32768u) : "memory");                \
            uint32_t dst_ = sbase + s_ * G1_STAGE;                            \
            bulk_cp(dst_, A + (((size_t)(bm >> 7) * total + (ch)) << 13),     \
                    16384u, mb_);                                             \
            bulk_cp(dst_ + G1_ABYTES,                                         \
                    B + (((size_t)(bn >> 7) * total + (ch)) << 13),           \
                    16384u, mb_);                                             \
        }                                                                     \
    } while (0)

    ISSUE_T(0);
    if (total > 1) ISSUE_T(1);
    for (int ch = 0; ch < total; ch++) {
        mbar_wait(mbar + (ch % 3) * 8, (uint32_t)((ch / 3) & 1));

        uint32_t stg = sbase + (ch % 3) * G1_STAGE;
#pragma unroll
        for (int kk = 0; kk < 4; kk++) {
            uint32_t a[2][4];
#pragma unroll
            for (int mt = 0; mt < 2; mt++) {
                uint32_t byte = (uint32_t)(wr * 32 + mt * 16 + a_row) * 128 + kk * 32 + a_kb;
                ldm_x4(stg + SW128(byte), a[mt][0], a[mt][1], a[mt][2], a[mt][3]);
            }
            uint32_t b[4][4];
#pragma unroll
            for (int np = 0; np < 4; np++) {
                uint32_t byte = (uint32_t)(wc * 64 + np * 16 + b_n) * 128 + kk * 32 + b_kb;
                ldm_x4(stg + G1_ABYTES + SW128(byte), b[np][0], b[np][1], b[np][2], b[np][3]);
            }
#pragma unroll
            for (int mt = 0; mt < 2; mt++)
#pragma unroll
                for (int nt = 0; nt < 8; nt++)
                    mma16816h(acc[mt][nt], a[mt], b[nt >> 1][(nt & 1) * 2],
                              b[nt >> 1][(nt & 1) * 2 + 1]);
        }
        __syncthreads();
        if (ch + 2 < total) ISSUE_T(ch + 2);
    }

    // ---------------- epilogue ----------------
    if (mode == 0) {
        float* Cm = (float*)outp;
#pragma unroll
        for (int mt = 0; mt < 2; mt++)
#pragma unroll
            for (int nt = 0; nt < 8; nt++) {
                int r0 = bm + wr * 32 + mt * 16 + (lane >> 2);
                int c  = bn + wc * 64 + nt * 8 + 2 * (lane & 3);
                size_t i0 = (size_t)r0 * N + c;
                size_t i1 = i0 + (size_t)8 * N;
                float2 v0 = make_float2(acc[mt][nt][0], acc[mt][nt][1]);
                float2 v1 = make_float2(acc[mt][nt][2], acc[mt][nt][3]);
                if (addsrc) {
                    float2 s0 = *(const float2*)&addsrc[i0];
                    float2 s1 = *(const float2*)&addsrc[i1];
                    v0.x += s0.x; v0.y += s0.y;
                    v1.x += s1.x; v1.y += s1.y;
                }
                *(float2*)&Cm[i0] = v0;
                *(float2*)&Cm[i1] = v1;
            }
    } else if (mode == 2) {
        __half* Cm = (__half*)outp;
#pragma unroll
        for (int mt = 0; mt < 2; mt++)
#pragma unroll
            for (int nt = 0; nt < 8; nt++) {
                int r0 = bm + wr * 32 + mt * 16 + (lane >> 2);
                int c  = bn + wc * 64 + nt * 8 + 2 * (lane & 3);
                float x0 = acc[mt][nt][0], y0 = acc[mt][nt][1];
                float x1 = acc[mt][nt][2], y1 = acc[mt][nt][3];
                if (c < 4096) {
                    int dp = (c & 127) >> 1;
                    int t0 = r0 & (T_ - 1), t1 = (r0 + 8) & (T_ - 1);
                    float c0 = fc[t0 * 64 + dp], s0 = fs[t0 * 64 + dp];
                    float c1 = fc[t1 * 64 + dp], s1 = fs[t1 * 64 + dp];
                    float nx0 = x0 * c0 - y0 * s0, ny0 = x0 * s0 + y0 * c0;
                    float nx1 = x1 * c1 - y1 * s1, ny1 = x1 * s1 + y1 * c1;
                    x0 = nx0; y0 = ny0; x1 = nx1; y1 = ny1;
                }
                *(__half2*)&Cm[(size_t)r0 * N + c] = __floats2half2_rn(x0, y0);
                *(__half2*)&Cm[(size_t)(r0 + 8) * N + c] = __floats2half2_rn(x1, y1);
            }
    } else {   // mode 3: silu(gate)*up -> TILED half out, K-width HIDP_
        __half* Cm = (__half*)outp;
#pragma unroll
        for (int mt = 0; mt < 2; mt++)
#pragma unroll
            for (int ntp = 0; ntp < 4; ntp++) {
                int r0 = bm + wr * 32 + mt * 16 + (lane >> 2);
                int n0 = bn + wc * 64 + ntp * 16 + 2 * (lane & 3);
                int hid = ((n0 >> 4) << 3) + (n0 & 7);
                float* gv = acc[mt][2 * ntp];
                float* uv = acc[mt][2 * ntp + 1];
                float p0 = gv[0] / (1.f + __expf(-gv[0])) * uv[0];
                float p1 = gv[1] / (1.f + __expf(-gv[1])) * uv[1];
                float p2 = gv[2] / (1.f + __expf(-gv[2])) * uv[2];
                float p3 = gv[3] / (1.f + __expf(-gv[3])) * uv[3];
                *tptr(Cm, r0, hid, NTK_H)     = __floats2half2_rn(p0, p1);
                *tptr(Cm, r0 + 8, hid, NTK_H) = __floats2half2_rn(p2, p3);
            }
    }
}

// ---------------- HMMA flash attention: 64-row Q tiles, 32-key KV, 3 CTAs/SM ----------------
#define ATT_SMEM 49152
__global__ __launch_bounds__(128, 3) void attn_k(
    const __half* __restrict__ qkv, __half* __restrict__ y)
{
    extern __shared__ __align__(1024) char smem[];
    uint32_t sQ = smem_u32(smem);
    int tid = threadIdx.x, wid = tid >> 5, lane = tid & 31;
    int bh = blockIdx.x;
    int qt = (int)(gridDim.y - 1 - blockIdx.y);
    int bb = bh >> 4, h = bh & 15;
    const float sc = 0.08838834764831845f;

    int a_row = ((lane >> 3) & 1) * 8 + (lane & 7);
    int a_kb  = (lane >> 4) * 16;
    int b_n   = ((lane >> 4) & 1) * 8 + (lane & 7);
    int b_kb  = ((lane >> 3) & 1) * 16;
    int v_key = ((lane >> 3) & 1) * 8 + (lane & 7);
    int v_col = ((lane >> 4) & 1) * 8;

    int qrow0 = bb * T_ + qt * 64;

#pragma unroll
    for (int u = 0; u < 8; u++) {
        int i = tid + u * 128;
        int row = i >> 4, seg = i & 15;
        cp16(sQ + SWK(row * 256 + seg * 16),
             qkv + (size_t)(qrow0 + row) * NQKV_ + h * HD_ + seg * 8);
    }
    asm volatile("cp.async.commit_group;" ::: "memory");

    int nkt = 2 * qt + 2;
#define ISSUE_KV(kt_) do {                                                    \
        uint32_t stg_ = sQ + 16384 + ((kt_) & 1) * 16384;                     \
        int kb_ = (kt_) * 32;                                                 \
        _Pragma("unroll")                                                     \
        for (int u = 0; u < 4; u++) {                                         \
            int i_ = tid + u * 128;                                           \
            int row_ = i_ >> 4, seg_ = i_ & 15;                               \
            size_t gr_ = (size_t)(bb * T_ + kb_ + row_) * NQKV_ + h * HD_ + seg_ * 8; \
            uint32_t so_ = SWK(row_ * 256 + seg_ * 16);                       \
            cp16(stg_ + so_, qkv + 2048 + gr_);                               \
            cp16(stg_ + 8192 + so_, qkv + 4096 + gr_);                        \
        }                                                                     \
        asm volatile("cp.async.commit_group;" ::: "memory");                  \
    } while (0)

    ISSUE_KV(0);
    asm volatile("cp.async.wait_group 1;" ::: "memory");
    __syncthreads();

    uint32_t qa[8][4];
#pragma unroll
    for (int kk = 0; kk < 8; kk++) {
        uint32_t byte = (uint32_t)(wid * 16 + a_row) * 256 + kk * 32 + a_kb;
        ldm_x4(sQ + SWK(byte), qa[kk][0], qa[kk][1], qa[kk][2], qa[kk][3]);
    }

    float o[16][4];
#pragma unroll
    for (int nt = 0; nt < 16; nt++)
#pragma unroll
        for (int e = 0; e < 4; e++) o[nt][e] = 0.f;
    float mrun0 = -INFINITY, mrun1 = -INFINITY, lrun0 = 0.f, lrun1 = 0.f;

    int rg0 = qt * 64 + wid * 16 + (lane >> 2);
    int rg1 = rg0 + 8;

    for (int kt = 0; kt < nkt; kt++) {
        asm volatile("cp.async.wait_group 0;" ::: "memory");
        __syncthreads();
        if (kt + 1 < nkt) ISSUE_KV(kt + 1);
        uint32_t sK = sQ + 16384 + (kt & 1) * 16384;
        uint32_t sV = sK + 8192;

        float s[4][4];
#pragma unroll
        for (int nt = 0; nt < 4; nt++)
#pragma unroll
            for (int e = 0; e < 4; e++) s[nt][e] = 0.f;
#pragma unroll
        for (int kk = 0; kk < 8; kk++) {
            uint32_t bq[2][4];
#pragma unroll
            for (int np = 0; np < 2; np++) {
                uint32_t byte = (uint32_t)(np * 16 + b_n) * 256 + kk * 32 + b_kb;
                ldm_x4(sK + SWK(byte), bq[np][0], bq[np][1], bq[np][2], bq[np][3]);
            }
#pragma unroll
            for (int nt = 0; nt < 4; nt++)
                mma16816h(s[nt], qa[kk], bq[nt >> 1][(nt & 1) * 2],
                          bq[nt >> 1][(nt & 1) * 2 + 1]);
        }

        int kb0 = kt * 32;
        bool domask = (kt >= 2 * qt);
        float m0 = -INFINITY, m1 = -INFINITY;
#pragma unroll
        for (int nt = 0; nt < 4; nt++) {
            int k0 = kb0 + nt * 8 + 2 * (lane & 3);
#pragma unroll
            for (int e = 0; e < 4; e++) {
                float sv = s[nt][e] * sc;
                if (domask) {
                    int kc = k0 + (e & 1);
                    int rg = (e < 2) ? rg0 : rg1;
                    if (kc > rg) sv = -1e30f;
                }
                s[nt][e] = sv;
            }
            m0 = fmaxf(m0, fmaxf(s[nt][0], s[nt][1]));
            m1 = fmaxf(m1, fmaxf(s[nt][2], s[nt][3]));
        }
        m0 = fmaxf(m0, __shfl_xor_sync(0xffffffffu, m0, 1));
        m0 = fmaxf(m0, __shfl_xor_sync(0xffffffffu, m0, 2));
        m1 = fmaxf(m1, __shfl_xor_sync(0xffffffffu, m1, 1));
        m1 = fmaxf(m1, __shfl_xor_sync(0xffffffffu, m1, 2));
        float mn0 = fmaxf(mrun0, m0), mn1 = fmaxf(mrun1, m1);
        float al0 = __expf(mrun0 - mn0), al1 = __expf(mrun1 - mn1);
        mrun0 = mn0; mrun1 = mn1;
        float ls0 = 0.f, ls1 = 0.f;
#pragma unroll
        for (int nt = 0; nt < 4; nt++) {
            s[nt][0] = __expf(s[nt][0] - mn0);
            s[nt][1] = __expf(s[nt][1] - mn0);
            s[nt][2] = __expf(s[nt][2] - mn1);
            s[nt][3] = __expf(s[nt][3] - mn1);
            ls0 += s[nt][0] + s[nt][1];
            ls1 += s[nt][2] + s[nt][3];
        }
        ls0 += __shfl_xor_sync(0xffffffffu, ls0, 1);
        ls0 += __shfl_xor_sync(0xffffffffu, ls0, 2);
        ls1 += __shfl_xor_sync(0xffffffffu, ls1, 1);
        ls1 += __shfl_xor_sync(0xffffffffu, ls1, 2);
        lrun0 = lrun0 * al0 + ls0;
        lrun1 = lrun1 * al1 + ls1;
#pragma unroll
        for (int nt = 0; nt < 16; nt++) {
            o[nt][0] *= al0; o[nt][1] *= al0;
            o[nt][2] *= al1; o[nt][3] *= al1;
        }

#pragma unroll
        for (int ks = 0; ks < 2; ks++) {
            uint32_t pa[4];
            pa[0] = packh2(s[2*ks][0],   s[2*ks][1]);
            pa[1] = packh2(s[2*ks][2],   s[2*ks][3]);
            pa[2] = packh2(s[2*ks+1][0], s[2*ks+1][1]);
            pa[3] = packh2(s[2*ks+1][2], s[2*ks+1][3]);
#pragma unroll
            for (int nv = 0; nv < 8; nv++) {
                uint32_t r0, r1, r2, r3;
                uint32_t byte = (uint32_t)(ks * 16 + v_key) * 256 + (nv * 16 + v_col) * 2;
                ldm_x4t(sV + SWK(byte), r0, r1, r2, r3);
                mma16816h(o[2*nv],     pa, r0, r1);
                mma16816h(o[2*nv + 1], pa, r2, r3);
            }
        }
    }

    float il0 = 1.f / lrun0, il1 = 1.f / lrun1;
    int row0 = bb * T_ + rg0;
    int row1 = row0 + 8;
#pragma unroll
    for (int nt = 0; nt < 16; nt++) {
        int c = h * HD_ + nt * 8 + 2 * (lane & 3);
        *tptr(y, row0, c, NTK_C) = __floats2half2_rn(o[nt][0] * il0, o[nt][1] * il0);
        *tptr(y, row1, c, NTK_C) = __floats2half2_rn(o[nt][2] * il1, o[nt][3] * il1);
    }
}

// ---------------- launch ----------------
extern "C" void kernel_launch(void* const* d_in, const int* in_sizes, int n_in,
                              void* d_out, int out_size) {
    const float* x   = (const float*)d_in[0];
    const float* fc  = (const float*)d_in[1];
    const float* fs  = (const float*)d_in[2];
    const float* anw = (const float*)d_in[3];
    const float* fnw = (const float*)d_in[4];
    const float* wq  = (const float*)d_in[5];
    const float* wk  = (const float*)d_in[6];
    const float* wv  = (const float*)d_in[7];
    const float* wo  = (const float*)d_in[8];
    const float* wg  = (const float*)d_in[9];
    const float* wu  = (const float*)d_in[10];
    const float* wd  = (const float*)d_in[11];
    float* out = (float*)d_out;

    __half *Wqkv, *Wo, *Wgu, *Wd, *XN, *Y, *HN, *PR, *QKV;
    float *Hb;
    cudaGetSymbolAddress((void**)&Wqkv, g_Wqkv);
    cudaGetSymbolAddress((void**)&Wo,   g_Wo);
    cudaGetSymbolAddress((void**)&Wgu,  g_Wgu);
    cudaGetSymbolAddress((void**)&Wd,   g_Wd);
    cudaGetSymbolAddress((void**)&XN,   g_XN);
    cudaGetSymbolAddress((void**)&Y,    g_Y);
    cudaGetSymbolAddress((void**)&HN,   g_HN);
    cudaGetSymbolAddress((void**)&PR,   g_PR);
    cudaGetSymbolAddress((void**)&QKV,  g_QKV);
    cudaGetSymbolAddress((void**)&Hb,   g_Hb);

    cudaFuncSetAttribute(attn_k, cudaFuncAttributeMaxDynamicSharedMemorySize, ATT_SMEM);
    cudaFuncSetAttribute(gemm1_k, cudaFuncAttributeMaxDynamicSharedMemorySize, G1_SMEM);

    // side stream + events (created once per call; intentionally not destroyed
    // so capture-participating objects stay alive; host-side only, no device mem)
    cudaStream_t s2;
    cudaStreamCreateWithFlags(&s2, cudaStreamNonBlocking);
    cudaEvent_t eS, eJ;
    cudaEventCreateWithFlags(&eS, cudaEventDisableTiming);
    cudaEventCreateWithFlags(&eJ, cudaEventDisableTiming);

    ScaleSrc ss;
    ss.p[0] = wq; ss.p[1] = wk; ss.p[2] = wv; ss.p[3] = wo;
    ss.p[4] = wg; ss.p[5] = wu; ss.p[6] = wd;
    ss.op[0] = ss.op[1] = ss.op[2] = ss.op[3] = 65536;
    ss.op[4] = ss.op[5] = ss.op[6] = 683 * 256;
    scales_part_k<<<dim3(8, 8, 7), 256>>>(ss);
    scales_fin_k<<<1, 64>>>(ss);

    // fork: WO/GU/WD builds run on s2 concurrently with QKV build + GEMM + attention
    cudaEventRecord(eS, 0);
    cudaStreamWaitEvent(s2, eS, 0);
    build_rest_k<<<NB_REST, 256, 0, s2>>>(wo, wg, wu, wd, Wo, Wgu, Wd);
    cudaEventRecord(eJ, s2);

    build_qr_k<<<NB_QR, 256>>>(wq, wk, wv, x, anw, Wqkv, XN);

    gemm1_k<<<dim3(NQKV_ / 128, BT_ / 128), 256, G1_SMEM>>>(
        XN, Wqkv, nullptr, QKV, BT_, NQKV_, C_, 2, fc, fs);

    attn_k<<<dim3(64, 16), 128, ATT_SMEM>>>(QKV, Y);

    // join: WO GEMM needs Wo (and later Wgu/Wd)
    cudaStreamWaitEvent(0, eJ, 0);

    gemm1_k<<<dim3(C_ / 128, BT_ / 128), 256, G1_SMEM>>>(
        Y, Wo, x, Hb, BT_, C_, C_, 0, nullptr, nullptr);

    rmsnorm_k<<<BT_, 256>>>(Hb, fnw, HN);

    gemm1_k<<<dim3(NGU_ / 128, BT_ / 128), 256, G1_SMEM>>>(
        HN, Wgu, nullptr, PR, BT_, NGU_, C_, 3, nullptr, nullptr);

    gemm1_k<<<dim3(C_ / 128, BT_ / 128), 256, G1_SMEM>>>(
        PR, Wd, Hb, out, BT_, C_, HIDP_, 0, nullptr, nullptr);
}